// round 1
// baseline (speedup 1.0000x reference)
#include <cuda_runtime.h>
#include <cuda_bf16.h>
#include <math.h>

// ---------------- problem constants ----------------
#define B_      2
#define S_      2048
#define BS_     (B_*S_)          // 4096 token rows
#define D_      1024
#define H_      16
#define HD_     64
#define HM_     4096
#define V_      32768
#define LG_     8
#define CHUNK_  64
#define QEPS_   1.1920929e-07f

// ---------------- static device scratch ----------------
__device__ float g_x   [BS_*D_];
__device__ float g_xn  [BS_*D_];
__device__ float g_proj[BS_*5*D_];      // reused: gdn proj (5120) / qkv (3072) / mlp hidden (4096)
__device__ float g_qh  [BS_*D_];
__device__ float g_u   [BS_*D_];
__device__ float g_a   [BS_*D_];
__device__ float g_mem [BS_*D_];
__device__ float g_y   [BS_*D_];
__device__ float g_logits[(size_t)BS_*V_];   // 512 MB
__device__ float g_rowloss[BS_];

// ---------------- embedding ----------------
__global__ void embed_kernel(const int* __restrict__ ids,
                             const float* __restrict__ emb,
                             float* __restrict__ x) {
    int row = blockIdx.x;
    int id = ids[row];
    const float* src = emb + (size_t)id * D_;
    float* dst = x + (size_t)row * D_;
    for (int d = threadIdx.x; d < D_; d += blockDim.x) dst[d] = src[d];
}

// ---------------- rmsnorm (row of D_) ----------------
__global__ void rmsnorm_kernel(const float* __restrict__ x,
                               const float* __restrict__ w,
                               float* __restrict__ y, float eps) {
    __shared__ float red[256];
    int row = blockIdx.x;
    const float* xr = x + (size_t)row * D_;
    float s = 0.f;
    for (int d = threadIdx.x; d < D_; d += 256) { float v = xr[d]; s += v * v; }
    red[threadIdx.x] = s; __syncthreads();
    for (int o = 128; o > 0; o >>= 1) {
        if (threadIdx.x < o) red[threadIdx.x] += red[threadIdx.x + o];
        __syncthreads();
    }
    float r = rsqrtf(red[0] / D_ + eps);
    float* yr = y + (size_t)row * D_;
    for (int d = threadIdx.x; d < D_; d += 256) yr[d] = w[d] * xr[d] * r;
}

// ---------------- SGEMM: C[M,N] (+)= alpha * A[M,K] @ W[N,K]^T ----------------
// All dims multiples of tile sizes (M%64==0, N%64==0, K%16==0) by construction.
__global__ __launch_bounds__(256)
void sgemm_nt(const float* __restrict__ A, const float* __restrict__ W,
              float* __restrict__ C, int M, int N, int K, float alpha, int accum) {
    __shared__ float As[64][17];
    __shared__ float Ws[64][17];
    const int bm = blockIdx.y * 64, bn = blockIdx.x * 64;
    const int tid = threadIdx.x;
    const int ty = tid / 16, tx = tid % 16;
    float acc[4][4];
#pragma unroll
    for (int i = 0; i < 4; i++)
#pragma unroll
        for (int j = 0; j < 4; j++) acc[i][j] = 0.f;

    for (int k0 = 0; k0 < K; k0 += 16) {
#pragma unroll
        for (int l = 0; l < 4; l++) {
            int idx = tid + l * 256;
            int r = idx >> 4, c = idx & 15;
            As[r][c] = A[(size_t)(bm + r) * K + k0 + c];
            Ws[r][c] = W[(size_t)(bn + r) * K + k0 + c];
        }
        __syncthreads();
#pragma unroll
        for (int kk = 0; kk < 16; kk++) {
            float av[4], wv[4];
#pragma unroll
            for (int i = 0; i < 4; i++) av[i] = As[ty * 4 + i][kk];
#pragma unroll
            for (int j = 0; j < 4; j++) wv[j] = Ws[tx * 4 + j][kk];
#pragma unroll
            for (int i = 0; i < 4; i++)
#pragma unroll
                for (int j = 0; j < 4; j++) acc[i][j] = fmaf(av[i], wv[j], acc[i][j]);
        }
        __syncthreads();
    }
#pragma unroll
    for (int i = 0; i < 4; i++)
#pragma unroll
        for (int j = 0; j < 4; j++) {
            size_t ci = (size_t)(bm + ty * 4 + i) * N + bn + tx * 4 + j;
            float v = alpha * acc[i][j];
            C[ci] = accum ? (C[ci] + v) : v;
        }
}

// ---------------- GDN pre: q-rms / tanh k / gated a / u=k*v ----------------
__global__ void gdn_pre_kernel() {
    __shared__ float hs[H_];
    int row = blockIdx.x;
    size_t base = (size_t)row * (5 * D_);
    if (threadIdx.x < H_) hs[threadIdx.x] = 0.f;
    __syncthreads();
#pragma unroll
    for (int l = 0; l < 4; l++) {
        int d = threadIdx.x + l * 256;
        float qv = g_proj[base + d];
        atomicAdd(&hs[d >> 6], qv * qv);
    }
    __syncthreads();
#pragma unroll
    for (int l = 0; l < 4; l++) {
        int d = threadIdx.x + l * 256;
        size_t o = (size_t)row * D_ + d;
        float qv = g_proj[base + d];
        g_qh[o] = qv * rsqrtf(hs[d >> 6] / (float)HD_ + QEPS_);
        float kv = tanhf(g_proj[base + D_ + d]);
        float vv = g_proj[base + 2 * D_ + d];
        float avi = g_proj[base + 3 * D_ + d];
        float av = 1.f / (1.f + expf(-(avi + 2.f)));
        av = fminf(fmaxf(av, 0.6f), 0.9995f);
        g_u[o] = kv * vv;
        g_a[o] = av;
    }
}

// ---------------- chunked gated scan: one lane per (b, h*64+d) ----------------
__global__ void gdn_scan_kernel() {
    int lane = blockIdx.x * blockDim.x + threadIdx.x;   // 0..2047
    int b = lane / D_;
    int col = lane % D_;
    float carry = 0.f;
    for (int c = 0; c < S_ / CHUNK_; c++) {
        float p = 1.f, accv = 0.f, m = 0.f;
        for (int t = 0; t < CHUNK_; t++) {
            size_t idx = (size_t)(b * S_ + c * CHUNK_ + t) * D_ + col;
            float a = g_a[idx];
            float u = g_u[idx];
            p *= a;
            accv += u / fmaxf(p, 1e-6f);
            m = p * (carry + accv);
            g_mem[idx] = m;
        }
        carry = m;
    }
}

// ---------------- GDN post: y = gate*(qhat*mem) + (1-gate)*v ----------------
__global__ void gdn_post_kernel() {
    int i = blockIdx.x * blockDim.x + threadIdx.x;      // 0 .. BS_*D_-1
    int row = i >> 10, d = i & 1023;
    size_t base = (size_t)row * (5 * D_);
    float gv = g_proj[base + 4 * D_ + d];
    float vv = g_proj[base + 2 * D_ + d];
    float gate = 1.f / (1.f + expf(-gv));
    g_y[i] = gate * (g_qh[i] * g_mem[i]) + (1.f - gate) * vv;
}

// ---------------- silu ----------------
__global__ void silu_kernel(float* __restrict__ h, int n) {
    int i = blockIdx.x * blockDim.x + threadIdx.x;
    if (i < n) { float v = h[i]; h[i] = v / (1.f + expf(-v)); }
}

// ---------------- flash causal attention ----------------
// qkv in g_proj as [BS_, 3*D_]; one thread per query row; 64-key tiles in SMEM.
__global__ __launch_bounds__(128)
void flash_attn_kernel() {
    __shared__ float Ks[64][64];
    __shared__ float Vs[64][64];
    const int qt = blockIdx.x & 15;
    const int h  = (blockIdx.x >> 4) & 15;
    const int b  = blockIdx.x >> 8;
    const int qi = qt * 128 + threadIdx.x;
    const float scale = 0.125f;   // 1/sqrt(64)

    float qr[64], acc[64];
    {
        const float* qp = g_proj + (size_t)(b * S_ + qi) * (3 * D_) + h * HD_;
#pragma unroll
        for (int d = 0; d < 64; d++) { qr[d] = qp[d]; acc[d] = 0.f; }
    }
    float m = -1e30f, l = 0.f;
    const int last_tile = (qt * 128 + 127) / 64;   // inclusive

    for (int kt = 0; kt <= last_tile; kt++) {
        // stage 64 keys + values
#pragma unroll
        for (int ld = 0; ld < 32; ld++) {
            int idx = threadIdx.x + ld * 128;
            int kr = idx >> 6, kc = idx & 63;
            size_t base = (size_t)(b * S_ + kt * 64 + kr) * (3 * D_) + h * HD_ + kc;
            Ks[kr][kc] = g_proj[base + D_];
            Vs[kr][kc] = g_proj[base + 2 * D_];
        }
        __syncthreads();
        int jmax = min(64, qi - kt * 64 + 1);
        for (int j = 0; j < jmax; j++) {
            float s = 0.f;
#pragma unroll
            for (int d = 0; d < 64; d++) s = fmaf(qr[d], Ks[j][d], s);
            s *= scale;
            float nm = fmaxf(m, s);
            float corr = expf(m - nm);
            float p = expf(s - nm);
            l = l * corr + p;
            if (corr != 1.f) {
#pragma unroll
                for (int d = 0; d < 64; d++) acc[d] = acc[d] * corr + p * Vs[j][d];
            } else {
#pragma unroll
                for (int d = 0; d < 64; d++) acc[d] = fmaf(p, Vs[j][d], acc[d]);
            }
            m = nm;
        }
        __syncthreads();
    }
    float inv = 1.f / l;
    float* yp = g_y + (size_t)(b * S_ + qi) * D_ + h * HD_;
#pragma unroll
    for (int d = 0; d < 64; d++) yp[d] = acc[d] * inv;
}

// ---------------- loss: per-row logsumexp + NLL ----------------
__global__ void loss_rows_kernel(const float* __restrict__ bias,
                                 const int* __restrict__ tgt) {
    __shared__ float red[256];
    int row = blockIdx.x;
    const float* lr = g_logits + (size_t)row * V_;
    // pass 1: max
    float lm = -1e30f;
    for (int v = threadIdx.x; v < V_; v += 256) lm = fmaxf(lm, lr[v] + bias[v]);
    red[threadIdx.x] = lm; __syncthreads();
    for (int o = 128; o > 0; o >>= 1) {
        if (threadIdx.x < o) red[threadIdx.x] = fmaxf(red[threadIdx.x], red[threadIdx.x + o]);
        __syncthreads();
    }
    float M = red[0]; __syncthreads();
    // pass 2: sumexp
    float s = 0.f;
    for (int v = threadIdx.x; v < V_; v += 256) s += expf(lr[v] + bias[v] - M);
    red[threadIdx.x] = s; __syncthreads();
    for (int o = 128; o > 0; o >>= 1) {
        if (threadIdx.x < o) red[threadIdx.x] += red[threadIdx.x + o];
        __syncthreads();
    }
    if (threadIdx.x == 0) {
        int t = tgt[row];
        float lt = lr[t] + bias[t];
        g_rowloss[row] = -(lt - M - logf(red[0]));
    }
}

__global__ void loss_reduce_kernel(float* __restrict__ out) {
    __shared__ float red[256];
    float s = 0.f;
    for (int i = threadIdx.x; i < BS_; i += 256) s += g_rowloss[i];
    red[threadIdx.x] = s; __syncthreads();
    for (int o = 128; o > 0; o >>= 1) {
        if (threadIdx.x < o) red[threadIdx.x] += red[threadIdx.x + o];
        __syncthreads();
    }
    if (threadIdx.x == 0) out[0] = red[0] / (float)BS_;
}

// ---------------- host orchestration ----------------
static void launch_gemm(const float* A, const float* W, float* C,
                        int M, int N, int K, float alpha, int accum) {
    dim3 grid(N / 64, M / 64);
    sgemm_nt<<<grid, 256>>>(A, W, C, M, N, K, alpha, accum);
}

extern "C" void kernel_launch(void* const* d_in, const int* in_sizes, int n_in,
                              void* d_out, int out_size) {
    const int*   input_ids   = (const int*)  d_in[0];
    const int*   target_ids  = (const int*)  d_in[1];
    const float* tok_emb     = (const float*)d_in[2];
    const float* lm_bias     = (const float*)d_in[3];
    const float* gdn_in_w    = (const float*)d_in[4];
    const float* gdn_out_w   = (const float*)d_in[5];
    const float* gdn_norm1   = (const float*)d_in[6];
    const float* gdn_norm2   = (const float*)d_in[7];
    const float* gdn_fc_w    = (const float*)d_in[8];
    const float* gdn_proj_w  = (const float*)d_in[9];
    const float* attn_qkv_w  = (const float*)d_in[10];
    const float* attn_proj_w = (const float*)d_in[11];
    const float* attn_norm1  = (const float*)d_in[12];
    const float* attn_norm2  = (const float*)d_in[13];
    const float* attn_fc_w   = (const float*)d_in[14];
    const float* attn_mlp_w  = (const float*)d_in[15];
    const float* final_norm  = (const float*)d_in[16];
    float* out = (float*)d_out;

    float *x, *xn, *proj, *y, *logits;
    cudaGetSymbolAddress((void**)&x,      g_x);
    cudaGetSymbolAddress((void**)&xn,     g_xn);
    cudaGetSymbolAddress((void**)&proj,   g_proj);
    cudaGetSymbolAddress((void**)&y,      g_y);
    cudaGetSymbolAddress((void**)&logits, g_logits);

    embed_kernel<<<BS_, 256>>>(input_ids, tok_emb, x);

    for (int i = 0; i < LG_; i++) {
        float rsc = rsqrtf(2.0f * (i + 1));
        // gated delta mixer
        rmsnorm_kernel<<<BS_, 256>>>(x, gdn_norm1 + (size_t)i * D_, xn, 1e-6f);
        launch_gemm(xn, gdn_in_w + (size_t)i * 5 * D_ * D_, proj, BS_, 5 * D_, D_, 1.f, 0);
        gdn_pre_kernel<<<BS_, 256>>>();
        gdn_scan_kernel<<<B_ * D_ / 256, 256>>>();
        gdn_post_kernel<<<BS_ * D_ / 256, 256>>>();
        launch_gemm(y, gdn_out_w + (size_t)i * D_ * D_, x, BS_, D_, D_, rsc, 1);
        // mlp
        rmsnorm_kernel<<<BS_, 256>>>(x, gdn_norm2 + (size_t)i * D_, xn, 1e-6f);
        launch_gemm(xn, gdn_fc_w + (size_t)i * HM_ * D_, proj, BS_, HM_, D_, 1.f, 0);
        silu_kernel<<<BS_ * HM_ / 256, 256>>>(proj, BS_ * HM_);
        launch_gemm(proj, gdn_proj_w + (size_t)i * D_ * HM_, x, BS_, D_, HM_, rsc, 1);
    }

    float rsc = rsqrtf(2.0f * (LG_ + 1));
    // attention
    rmsnorm_kernel<<<BS_, 256>>>(x, attn_norm1, xn, 1e-6f);
    launch_gemm(xn, attn_qkv_w, proj, BS_, 3 * D_, D_, 1.f, 0);
    flash_attn_kernel<<<B_ * H_ * (S_ / 128), 128>>>();
    launch_gemm(y, attn_proj_w, x, BS_, D_, D_, rsc, 1);
    // attention mlp
    rmsnorm_kernel<<<BS_, 256>>>(x, attn_norm2, xn, 1e-6f);
    launch_gemm(xn, attn_fc_w, proj, BS_, HM_, D_, 1.f, 0);
    silu_kernel<<<BS_ * HM_ / 256, 256>>>(proj, BS_ * HM_);
    launch_gemm(proj, attn_mlp_w, x, BS_, D_, HM_, rsc, 1);

    // head + loss
    rmsnorm_kernel<<<BS_, 256>>>(x, final_norm, xn, 1e-6f);
    launch_gemm(xn, tok_emb, logits, BS_, V_, D_, 1.f, 0);
    loss_rows_kernel<<<BS_, 256>>>(lm_bias, target_ids);
    loss_reduce_kernel<<<1, 256>>>(out);
}

// round 3
// speedup vs baseline: 4.7875x; 4.7875x over previous
#include <cuda_runtime.h>
#include <cuda_bf16.h>
#include <math.h>
#include <stdint.h>

// ---------------- problem constants ----------------
#define B_      2
#define S_      2048
#define BS_     (B_*S_)          // 4096 token rows
#define D_      1024
#define H_      16
#define HD_     64
#define HM_     4096
#define V_      32768
#define LG_     8
#define CHUNK_  64
#define NCHUNK_ (S_/CHUNK_)      // 32
#define QEPS_   1.1920929e-07f

// ---------------- static device scratch ----------------
__device__ float g_x   [BS_*D_];
__device__ float g_xn  [BS_*D_];
__device__ float g_proj[BS_*5*D_];
__device__ float g_qh  [BS_*D_];
__device__ float g_u   [BS_*D_];
__device__ float g_a   [BS_*D_];
__device__ float g_mem [BS_*D_];
__device__ float g_y   [BS_*D_];
__device__ float g_scanP[B_*D_*NCHUNK_];
__device__ float g_scanA[B_*D_*NCHUNK_];
__device__ float g_scanC[B_*D_*NCHUNK_];
__device__ float g_logits[(size_t)BS_*V_];   // 512 MB
__device__ float g_rowloss[BS_];

// =====================================================================
// tf32 mma.sync GEMM: C[M,N] (+)= alpha * A[M,K] @ W[N,K]^T
// 128x128 block tile, K-tile 32, 8 warps (warp tile 32x64),
// double-buffered SMEM, pad-36 layout (LDG coalesced, STS/LDS bank-free).
// M,N multiples of 128; K multiple of 32.
// =====================================================================
#define PAD_ 36
#define TILE_FLOATS (128*PAD_)            // per matrix per stage
#define STAGE_FLOATS (2*TILE_FLOATS)      // A + W
#define GT_SMEM_BYTES (2*STAGE_FLOATS*4)  // 2 stages = 73728 B

__device__ __forceinline__ uint32_t f2tf(float f) {
    uint32_t r;
    asm("cvt.rna.tf32.f32 %0, %1;" : "=r"(r) : "f"(f));
    return r;
}

__device__ __forceinline__ void mma_tf32(float c[4], const uint32_t a[4],
                                         const uint32_t b[2]) {
    asm volatile(
        "mma.sync.aligned.m16n8k8.row.col.f32.tf32.tf32.f32 "
        "{%0,%1,%2,%3}, {%4,%5,%6,%7}, {%8,%9}, {%0,%1,%2,%3};"
        : "+f"(c[0]), "+f"(c[1]), "+f"(c[2]), "+f"(c[3])
        : "r"(a[0]), "r"(a[1]), "r"(a[2]), "r"(a[3]), "r"(b[0]), "r"(b[1]));
}

__global__ __launch_bounds__(256, 1)
void gemm_tc(const float* __restrict__ A, const float* __restrict__ W,
             float* __restrict__ C, int M, int N, int K, float alpha, int accum) {
    extern __shared__ float sm[];
    const int tid  = threadIdx.x;
    const int lane = tid & 31;
    const int wid  = tid >> 5;
    const int wm   = wid & 3;          // 4 warps along M (32 rows each)
    const int wn   = wid >> 2;         // 2 warps along N (64 cols each)
    const int bm   = blockIdx.y * 128, bn = blockIdx.x * 128;
    const int gid  = lane >> 2;        // group id 0..7
    const int tig  = lane & 3;         // thread in group 0..3

    float acc[2][8][4];
#pragma unroll
    for (int mt = 0; mt < 2; mt++)
#pragma unroll
        for (int nt = 0; nt < 8; nt++)
#pragma unroll
            for (int j = 0; j < 4; j++) acc[mt][nt][j] = 0.f;

    const int nIter = K >> 5;
    float4 ra[4], rw[4];
    const int fm[4] = { (tid + 0) >> 3, (tid + 256) >> 3,
                        (tid + 512) >> 3, (tid + 768) >> 3 };
    const int fk[4] = { (tid & 7) * 4, (tid & 7) * 4, (tid & 7) * 4, (tid & 7) * 4 };

    // ---- LDG tile it into registers ----
#define LDG_TILE(it) do {                                                   \
        int k0 = (it) * 32;                                                  \
        _Pragma("unroll")                                                    \
        for (int i = 0; i < 4; i++) {                                        \
            ra[i] = *reinterpret_cast<const float4*>(                        \
                A + (size_t)(bm + fm[i]) * K + k0 + fk[i]);                  \
            rw[i] = *reinterpret_cast<const float4*>(                        \
                W + (size_t)(bn + fm[i]) * K + k0 + fk[i]);                  \
        }                                                                    \
    } while (0)

    // ---- STS registers into stage buffer (with tf32 rounding) ----
#define STS_TILE(it) do {                                                   \
        float* sa = sm + ((it) & 1) * STAGE_FLOATS;                          \
        float* sw = sa + TILE_FLOATS;                                        \
        _Pragma("unroll")                                                    \
        for (int i = 0; i < 4; i++) {                                        \
            uint4 va = make_uint4(f2tf(ra[i].x), f2tf(ra[i].y),              \
                                  f2tf(ra[i].z), f2tf(ra[i].w));             \
            uint4 vw = make_uint4(f2tf(rw[i].x), f2tf(rw[i].y),              \
                                  f2tf(rw[i].z), f2tf(rw[i].w));             \
            *reinterpret_cast<uint4*>(sa + fm[i] * PAD_ + fk[i]) = va;       \
            *reinterpret_cast<uint4*>(sw + fm[i] * PAD_ + fk[i]) = vw;       \
        }                                                                    \
    } while (0)

    LDG_TILE(0);
    STS_TILE(0);
    __syncthreads();

    for (int it = 0; it < nIter; it++) {
        if (it + 1 < nIter) LDG_TILE(it + 1);

        const uint32_t* sA = reinterpret_cast<const uint32_t*>(
            sm + (it & 1) * STAGE_FLOATS);
        const uint32_t* sW = sA + TILE_FLOATS;

#pragma unroll
        for (int kk = 0; kk < 4; kk++) {
            const int kb = kk * 8;
            uint32_t afr[2][4], bfr[8][2];
#pragma unroll
            for (int mt = 0; mt < 2; mt++) {
                int m = wm * 32 + mt * 16 + gid;
                afr[mt][0] = sA[m * PAD_ + kb + tig];
                afr[mt][1] = sA[(m + 8) * PAD_ + kb + tig];
                afr[mt][2] = sA[m * PAD_ + kb + tig + 4];
                afr[mt][3] = sA[(m + 8) * PAD_ + kb + tig + 4];
            }
#pragma unroll
            for (int nt = 0; nt < 8; nt++) {
                int n = wn * 64 + nt * 8 + gid;
                bfr[nt][0] = sW[n * PAD_ + kb + tig];
                bfr[nt][1] = sW[n * PAD_ + kb + tig + 4];
            }
#pragma unroll
            for (int mt = 0; mt < 2; mt++)
#pragma unroll
                for (int nt = 0; nt < 8; nt++)
                    mma_tf32(acc[mt][nt], afr[mt], bfr[nt]);
        }

        if (it + 1 < nIter) STS_TILE(it + 1);
        __syncthreads();
    }

    // ---- epilogue ----
#pragma unroll
    for (int mt = 0; mt < 2; mt++) {
        int r0 = bm + wm * 32 + mt * 16 + gid;
#pragma unroll
        for (int nt = 0; nt < 8; nt++) {
            int col = bn + wn * 64 + nt * 8 + tig * 2;
            float* p0 = C + (size_t)r0 * N + col;
            float* p1 = C + (size_t)(r0 + 8) * N + col;
            if (accum) {
                float2 o0 = *reinterpret_cast<float2*>(p0);
                float2 o1 = *reinterpret_cast<float2*>(p1);
                o0.x += alpha * acc[mt][nt][0];
                o0.y += alpha * acc[mt][nt][1];
                o1.x += alpha * acc[mt][nt][2];
                o1.y += alpha * acc[mt][nt][3];
                *reinterpret_cast<float2*>(p0) = o0;
                *reinterpret_cast<float2*>(p1) = o1;
            } else {
                float2 o0 = make_float2(alpha * acc[mt][nt][0], alpha * acc[mt][nt][1]);
                float2 o1 = make_float2(alpha * acc[mt][nt][2], alpha * acc[mt][nt][3]);
                *reinterpret_cast<float2*>(p0) = o0;
                *reinterpret_cast<float2*>(p1) = o1;
            }
        }
    }
}

// =====================================================================
// non-GEMM kernels
// =====================================================================
__global__ void embed_kernel(const int* __restrict__ ids,
                             const float* __restrict__ emb,
                             float* __restrict__ x) {
    int row = blockIdx.x;
    int id = ids[row];
    const float* src = emb + (size_t)id * D_;
    float* dst = x + (size_t)row * D_;
    for (int d = threadIdx.x; d < D_; d += blockDim.x) dst[d] = src[d];
}

__global__ void rmsnorm_kernel(const float* __restrict__ x,
                               const float* __restrict__ w,
                               float* __restrict__ y, float eps) {
    __shared__ float red[256];
    int row = blockIdx.x;
    const float* xr = x + (size_t)row * D_;
    float s = 0.f;
    for (int d = threadIdx.x; d < D_; d += 256) { float v = xr[d]; s += v * v; }
    red[threadIdx.x] = s; __syncthreads();
    for (int o = 128; o > 0; o >>= 1) {
        if (threadIdx.x < o) red[threadIdx.x] += red[threadIdx.x + o];
        __syncthreads();
    }
    float r = rsqrtf(red[0] / D_ + eps);
    float* yr = y + (size_t)row * D_;
    for (int d = threadIdx.x; d < D_; d += 256) yr[d] = w[d] * xr[d] * r;
}

// one warp per (row, head)
__global__ void gdn_pre_kernel() {
    int gw = blockIdx.x * 8 + (threadIdx.x >> 5);   // 0 .. BS_*H_-1
    int lid = threadIdx.x & 31;
    int row = gw >> 4;
    int h = gw & 15;
    size_t base = (size_t)row * (5 * D_) + h * 64;
    float q0 = g_proj[base + lid];
    float q1 = g_proj[base + 32 + lid];
    float s = q0 * q0 + q1 * q1;
#pragma unroll
    for (int o = 16; o > 0; o >>= 1) s += __shfl_xor_sync(0xffffffffu, s, o);
    float r = rsqrtf(s / 64.f + QEPS_);
    size_t ob = (size_t)row * D_ + h * 64;
#pragma unroll
    for (int half = 0; half < 2; half++) {
        int d = half * 32 + lid;
        float q = half ? q1 : q0;
        g_qh[ob + d] = q * r;
        float kv = tanhf(g_proj[base + D_ + d]);
        float vv = g_proj[base + 2 * D_ + d];
        float av = 1.f / (1.f + expf(-(g_proj[base + 3 * D_ + d] + 2.f)));
        av = fminf(fmaxf(av, 0.6f), 0.9995f);
        g_u[ob + d] = kv * vv;
        g_a[ob + d] = av;
    }
}

// ---- 3-phase chunked gated scan ----
__global__ void scan_phase1() {
    int g = blockIdx.x * blockDim.x + threadIdx.x;   // c*2048 + lane
    int lane = g & 2047;
    int c = g >> 11;
    int b = lane >> 10, col = lane & 1023;
    float p = 1.f, acc = 0.f;
    size_t idx0 = (size_t)(b * S_ + c * CHUNK_) * D_ + col;
    for (int t = 0; t < CHUNK_; t++) {
        size_t idx = idx0 + (size_t)t * D_;
        p *= g_a[idx];
        acc += g_u[idx] / fmaxf(p, 1e-6f);
    }
    g_scanP[g] = p; g_scanA[g] = acc;
}
__global__ void scan_phase2() {
    int lane = blockIdx.x * blockDim.x + threadIdx.x;   // 0..2047
    float carry = 0.f;
    for (int c = 0; c < NCHUNK_; c++) {
        int i = c * 2048 + lane;
        g_scanC[i] = carry;
        carry = g_scanP[i] * (carry + g_scanA[i]);
    }
}
__global__ void scan_phase3() {
    int g = blockIdx.x * blockDim.x + threadIdx.x;
    int lane = g & 2047;
    int c = g >> 11;
    int b = lane >> 10, col = lane & 1023;
    float carry = g_scanC[g];
    float p = 1.f, acc = 0.f;
    size_t idx0 = (size_t)(b * S_ + c * CHUNK_) * D_ + col;
    for (int t = 0; t < CHUNK_; t++) {
        size_t idx = idx0 + (size_t)t * D_;
        p *= g_a[idx];
        acc += g_u[idx] / fmaxf(p, 1e-6f);
        g_mem[idx] = p * (carry + acc);
    }
}

__global__ void gdn_post_kernel() {
    int i = blockIdx.x * blockDim.x + threadIdx.x;
    int row = i >> 10, d = i & 1023;
    size_t base = (size_t)row * (5 * D_);
    float gv = g_proj[base + 4 * D_ + d];
    float vv = g_proj[base + 2 * D_ + d];
    float gate = 1.f / (1.f + expf(-gv));
    g_y[i] = gate * (g_qh[i] * g_mem[i]) + (1.f - gate) * vv;
}

__global__ void silu_kernel(float* __restrict__ h, int n) {
    int i = blockIdx.x * blockDim.x + threadIdx.x;
    if (i < n) { float v = h[i]; h[i] = v / (1.f + expf(-v)); }
}

// ---- flash causal attention (fp32 SIMT) ----
__global__ __launch_bounds__(128)
void flash_attn_kernel() {
    __shared__ float Ks[64][64];
    __shared__ float Vs[64][64];
    const int qt = blockIdx.x & 15;
    const int h  = (blockIdx.x >> 4) & 15;
    const int b  = blockIdx.x >> 8;
    const int qi = qt * 128 + threadIdx.x;
    const float scale = 0.125f;

    float qr[64], acc[64];
    {
        const float* qp = g_proj + (size_t)(b * S_ + qi) * (3 * D_) + h * HD_;
#pragma unroll
        for (int d = 0; d < 64; d++) { qr[d] = qp[d]; acc[d] = 0.f; }
    }
    float m = -1e30f, l = 0.f;
    const int last_tile = (qt * 128 + 127) / 64;

    for (int kt = 0; kt <= last_tile; kt++) {
#pragma unroll
        for (int ld = 0; ld < 32; ld++) {
            int idx = threadIdx.x + ld * 128;
            int kr = idx >> 6, kc = idx & 63;
            size_t base = (size_t)(b * S_ + kt * 64 + kr) * (3 * D_) + h * HD_ + kc;
            Ks[kr][kc] = g_proj[base + D_];
            Vs[kr][kc] = g_proj[base + 2 * D_];
        }
        __syncthreads();
        int jmax = min(64, qi - kt * 64 + 1);
        for (int j = 0; j < jmax; j++) {
            float s = 0.f;
#pragma unroll
            for (int d = 0; d < 64; d++) s = fmaf(qr[d], Ks[j][d], s);
            s *= scale;
            float nm = fmaxf(m, s);
            float corr = expf(m - nm);
            float p = expf(s - nm);
            l = l * corr + p;
            if (corr != 1.f) {
#pragma unroll
                for (int d = 0; d < 64; d++) acc[d] = acc[d] * corr + p * Vs[j][d];
            } else {
#pragma unroll
                for (int d = 0; d < 64; d++) acc[d] = fmaf(p, Vs[j][d], acc[d]);
            }
            m = nm;
        }
        __syncthreads();
    }
    float inv = 1.f / l;
    float* yp = g_y + (size_t)(b * S_ + qi) * D_ + h * HD_;
#pragma unroll
    for (int d = 0; d < 64; d++) yp[d] = acc[d] * inv;
}

// ---- loss ----
__global__ void loss_rows_kernel(const float* __restrict__ bias,
                                 const int* __restrict__ tgt) {
    __shared__ float red[256];
    int row = blockIdx.x;
    const float* lr = g_logits + (size_t)row * V_;
    float lm = -1e30f;
    for (int v = threadIdx.x; v < V_; v += 256) lm = fmaxf(lm, lr[v] + bias[v]);
    red[threadIdx.x] = lm; __syncthreads();
    for (int o = 128; o > 0; o >>= 1) {
        if (threadIdx.x < o) red[threadIdx.x] = fmaxf(red[threadIdx.x], red[threadIdx.x + o]);
        __syncthreads();
    }
    float M = red[0]; __syncthreads();
    float s = 0.f;
    for (int v = threadIdx.x; v < V_; v += 256) s += expf(lr[v] + bias[v] - M);
    red[threadIdx.x] = s; __syncthreads();
    for (int o = 128; o > 0; o >>= 1) {
        if (threadIdx.x < o) red[threadIdx.x] += red[threadIdx.x + o];
        __syncthreads();
    }
    if (threadIdx.x == 0) {
        int t = tgt[row];
        float lt = lr[t] + bias[t];
        g_rowloss[row] = -(lt - M - logf(red[0]));
    }
}

__global__ void loss_reduce_kernel(float* __restrict__ out) {
    __shared__ float red[256];
    float s = 0.f;
    for (int i = threadIdx.x; i < BS_; i += 256) s += g_rowloss[i];
    red[threadIdx.x] = s; __syncthreads();
    for (int o = 128; o > 0; o >>= 1) {
        if (threadIdx.x < o) red[threadIdx.x] += red[threadIdx.x + o];
        __syncthreads();
    }
    if (threadIdx.x == 0) out[0] = red[0] / (float)BS_;
}

// =====================================================================
// host orchestration
// =====================================================================
static void launch_gemm(const float* A, const float* W, float* C,
                        int M, int N, int K, float alpha, int accum) {
    dim3 grid(N / 128, M / 128);
    gemm_tc<<<grid, 256, GT_SMEM_BYTES>>>(A, W, C, M, N, K, alpha, accum);
}

extern "C" void kernel_launch(void* const* d_in, const int* in_sizes, int n_in,
                              void* d_out, int out_size) {
    const int*   input_ids   = (const int*)  d_in[0];
    const int*   target_ids  = (const int*)  d_in[1];
    const float* tok_emb     = (const float*)d_in[2];
    const float* lm_bias     = (const float*)d_in[3];
    const float* gdn_in_w    = (const float*)d_in[4];
    const float* gdn_out_w   = (const float*)d_in[5];
    const float* gdn_norm1   = (const float*)d_in[6];
    const float* gdn_norm2   = (const float*)d_in[7];
    const float* gdn_fc_w    = (const float*)d_in[8];
    const float* gdn_proj_w  = (const float*)d_in[9];
    const float* attn_qkv_w  = (const float*)d_in[10];
    const float* attn_proj_w = (const float*)d_in[11];
    const float* attn_norm1  = (const float*)d_in[12];
    const float* attn_norm2  = (const float*)d_in[13];
    const float* attn_fc_w   = (const float*)d_in[14];
    const float* attn_mlp_w  = (const float*)d_in[15];
    const float* final_norm  = (const float*)d_in[16];
    float* out = (float*)d_out;

    cudaFuncSetAttribute(gemm_tc, cudaFuncAttributeMaxDynamicSharedMemorySize,
                         GT_SMEM_BYTES);

    float *x, *xn, *proj, *y, *logits;
    cudaGetSymbolAddress((void**)&x,      g_x);
    cudaGetSymbolAddress((void**)&xn,     g_xn);
    cudaGetSymbolAddress((void**)&proj,   g_proj);
    cudaGetSymbolAddress((void**)&y,      g_y);
    cudaGetSymbolAddress((void**)&logits, g_logits);

    embed_kernel<<<BS_, 256>>>(input_ids, tok_emb, x);

    for (int i = 0; i < LG_; i++) {
        float rsc = rsqrtf(2.0f * (i + 1));
        rmsnorm_kernel<<<BS_, 256>>>(x, gdn_norm1 + (size_t)i * D_, xn, 1e-6f);
        launch_gemm(xn, gdn_in_w + (size_t)i * 5 * D_ * D_, proj, BS_, 5 * D_, D_, 1.f, 0);
        gdn_pre_kernel<<<BS_ * H_ / 8, 256>>>();
        scan_phase1<<<B_ * D_ * NCHUNK_ / 256, 256>>>();
        scan_phase2<<<B_ * D_ / 256, 256>>>();
        scan_phase3<<<B_ * D_ * NCHUNK_ / 256, 256>>>();
        gdn_post_kernel<<<BS_ * D_ / 256, 256>>>();
        launch_gemm(y, gdn_out_w + (size_t)i * D_ * D_, x, BS_, D_, D_, rsc, 1);
        rmsnorm_kernel<<<BS_, 256>>>(x, gdn_norm2 + (size_t)i * D_, xn, 1e-6f);
        launch_gemm(xn, gdn_fc_w + (size_t)i * HM_ * D_, proj, BS_, HM_, D_, 1.f, 0);
        silu_kernel<<<BS_ * HM_ / 256, 256>>>(proj, BS_ * HM_);
        launch_gemm(proj, gdn_proj_w + (size_t)i * D_ * HM_, x, BS_, D_, HM_, rsc, 1);
    }

    float rsc = rsqrtf(2.0f * (LG_ + 1));
    rmsnorm_kernel<<<BS_, 256>>>(x, attn_norm1, xn, 1e-6f);
    launch_gemm(xn, attn_qkv_w, proj, BS_, 3 * D_, D_, 1.f, 0);
    flash_attn_kernel<<<B_ * H_ * (S_ / 128), 128>>>();
    launch_gemm(y, attn_proj_w, x, BS_, D_, D_, rsc, 1);
    rmsnorm_kernel<<<BS_, 256>>>(x, attn_norm2, xn, 1e-6f);
    launch_gemm(xn, attn_fc_w, proj, BS_, HM_, D_, 1.f, 0);
    silu_kernel<<<BS_ * HM_ / 256, 256>>>(proj, BS_ * HM_);
    launch_gemm(proj, attn_mlp_w, x, BS_, D_, HM_, rsc, 1);

    rmsnorm_kernel<<<BS_, 256>>>(x, final_norm, xn, 1e-6f);
    launch_gemm(xn, tok_emb, logits, BS_, V_, D_, 1.f, 0);
    loss_rows_kernel<<<BS_, 256>>>(lm_bias, target_ids);
    loss_reduce_kernel<<<1, 256>>>(out);
}

// round 4
// speedup vs baseline: 7.0753x; 1.4779x over previous
#include <cuda_runtime.h>
#include <cuda_bf16.h>
#include <math.h>
#include <stdint.h>

// ---------------- problem constants ----------------
#define B_      2
#define S_      2048
#define BS_     (B_*S_)          // 4096 token rows
#define D_      1024
#define H_      16
#define HD_     64
#define HM_     4096
#define V_      32768
#define LG_     8
#define CHUNK_  64
#define NCHUNK_ (S_/CHUNK_)      // 32
#define QEPS_   1.1920929e-07f

// ---------------- static device scratch ----------------
__device__ float g_x   [BS_*D_];
__device__ float g_xn  [BS_*D_];
__device__ float g_proj[BS_*5*D_];
__device__ float g_qh  [BS_*D_];
__device__ float g_u   [BS_*D_];
__device__ float g_a   [BS_*D_];
__device__ float g_y   [BS_*D_];
__device__ float g_scanP[B_*D_*NCHUNK_];
__device__ float g_scanA[B_*D_*NCHUNK_];
__device__ float g_scanC[B_*D_*NCHUNK_];
__device__ float g_logits[(size_t)BS_*V_];   // 512 MB
__device__ float g_rowloss[BS_];

// =====================================================================
// bf16 mma.sync GEMM: C[M,N] = op(alpha * A[M,K] @ W[N,K]^T)
// 128x128 block tile, K-tile 64, 8 warps (warp tile 32x64),
// double-buffered SMEM, pad-36(u32) layout: LDG coalesced, STS/LDS bank-free.
// mode: 0 = overwrite (alpha), 1 = accumulate (alpha), 2 = silu (alpha ignored)
// M,N multiples of 128; K multiple of 64.
// =====================================================================
#define PADU_ 36
#define TILE_U32 (128*PADU_)
#define STAGE_U32 (2*TILE_U32)
#define GT_SMEM_BYTES (2*STAGE_U32*4)   // 73728 B

__device__ __forceinline__ uint32_t pack_bf16(float lo, float hi) {
    __nv_bfloat162 h = __floats2bfloat162_rn(lo, hi);
    return *reinterpret_cast<uint32_t*>(&h);
}

__device__ __forceinline__ void mma_bf16(float c[4], const uint32_t a[4],
                                         const uint32_t b[2]) {
    asm volatile(
        "mma.sync.aligned.m16n8k16.row.col.f32.bf16.bf16.f32 "
        "{%0,%1,%2,%3}, {%4,%5,%6,%7}, {%8,%9}, {%0,%1,%2,%3};"
        : "+f"(c[0]), "+f"(c[1]), "+f"(c[2]), "+f"(c[3])
        : "r"(a[0]), "r"(a[1]), "r"(a[2]), "r"(a[3]), "r"(b[0]), "r"(b[1]));
}

__global__ __launch_bounds__(256, 1)
void gemm_tc(const float* __restrict__ A, const float* __restrict__ W,
             float* __restrict__ C, int M, int N, int K, float alpha, int mode) {
    extern __shared__ uint32_t sm[];
    const int tid  = threadIdx.x;
    const int lane = tid & 31;
    const int wid  = tid >> 5;
    const int wm   = wid & 3;          // 4 warps along M (32 rows each)
    const int wn   = wid >> 2;         // 2 warps along N (64 cols each)
    const int bm   = blockIdx.y * 128, bn = blockIdx.x * 128;
    const int gid  = lane >> 2;
    const int tig  = lane & 3;

    float acc[2][8][4];
#pragma unroll
    for (int mt = 0; mt < 2; mt++)
#pragma unroll
        for (int nt = 0; nt < 8; nt++)
#pragma unroll
            for (int j = 0; j < 4; j++) acc[mt][nt][j] = 0.f;

    const int nIter = K >> 6;          // K/64
    const int r0_ = tid >> 4;          // 0..15
    const int c4_ = tid & 15;          // float4 column index (k = c4*4)
    float4 ra[8], rw[8];

#define LDG_TILE(it) do {                                                   \
        int k0 = (it) * 64;                                                  \
        _Pragma("unroll")                                                    \
        for (int i = 0; i < 8; i++) {                                        \
            int r = r0_ + i * 16;                                            \
            ra[i] = *reinterpret_cast<const float4*>(                        \
                A + (size_t)(bm + r) * K + k0 + c4_ * 4);                    \
            rw[i] = *reinterpret_cast<const float4*>(                        \
                W + (size_t)(bn + r) * K + k0 + c4_ * 4);                    \
        }                                                                    \
    } while (0)

#define STS_TILE(it) do {                                                   \
        uint32_t* sa = sm + ((it) & 1) * STAGE_U32;                          \
        uint32_t* sw = sa + TILE_U32;                                        \
        _Pragma("unroll")                                                    \
        for (int i = 0; i < 8; i++) {                                        \
            int r = r0_ + i * 16;                                            \
            uint2 va = make_uint2(pack_bf16(ra[i].x, ra[i].y),               \
                                  pack_bf16(ra[i].z, ra[i].w));              \
            uint2 vw = make_uint2(pack_bf16(rw[i].x, rw[i].y),               \
                                  pack_bf16(rw[i].z, rw[i].w));              \
            *reinterpret_cast<uint2*>(sa + r * PADU_ + c4_ * 2) = va;        \
            *reinterpret_cast<uint2*>(sw + r * PADU_ + c4_ * 2) = vw;        \
        }                                                                    \
    } while (0)

    LDG_TILE(0);
    STS_TILE(0);
    __syncthreads();

    for (int it = 0; it < nIter; it++) {
        if (it + 1 < nIter) LDG_TILE(it + 1);

        const uint32_t* sA = sm + (it & 1) * STAGE_U32;
        const uint32_t* sW = sA + TILE_U32;

#pragma unroll
        for (int kk = 0; kk < 4; kk++) {
            const int kb = kk * 8;     // u32 offset (16 halves per sub-step)
            uint32_t afr[2][4], bfr[8][2];
#pragma unroll
            for (int mt = 0; mt < 2; mt++) {
                int m = wm * 32 + mt * 16 + gid;
                afr[mt][0] = sA[m * PADU_ + kb + tig];
                afr[mt][1] = sA[(m + 8) * PADU_ + kb + tig];
                afr[mt][2] = sA[m * PADU_ + kb + 4 + tig];
                afr[mt][3] = sA[(m + 8) * PADU_ + kb + 4 + tig];
            }
#pragma unroll
            for (int nt = 0; nt < 8; nt++) {
                int n = wn * 64 + nt * 8 + gid;
                bfr[nt][0] = sW[n * PADU_ + kb + tig];
                bfr[nt][1] = sW[n * PADU_ + kb + 4 + tig];
            }
#pragma unroll
            for (int mt = 0; mt < 2; mt++)
#pragma unroll
                for (int nt = 0; nt < 8; nt++)
                    mma_bf16(acc[mt][nt], afr[mt], bfr[nt]);
        }

        if (it + 1 < nIter) STS_TILE(it + 1);
        __syncthreads();
    }

    // ---- epilogue ----
#pragma unroll
    for (int mt = 0; mt < 2; mt++) {
        int r0 = bm + wm * 32 + mt * 16 + gid;
#pragma unroll
        for (int nt = 0; nt < 8; nt++) {
            int col = bn + wn * 64 + nt * 8 + tig * 2;
            float* p0 = C + (size_t)r0 * N + col;
            float* p1 = C + (size_t)(r0 + 8) * N + col;
            if (mode == 1) {
                float2 o0 = *reinterpret_cast<float2*>(p0);
                float2 o1 = *reinterpret_cast<float2*>(p1);
                o0.x += alpha * acc[mt][nt][0];
                o0.y += alpha * acc[mt][nt][1];
                o1.x += alpha * acc[mt][nt][2];
                o1.y += alpha * acc[mt][nt][3];
                *reinterpret_cast<float2*>(p0) = o0;
                *reinterpret_cast<float2*>(p1) = o1;
            } else if (mode == 2) {
                float v0 = acc[mt][nt][0], v1 = acc[mt][nt][1];
                float v2 = acc[mt][nt][2], v3 = acc[mt][nt][3];
                *reinterpret_cast<float2*>(p0) =
                    make_float2(v0 / (1.f + expf(-v0)), v1 / (1.f + expf(-v1)));
                *reinterpret_cast<float2*>(p1) =
                    make_float2(v2 / (1.f + expf(-v2)), v3 / (1.f + expf(-v3)));
            } else {
                *reinterpret_cast<float2*>(p0) =
                    make_float2(alpha * acc[mt][nt][0], alpha * acc[mt][nt][1]);
                *reinterpret_cast<float2*>(p1) =
                    make_float2(alpha * acc[mt][nt][2], alpha * acc[mt][nt][3]);
            }
        }
    }
}

// =====================================================================
// non-GEMM kernels
// =====================================================================
__global__ void embed_kernel(const int* __restrict__ ids,
                             const float* __restrict__ emb,
                             float* __restrict__ x) {
    int row = blockIdx.x;
    int id = ids[row];
    const float* src = emb + (size_t)id * D_;
    float* dst = x + (size_t)row * D_;
    for (int d = threadIdx.x; d < D_; d += blockDim.x) dst[d] = src[d];
}

__global__ void rmsnorm_kernel(const float* __restrict__ x,
                               const float* __restrict__ w,
                               float* __restrict__ y, float eps) {
    __shared__ float red[256];
    int row = blockIdx.x;
    const float* xr = x + (size_t)row * D_;
    float s = 0.f;
    for (int d = threadIdx.x; d < D_; d += 256) { float v = xr[d]; s += v * v; }
    red[threadIdx.x] = s; __syncthreads();
    for (int o = 128; o > 0; o >>= 1) {
        if (threadIdx.x < o) red[threadIdx.x] += red[threadIdx.x + o];
        __syncthreads();
    }
    float r = rsqrtf(red[0] / D_ + eps);
    float* yr = y + (size_t)row * D_;
    for (int d = threadIdx.x; d < D_; d += 256) yr[d] = w[d] * xr[d] * r;
}

// one warp per (row, head)
__global__ void gdn_pre_kernel() {
    int gw = blockIdx.x * 8 + (threadIdx.x >> 5);   // 0 .. BS_*H_-1
    int lid = threadIdx.x & 31;
    int row = gw >> 4;
    int h = gw & 15;
    size_t base = (size_t)row * (5 * D_) + h * 64;
    float q0 = g_proj[base + lid];
    float q1 = g_proj[base + 32 + lid];
    float s = q0 * q0 + q1 * q1;
#pragma unroll
    for (int o = 16; o > 0; o >>= 1) s += __shfl_xor_sync(0xffffffffu, s, o);
    float r = rsqrtf(s / 64.f + QEPS_);
    size_t ob = (size_t)row * D_ + h * 64;
#pragma unroll
    for (int half = 0; half < 2; half++) {
        int d = half * 32 + lid;
        float q = half ? q1 : q0;
        g_qh[ob + d] = q * r;
        float kv = tanhf(g_proj[base + D_ + d]);
        float vv = g_proj[base + 2 * D_ + d];
        float av = 1.f / (1.f + expf(-(g_proj[base + 3 * D_ + d] + 2.f)));
        av = fminf(fmaxf(av, 0.6f), 0.9995f);
        g_u[ob + d] = kv * vv;
        g_a[ob + d] = av;
    }
}

// ---- chunked gated scan ----
__global__ void scan_phase1() {
    int g = blockIdx.x * blockDim.x + threadIdx.x;   // c*2048 + lane
    int lane = g & 2047;
    int c = g >> 11;
    int b = lane >> 10, col = lane & 1023;
    float p = 1.f, acc = 0.f;
    size_t idx0 = (size_t)(b * S_ + c * CHUNK_) * D_ + col;
    for (int t = 0; t < CHUNK_; t++) {
        size_t idx = idx0 + (size_t)t * D_;
        p *= g_a[idx];
        acc += g_u[idx] / fmaxf(p, 1e-6f);
    }
    g_scanP[g] = p; g_scanA[g] = acc;
}
__global__ void scan_phase2() {
    int lane = blockIdx.x * blockDim.x + threadIdx.x;   // 0..2047
    float carry = 0.f;
    for (int c = 0; c < NCHUNK_; c++) {
        int i = c * 2048 + lane;
        g_scanC[i] = carry;
        carry = g_scanP[i] * (carry + g_scanA[i]);
    }
}
// phase3 fused with gdn_post: computes mem inline and writes y directly
__global__ void scan_phase3_post() {
    int g = blockIdx.x * blockDim.x + threadIdx.x;
    int lane = g & 2047;
    int c = g >> 11;
    int b = lane >> 10, col = lane & 1023;
    float carry = g_scanC[g];
    float p = 1.f, acc = 0.f;
    int row0 = b * S_ + c * CHUNK_;
    for (int t = 0; t < CHUNK_; t++) {
        int row = row0 + t;
        size_t idx = (size_t)row * D_ + col;
        p *= g_a[idx];
        acc += g_u[idx] / fmaxf(p, 1e-6f);
        float mem = p * (carry + acc);
        size_t b5 = (size_t)row * (5 * D_);
        float gate = 1.f / (1.f + expf(-g_proj[b5 + 4 * D_ + col]));
        float vv = g_proj[b5 + 2 * D_ + col];
        g_y[idx] = gate * (g_qh[idx] * mem) + (1.f - gate) * vv;
    }
}

// ---- flash causal attention (fp32 SIMT) ----
__global__ __launch_bounds__(128)
void flash_attn_kernel() {
    __shared__ float Ks[64][64];
    __shared__ float Vs[64][64];
    const int qt = blockIdx.x & 15;
    const int h  = (blockIdx.x >> 4) & 15;
    const int b  = blockIdx.x >> 8;
    const int qi = qt * 128 + threadIdx.x;
    const float scale = 0.125f;

    float qr[64], acc[64];
    {
        const float* qp = g_proj + (size_t)(b * S_ + qi) * (3 * D_) + h * HD_;
#pragma unroll
        for (int d = 0; d < 64; d++) { qr[d] = qp[d]; acc[d] = 0.f; }
    }
    float m = -1e30f, l = 0.f;
    const int last_tile = (qt * 128 + 127) / 64;

    for (int kt = 0; kt <= last_tile; kt++) {
#pragma unroll
        for (int ld = 0; ld < 32; ld++) {
            int idx = threadIdx.x + ld * 128;
            int kr = idx >> 6, kc = idx & 63;
            size_t base = (size_t)(b * S_ + kt * 64 + kr) * (3 * D_) + h * HD_ + kc;
            Ks[kr][kc] = g_proj[base + D_];
            Vs[kr][kc] = g_proj[base + 2 * D_];
        }
        __syncthreads();
        int jmax = min(64, qi - kt * 64 + 1);
        for (int j = 0; j < jmax; j++) {
            float s = 0.f;
#pragma unroll
            for (int d = 0; d < 64; d++) s = fmaf(qr[d], Ks[j][d], s);
            s *= scale;
            float nm = fmaxf(m, s);
            float corr = expf(m - nm);
            float p = expf(s - nm);
            l = l * corr + p;
            if (corr != 1.f) {
#pragma unroll
                for (int d = 0; d < 64; d++) acc[d] = acc[d] * corr + p * Vs[j][d];
            } else {
#pragma unroll
                for (int d = 0; d < 64; d++) acc[d] = fmaf(p, Vs[j][d], acc[d]);
            }
            m = nm;
        }
        __syncthreads();
    }
    float inv = 1.f / l;
    float* yp = g_y + (size_t)(b * S_ + qi) * D_ + h * HD_;
#pragma unroll
    for (int d = 0; d < 64; d++) yp[d] = acc[d] * inv;
}

// ---- loss ----
__global__ void loss_rows_kernel(const float* __restrict__ bias,
                                 const int* __restrict__ tgt) {
    __shared__ float red[256];
    int row = blockIdx.x;
    const float* lr = g_logits + (size_t)row * V_;
    float lm = -1e30f;
    for (int v = threadIdx.x; v < V_; v += 256) lm = fmaxf(lm, lr[v] + bias[v]);
    red[threadIdx.x] = lm; __syncthreads();
    for (int o = 128; o > 0; o >>= 1) {
        if (threadIdx.x < o) red[threadIdx.x] = fmaxf(red[threadIdx.x], red[threadIdx.x + o]);
        __syncthreads();
    }
    float M = red[0]; __syncthreads();
    float s = 0.f;
    for (int v = threadIdx.x; v < V_; v += 256) s += expf(lr[v] + bias[v] - M);
    red[threadIdx.x] = s; __syncthreads();
    for (int o = 128; o > 0; o >>= 1) {
        if (threadIdx.x < o) red[threadIdx.x] += red[threadIdx.x + o];
        __syncthreads();
    }
    if (threadIdx.x == 0) {
        int t = tgt[row];
        float lt = lr[t] + bias[t];
        g_rowloss[row] = -(lt - M - logf(red[0]));
    }
}

__global__ void loss_reduce_kernel(float* __restrict__ out) {
    __shared__ float red[256];
    float s = 0.f;
    for (int i = threadIdx.x; i < BS_; i += 256) s += g_rowloss[i];
    red[threadIdx.x] = s; __syncthreads();
    for (int o = 128; o > 0; o >>= 1) {
        if (threadIdx.x < o) red[threadIdx.x] += red[threadIdx.x + o];
        __syncthreads();
    }
    if (threadIdx.x == 0) out[0] = red[0] / (float)BS_;
}

// =====================================================================
// host orchestration
// =====================================================================
static void launch_gemm(const float* A, const float* W, float* C,
                        int M, int N, int K, float alpha, int mode) {
    dim3 grid(N / 128, M / 128);
    gemm_tc<<<grid, 256, GT_SMEM_BYTES>>>(A, W, C, M, N, K, alpha, mode);
}

extern "C" void kernel_launch(void* const* d_in, const int* in_sizes, int n_in,
                              void* d_out, int out_size) {
    const int*   input_ids   = (const int*)  d_in[0];
    const int*   target_ids  = (const int*)  d_in[1];
    const float* tok_emb     = (const float*)d_in[2];
    const float* lm_bias     = (const float*)d_in[3];
    const float* gdn_in_w    = (const float*)d_in[4];
    const float* gdn_out_w   = (const float*)d_in[5];
    const float* gdn_norm1   = (const float*)d_in[6];
    const float* gdn_norm2   = (const float*)d_in[7];
    const float* gdn_fc_w    = (const float*)d_in[8];
    const float* gdn_proj_w  = (const float*)d_in[9];
    const float* attn_qkv_w  = (const float*)d_in[10];
    const float* attn_proj_w = (const float*)d_in[11];
    const float* attn_norm1  = (const float*)d_in[12];
    const float* attn_norm2  = (const float*)d_in[13];
    const float* attn_fc_w   = (const float*)d_in[14];
    const float* attn_mlp_w  = (const float*)d_in[15];
    const float* final_norm  = (const float*)d_in[16];
    float* out = (float*)d_out;

    cudaFuncSetAttribute(gemm_tc, cudaFuncAttributeMaxDynamicSharedMemorySize,
                         GT_SMEM_BYTES);

    float *x, *xn, *proj, *y, *logits;
    cudaGetSymbolAddress((void**)&x,      g_x);
    cudaGetSymbolAddress((void**)&xn,     g_xn);
    cudaGetSymbolAddress((void**)&proj,   g_proj);
    cudaGetSymbolAddress((void**)&y,      g_y);
    cudaGetSymbolAddress((void**)&logits, g_logits);

    embed_kernel<<<BS_, 256>>>(input_ids, tok_emb, x);

    for (int i = 0; i < LG_; i++) {
        float rsc = rsqrtf(2.0f * (i + 1));
        rmsnorm_kernel<<<BS_, 256>>>(x, gdn_norm1 + (size_t)i * D_, xn, 1e-6f);
        launch_gemm(xn, gdn_in_w + (size_t)i * 5 * D_ * D_, proj, BS_, 5 * D_, D_, 1.f, 0);
        gdn_pre_kernel<<<BS_ * H_ / 8, 256>>>();
        scan_phase1<<<B_ * D_ * NCHUNK_ / 256, 256>>>();
        scan_phase2<<<B_ * D_ / 256, 256>>>();
        scan_phase3_post<<<B_ * D_ * NCHUNK_ / 256, 256>>>();
        launch_gemm(y, gdn_out_w + (size_t)i * D_ * D_, x, BS_, D_, D_, rsc, 1);
        rmsnorm_kernel<<<BS_, 256>>>(x, gdn_norm2 + (size_t)i * D_, xn, 1e-6f);
        launch_gemm(xn, gdn_fc_w + (size_t)i * HM_ * D_, proj, BS_, HM_, D_, 1.f, 2);
        launch_gemm(proj, gdn_proj_w + (size_t)i * D_ * HM_, x, BS_, D_, HM_, rsc, 1);
    }

    float rsc = rsqrtf(2.0f * (LG_ + 1));
    rmsnorm_kernel<<<BS_, 256>>>(x, attn_norm1, xn, 1e-6f);
    launch_gemm(xn, attn_qkv_w, proj, BS_, 3 * D_, D_, 1.f, 0);
    flash_attn_kernel<<<B_ * H_ * (S_ / 128), 128>>>();
    launch_gemm(y, attn_proj_w, x, BS_, D_, D_, rsc, 1);
    rmsnorm_kernel<<<BS_, 256>>>(x, attn_norm2, xn, 1e-6f);
    launch_gemm(xn, attn_fc_w, proj, BS_, HM_, D_, 1.f, 2);
    launch_gemm(proj, attn_mlp_w, x, BS_, D_, HM_, rsc, 1);

    rmsnorm_kernel<<<BS_, 256>>>(x, final_norm, xn, 1e-6f);
    launch_gemm(xn, tok_emb, logits, BS_, V_, D_, 1.f, 0);
    loss_rows_kernel<<<BS_, 256>>>(lm_bias, target_ids);
    loss_reduce_kernel<<<1, 256>>>(out);
}

// round 5
// speedup vs baseline: 8.3914x; 1.1860x over previous
#include <cuda_runtime.h>
#include <cuda_bf16.h>
#include <math.h>
#include <stdint.h>

// ---------------- problem constants ----------------
#define B_      2
#define S_      2048
#define BS_     (B_*S_)          // 4096 token rows
#define D_      1024
#define H_      16
#define HD_     64
#define HM_     4096
#define V_      32768
#define LG_     8
#define CHUNK_  64
#define NCHUNK_ (S_/CHUNK_)      // 32
#define QEPS_   1.1920929e-07f

typedef __nv_bfloat16 bf16;

// ---------------- static device scratch ----------------
__device__ float g_x   [BS_*D_];
__device__ bf16  g_xn  [BS_*D_];
__device__ float g_proj[BS_*5*D_];
__device__ float g_qh  [BS_*D_];
__device__ float g_u   [BS_*D_];
__device__ float g_a   [BS_*D_];
__device__ bf16  g_y   [BS_*D_];
__device__ bf16  g_hid [BS_*HM_];
__device__ float g_scanP[B_*D_*NCHUNK_];
__device__ float g_scanA[B_*D_*NCHUNK_];
__device__ float g_scanC[B_*D_*NCHUNK_];
__device__ float g_logits[(size_t)BS_*V_];   // 512 MB
__device__ float g_rowloss[BS_];

// bf16 weight mirrors (converted once per launch)
__device__ bf16 w_gdn_in [LG_*5*D_*D_];
__device__ bf16 w_gdn_out[LG_*D_*D_];
__device__ bf16 w_gdn_fc [LG_*HM_*D_];
__device__ bf16 w_gdn_pj [LG_*D_*HM_];
__device__ bf16 w_qkv    [3*D_*D_];
__device__ bf16 w_apj    [D_*D_];
__device__ bf16 w_afc    [HM_*D_];
__device__ bf16 w_ampj   [D_*HM_];
__device__ bf16 w_emb    [(size_t)V_*D_];

// =====================================================================
// helpers
// =====================================================================
__device__ __forceinline__ uint32_t smem_u32(const void* p) {
    uint32_t a;
    asm("{ .reg .u64 t; cvta.to.shared.u64 t, %1; cvt.u32.u64 %0, t; }"
        : "=r"(a) : "l"(p));
    return a;
}
__device__ __forceinline__ uint32_t pack_bf16(float lo, float hi) {
    __nv_bfloat162 h = __floats2bfloat162_rn(lo, hi);
    return *reinterpret_cast<uint32_t*>(&h);
}
__device__ __forceinline__ void cp16(uint32_t dst, const void* src) {
    asm volatile("cp.async.cg.shared.global [%0], [%1], 16;"
                 :: "r"(dst), "l"(src) : "memory");
}
#define CP_COMMIT() asm volatile("cp.async.commit_group;" ::: "memory")
#define CP_WAIT1()  asm volatile("cp.async.wait_group 1;" ::: "memory")

__device__ __forceinline__ void ldsm4(uint32_t r[4], uint32_t addr) {
    asm volatile("ldmatrix.sync.aligned.m8n8.x4.shared.b16 {%0,%1,%2,%3}, [%4];"
                 : "=r"(r[0]), "=r"(r[1]), "=r"(r[2]), "=r"(r[3]) : "r"(addr));
}
__device__ __forceinline__ void mma_bf16(float c[4], const uint32_t a[4],
                                         const uint32_t b[2]) {
    asm volatile(
        "mma.sync.aligned.m16n8k16.row.col.f32.bf16.bf16.f32 "
        "{%0,%1,%2,%3}, {%4,%5,%6,%7}, {%8,%9}, {%0,%1,%2,%3};"
        : "+f"(c[0]), "+f"(c[1]), "+f"(c[2]), "+f"(c[3])
        : "r"(a[0]), "r"(a[1]), "r"(a[2]), "r"(a[3]), "r"(b[0]), "r"(b[1]));
}

// =====================================================================
// bf16 GEMM: C[M,N] = op(alpha * A[M,K] @ W[N,K]^T)   (A,W bf16; acc fp32)
// 128x128 block tile, K-tile 64 halves, 3-stage cp.async pipeline,
// XOR-swizzled smem + ldmatrix fragments.
// mode: 0 = fp32 overwrite, 1 = fp32 accumulate, 2 = bf16 silu
// =====================================================================
#define TILE_B  16384u            // 128 rows * 128 bytes
#define STAGE_B 32768u            // A + W
#define GT_SMEM_BYTES (3*STAGE_B) // 98304

__global__ __launch_bounds__(256, 1)
void gemm_tc(const bf16* __restrict__ A, const bf16* __restrict__ W,
             void* __restrict__ Cv, int M, int N, int K, float alpha, int mode) {
    extern __shared__ char smraw[];
    const uint32_t sb = smem_u32(smraw);
    const int tid  = threadIdx.x;
    const int lane = tid & 31;
    const int wid  = tid >> 5;
    const int wm   = wid & 3;
    const int wn   = wid >> 2;
    const int bm   = blockIdx.y * 128, bn = blockIdx.x * 128;
    const int gid  = lane >> 2;
    const int tig  = lane & 3;

    float acc[2][8][4];
#pragma unroll
    for (int mt = 0; mt < 2; mt++)
#pragma unroll
        for (int nt = 0; nt < 8; nt++)
#pragma unroll
            for (int j = 0; j < 4; j++) acc[mt][nt][j] = 0.f;

    const int nIter = K >> 6;          // K/64 halves per tile
    const int lrow  = tid >> 3;        // 0..31
    const int lc    = tid & 7;         // 16B chunk 0..7

    // issue cp.async for K-tile `it` into stage s
#define LOAD_STAGE(it, s) do {                                               \
        int k0 = (it) * 64;                                                   \
        uint32_t base = sb + (uint32_t)(s) * STAGE_B;                         \
        _Pragma("unroll")                                                     \
        for (int i = 0; i < 4; i++) {                                         \
            int r = lrow + i * 32;                                            \
            uint32_t sw = (uint32_t)((lc ^ (r & 7)) << 4);                    \
            cp16(base + (uint32_t)r * 128u + sw,                              \
                 A + (size_t)(bm + r) * K + k0 + lc * 8);                     \
            cp16(base + TILE_B + (uint32_t)r * 128u + sw,                     \
                 W + (size_t)(bn + r) * K + k0 + lc * 8);                     \
        }                                                                     \
    } while (0)

    LOAD_STAGE(0, 0); CP_COMMIT();
    LOAD_STAGE(1, 1); CP_COMMIT();

    const int lg  = lane >> 3;   // 0..3
    const int lgi = lane & 7;    // 0..7

    for (int it = 0; it < nIter; it++) {
        CP_WAIT1();
        __syncthreads();
        if (it + 2 < nIter) LOAD_STAGE(it + 2, (it + 2) % 3);
        CP_COMMIT();

        const uint32_t sA = sb + (uint32_t)(it % 3) * STAGE_B;
        const uint32_t sW = sA + TILE_B;

#pragma unroll
        for (int kk = 0; kk < 4; kk++) {
            uint32_t afr[2][4], bfr[8][2];
            // A fragments: matrices (rows m0..+7 / +8..+15) x (chunk lo/hi)
#pragma unroll
            for (int mt = 0; mt < 2; mt++) {
                int row = wm * 32 + mt * 16 + lgi + (lg & 1) * 8;
                int chunk = kk * 2 + (lg >> 1);
                ldsm4(afr[mt], sA + (uint32_t)row * 128u +
                               (uint32_t)((chunk ^ (row & 7)) << 4));
            }
            // B fragments: pairs of nt
#pragma unroll
            for (int ntp = 0; ntp < 4; ntp++) {
                int row = wn * 64 + ntp * 16 + lgi + (lg >> 1) * 8;
                int chunk = kk * 2 + (lg & 1);
                uint32_t t4[4];
                ldsm4(t4, sW + (uint32_t)row * 128u +
                          (uint32_t)((chunk ^ (row & 7)) << 4));
                bfr[2 * ntp][0] = t4[0]; bfr[2 * ntp][1] = t4[1];
                bfr[2 * ntp + 1][0] = t4[2]; bfr[2 * ntp + 1][1] = t4[3];
            }
#pragma unroll
            for (int mt = 0; mt < 2; mt++)
#pragma unroll
                for (int nt = 0; nt < 8; nt++)
                    mma_bf16(acc[mt][nt], afr[mt], bfr[nt]);
        }
        __syncthreads();
    }

    // ---- epilogue ----
#pragma unroll
    for (int mt = 0; mt < 2; mt++) {
        int r0 = bm + wm * 32 + mt * 16 + gid;
#pragma unroll
        for (int nt = 0; nt < 8; nt++) {
            int col = bn + wn * 64 + nt * 8 + tig * 2;
            if (mode == 2) {
                bf16* hp0 = (bf16*)Cv + (size_t)r0 * N + col;
                bf16* hp1 = (bf16*)Cv + (size_t)(r0 + 8) * N + col;
                float v0 = acc[mt][nt][0], v1 = acc[mt][nt][1];
                float v2 = acc[mt][nt][2], v3 = acc[mt][nt][3];
                *reinterpret_cast<uint32_t*>(hp0) =
                    pack_bf16(v0 / (1.f + expf(-v0)), v1 / (1.f + expf(-v1)));
                *reinterpret_cast<uint32_t*>(hp1) =
                    pack_bf16(v2 / (1.f + expf(-v2)), v3 / (1.f + expf(-v3)));
            } else {
                float* p0 = (float*)Cv + (size_t)r0 * N + col;
                float* p1 = (float*)Cv + (size_t)(r0 + 8) * N + col;
                if (mode == 1) {
                    float2 o0 = *reinterpret_cast<float2*>(p0);
                    float2 o1 = *reinterpret_cast<float2*>(p1);
                    o0.x += alpha * acc[mt][nt][0];
                    o0.y += alpha * acc[mt][nt][1];
                    o1.x += alpha * acc[mt][nt][2];
                    o1.y += alpha * acc[mt][nt][3];
                    *reinterpret_cast<float2*>(p0) = o0;
                    *reinterpret_cast<float2*>(p1) = o1;
                } else {
                    *reinterpret_cast<float2*>(p0) =
                        make_float2(alpha * acc[mt][nt][0], alpha * acc[mt][nt][1]);
                    *reinterpret_cast<float2*>(p1) =
                        make_float2(alpha * acc[mt][nt][2], alpha * acc[mt][nt][3]);
                }
            }
        }
    }
}

// =====================================================================
// conversion + non-GEMM kernels
// =====================================================================
__global__ void f2bf_kernel(const float* __restrict__ src,
                            bf16* __restrict__ dst, int n4) {
    int i = blockIdx.x * blockDim.x + threadIdx.x;
    if (i < n4) {
        float4 v = reinterpret_cast<const float4*>(src)[i];
        uint2 o = make_uint2(pack_bf16(v.x, v.y), pack_bf16(v.z, v.w));
        reinterpret_cast<uint2*>(dst)[i] = o;
    }
}

__global__ void embed_kernel(const int* __restrict__ ids,
                             const float* __restrict__ emb,
                             float* __restrict__ x) {
    int row = blockIdx.x;
    int id = ids[row];
    const float* src = emb + (size_t)id * D_;
    float* dst = x + (size_t)row * D_;
    for (int d = threadIdx.x; d < D_; d += blockDim.x) dst[d] = src[d];
}

// rmsnorm with bf16 output (GEMM input)
__global__ void rmsnorm_kernel(const float* __restrict__ x,
                               const float* __restrict__ w,
                               bf16* __restrict__ y, float eps) {
    __shared__ float red[256];
    int row = blockIdx.x;
    const float* xr = x + (size_t)row * D_;
    float s = 0.f;
    for (int d = threadIdx.x; d < D_; d += 256) { float v = xr[d]; s += v * v; }
    red[threadIdx.x] = s; __syncthreads();
    for (int o = 128; o > 0; o >>= 1) {
        if (threadIdx.x < o) red[threadIdx.x] += red[threadIdx.x + o];
        __syncthreads();
    }
    float r = rsqrtf(red[0] / D_ + eps);
    bf16* yr = y + (size_t)row * D_;
    for (int d = threadIdx.x; d < D_; d += 256)
        yr[d] = __float2bfloat16(w[d] * xr[d] * r);
}

// one warp per (row, head)
__global__ void gdn_pre_kernel() {
    int gw = blockIdx.x * 8 + (threadIdx.x >> 5);
    int lid = threadIdx.x & 31;
    int row = gw >> 4;
    int h = gw & 15;
    size_t base = (size_t)row * (5 * D_) + h * 64;
    float q0 = g_proj[base + lid];
    float q1 = g_proj[base + 32 + lid];
    float s = q0 * q0 + q1 * q1;
#pragma unroll
    for (int o = 16; o > 0; o >>= 1) s += __shfl_xor_sync(0xffffffffu, s, o);
    float r = rsqrtf(s / 64.f + QEPS_);
    size_t ob = (size_t)row * D_ + h * 64;
#pragma unroll
    for (int half = 0; half < 2; half++) {
        int d = half * 32 + lid;
        float q = half ? q1 : q0;
        g_qh[ob + d] = q * r;
        float kv = tanhf(g_proj[base + D_ + d]);
        float vv = g_proj[base + 2 * D_ + d];
        float av = 1.f / (1.f + expf(-(g_proj[base + 3 * D_ + d] + 2.f)));
        av = fminf(fmaxf(av, 0.6f), 0.9995f);
        g_u[ob + d] = kv * vv;
        g_a[ob + d] = av;
    }
}

// ---- chunked gated scan ----
__global__ void scan_phase1() {
    int g = blockIdx.x * blockDim.x + threadIdx.x;
    int lane = g & 2047;
    int c = g >> 11;
    int b = lane >> 10, col = lane & 1023;
    float p = 1.f, acc = 0.f;
    size_t idx0 = (size_t)(b * S_ + c * CHUNK_) * D_ + col;
    for (int t = 0; t < CHUNK_; t++) {
        size_t idx = idx0 + (size_t)t * D_;
        p *= g_a[idx];
        acc += g_u[idx] / fmaxf(p, 1e-6f);
    }
    g_scanP[g] = p; g_scanA[g] = acc;
}
__global__ void scan_phase2() {
    int lane = blockIdx.x * blockDim.x + threadIdx.x;
    float carry = 0.f;
    for (int c = 0; c < NCHUNK_; c++) {
        int i = c * 2048 + lane;
        g_scanC[i] = carry;
        carry = g_scanP[i] * (carry + g_scanA[i]);
    }
}
__global__ void scan_phase3_post() {
    int g = blockIdx.x * blockDim.x + threadIdx.x;
    int lane = g & 2047;
    int c = g >> 11;
    int b = lane >> 10, col = lane & 1023;
    float carry = g_scanC[g];
    float p = 1.f, acc = 0.f;
    int row0 = b * S_ + c * CHUNK_;
    for (int t = 0; t < CHUNK_; t++) {
        int row = row0 + t;
        size_t idx = (size_t)row * D_ + col;
        p *= g_a[idx];
        acc += g_u[idx] / fmaxf(p, 1e-6f);
        float mem = p * (carry + acc);
        size_t b5 = (size_t)row * (5 * D_);
        float gate = 1.f / (1.f + expf(-g_proj[b5 + 4 * D_ + col]));
        float vv = g_proj[b5 + 2 * D_ + col];
        g_y[idx] = __float2bfloat16(gate * (g_qh[idx] * mem) + (1.f - gate) * vv);
    }
}

// ---- flash causal attention (fp32 SIMT, 1 MUFU/key steady-state) ----
__global__ __launch_bounds__(128)
void flash_attn_kernel() {
    __shared__ float Ks[64][64];
    __shared__ float Vs[64][64];
    const int qt = blockIdx.x & 15;
    const int h  = (blockIdx.x >> 4) & 15;
    const int b  = blockIdx.x >> 8;
    const int qi = qt * 128 + threadIdx.x;
    const float scale = 0.125f;

    float qr[64], acc[64];
    {
        const float* qp = g_proj + (size_t)(b * S_ + qi) * (3 * D_) + h * HD_;
#pragma unroll
        for (int d = 0; d < 64; d++) { qr[d] = qp[d]; acc[d] = 0.f; }
    }
    float m = -1e30f, l = 0.f;
    const int last_tile = (qt * 128 + 127) / 64;

    for (int kt = 0; kt <= last_tile; kt++) {
#pragma unroll
        for (int ld = 0; ld < 32; ld++) {
            int idx = threadIdx.x + ld * 128;
            int kr = idx >> 6, kc = idx & 63;
            size_t base = (size_t)(b * S_ + kt * 64 + kr) * (3 * D_) + h * HD_ + kc;
            Ks[kr][kc] = g_proj[base + D_];
            Vs[kr][kc] = g_proj[base + 2 * D_];
        }
        __syncthreads();
        int jmax = min(64, qi - kt * 64 + 1);
        for (int j = 0; j < jmax; j++) {
            float s = 0.f;
#pragma unroll
            for (int d = 0; d < 64; d++) s = fmaf(qr[d], Ks[j][d], s);
            s *= scale;
            if (s > m) {
                float corr = __expf(m - s);
                l *= corr;
#pragma unroll
                for (int d = 0; d < 64; d++) acc[d] *= corr;
                m = s;
            }
            float p = __expf(s - m);
            l += p;
#pragma unroll
            for (int d = 0; d < 64; d++) acc[d] = fmaf(p, Vs[j][d], acc[d]);
        }
        __syncthreads();
    }
    float inv = 1.f / l;
    bf16* yp = g_y + (size_t)(b * S_ + qi) * D_ + h * HD_;
#pragma unroll
    for (int d = 0; d < 64; d++) yp[d] = __float2bfloat16(acc[d] * inv);
}

// ---- loss ----
__global__ void loss_rows_kernel(const float* __restrict__ bias,
                                 const int* __restrict__ tgt) {
    __shared__ float red[256];
    int row = blockIdx.x;
    const float* lr = g_logits + (size_t)row * V_;
    float lm = -1e30f;
    for (int v = threadIdx.x; v < V_; v += 256) lm = fmaxf(lm, lr[v] + bias[v]);
    red[threadIdx.x] = lm; __syncthreads();
    for (int o = 128; o > 0; o >>= 1) {
        if (threadIdx.x < o) red[threadIdx.x] = fmaxf(red[threadIdx.x], red[threadIdx.x + o]);
        __syncthreads();
    }
    float M = red[0]; __syncthreads();
    float s = 0.f;
    for (int v = threadIdx.x; v < V_; v += 256) s += __expf(lr[v] + bias[v] - M);
    red[threadIdx.x] = s; __syncthreads();
    for (int o = 128; o > 0; o >>= 1) {
        if (threadIdx.x < o) red[threadIdx.x] += red[threadIdx.x + o];
        __syncthreads();
    }
    if (threadIdx.x == 0) {
        int t = tgt[row];
        float lt = lr[t] + bias[t];
        g_rowloss[row] = -(lt - M - logf(red[0]));
    }
}

__global__ void loss_reduce_kernel(float* __restrict__ out) {
    __shared__ float red[256];
    float s = 0.f;
    for (int i = threadIdx.x; i < BS_; i += 256) s += g_rowloss[i];
    red[threadIdx.x] = s; __syncthreads();
    for (int o = 128; o > 0; o >>= 1) {
        if (threadIdx.x < o) red[threadIdx.x] += red[threadIdx.x + o];
        __syncthreads();
    }
    if (threadIdx.x == 0) out[0] = red[0] / (float)BS_;
}

// =====================================================================
// host orchestration
// =====================================================================
static void launch_gemm(const bf16* A, const bf16* W, void* C,
                        int M, int N, int K, float alpha, int mode) {
    dim3 grid(N / 128, M / 128);
    gemm_tc<<<grid, 256, GT_SMEM_BYTES>>>(A, W, C, M, N, K, alpha, mode);
}
static void convert(const float* src, bf16* dst, size_t n) {
    int n4 = (int)(n / 4);
    f2bf_kernel<<<(n4 + 255) / 256, 256>>>(src, dst, n4);
}

extern "C" void kernel_launch(void* const* d_in, const int* in_sizes, int n_in,
                              void* d_out, int out_size) {
    const int*   input_ids   = (const int*)  d_in[0];
    const int*   target_ids  = (const int*)  d_in[1];
    const float* tok_emb     = (const float*)d_in[2];
    const float* lm_bias     = (const float*)d_in[3];
    const float* gdn_in_w    = (const float*)d_in[4];
    const float* gdn_out_w   = (const float*)d_in[5];
    const float* gdn_norm1   = (const float*)d_in[6];
    const float* gdn_norm2   = (const float*)d_in[7];
    const float* gdn_fc_w    = (const float*)d_in[8];
    const float* gdn_proj_w  = (const float*)d_in[9];
    const float* attn_qkv_w  = (const float*)d_in[10];
    const float* attn_proj_w = (const float*)d_in[11];
    const float* attn_norm1  = (const float*)d_in[12];
    const float* attn_norm2  = (const float*)d_in[13];
    const float* attn_fc_w   = (const float*)d_in[14];
    const float* attn_mlp_w  = (const float*)d_in[15];
    const float* final_norm  = (const float*)d_in[16];
    float* out = (float*)d_out;

    cudaFuncSetAttribute(gemm_tc, cudaFuncAttributeMaxDynamicSharedMemorySize,
                         GT_SMEM_BYTES);

    float *x, *proj, *logits;
    bf16 *xn, *y, *hid;
    bf16 *bw_in, *bw_out, *bw_fc, *bw_pj, *bw_qkv, *bw_apj, *bw_afc, *bw_ampj, *bw_emb;
    cudaGetSymbolAddress((void**)&x,      g_x);
    cudaGetSymbolAddress((void**)&xn,     g_xn);
    cudaGetSymbolAddress((void**)&proj,   g_proj);
    cudaGetSymbolAddress((void**)&y,      g_y);
    cudaGetSymbolAddress((void**)&hid,    g_hid);
    cudaGetSymbolAddress((void**)&logits, g_logits);
    cudaGetSymbolAddress((void**)&bw_in,   w_gdn_in);
    cudaGetSymbolAddress((void**)&bw_out,  w_gdn_out);
    cudaGetSymbolAddress((void**)&bw_fc,   w_gdn_fc);
    cudaGetSymbolAddress((void**)&bw_pj,   w_gdn_pj);
    cudaGetSymbolAddress((void**)&bw_qkv,  w_qkv);
    cudaGetSymbolAddress((void**)&bw_apj,  w_apj);
    cudaGetSymbolAddress((void**)&bw_afc,  w_afc);
    cudaGetSymbolAddress((void**)&bw_ampj, w_ampj);
    cudaGetSymbolAddress((void**)&bw_emb,  w_emb);

    // one-time per-launch weight conversion
    convert(gdn_in_w,   bw_in,   (size_t)LG_ * 5 * D_ * D_);
    convert(gdn_out_w,  bw_out,  (size_t)LG_ * D_ * D_);
    convert(gdn_fc_w,   bw_fc,   (size_t)LG_ * HM_ * D_);
    convert(gdn_proj_w, bw_pj,   (size_t)LG_ * D_ * HM_);
    convert(attn_qkv_w, bw_qkv,  (size_t)3 * D_ * D_);
    convert(attn_proj_w, bw_apj, (size_t)D_ * D_);
    convert(attn_fc_w,  bw_afc,  (size_t)HM_ * D_);
    convert(attn_mlp_w, bw_ampj, (size_t)D_ * HM_);
    convert(tok_emb,    bw_emb,  (size_t)V_ * D_);

    embed_kernel<<<BS_, 256>>>(input_ids, tok_emb, x);

    for (int i = 0; i < LG_; i++) {
        float rsc = rsqrtf(2.0f * (i + 1));
        rmsnorm_kernel<<<BS_, 256>>>(x, gdn_norm1 + (size_t)i * D_, xn, 1e-6f);
        launch_gemm(xn, bw_in + (size_t)i * 5 * D_ * D_, proj, BS_, 5 * D_, D_, 1.f, 0);
        gdn_pre_kernel<<<BS_ * H_ / 8, 256>>>();
        scan_phase1<<<B_ * D_ * NCHUNK_ / 256, 256>>>();
        scan_phase2<<<B_ * D_ / 256, 256>>>();
        scan_phase3_post<<<B_ * D_ * NCHUNK_ / 256, 256>>>();
        launch_gemm(y, bw_out + (size_t)i * D_ * D_, x, BS_, D_, D_, rsc, 1);
        rmsnorm_kernel<<<BS_, 256>>>(x, gdn_norm2 + (size_t)i * D_, xn, 1e-6f);
        launch_gemm(xn, bw_fc + (size_t)i * HM_ * D_, hid, BS_, HM_, D_, 1.f, 2);
        launch_gemm(hid, bw_pj + (size_t)i * D_ * HM_, x, BS_, D_, HM_, rsc, 1);
    }

    float rsc = rsqrtf(2.0f * (LG_ + 1));
    rmsnorm_kernel<<<BS_, 256>>>(x, attn_norm1, xn, 1e-6f);
    launch_gemm(xn, bw_qkv, proj, BS_, 3 * D_, D_, 1.f, 0);
    flash_attn_kernel<<<B_ * H_ * (S_ / 128), 128>>>();
    launch_gemm(y, bw_apj, x, BS_, D_, D_, rsc, 1);
    rmsnorm_kernel<<<BS_, 256>>>(x, attn_norm2, xn, 1e-6f);
    launch_gemm(xn, bw_afc, hid, BS_, HM_, D_, 1.f, 2);
    launch_gemm(hid, bw_ampj, x, BS_, D_, HM_, rsc, 1);

    rmsnorm_kernel<<<BS_, 256>>>(x, final_norm, xn, 1e-6f);
    launch_gemm(xn, bw_emb, logits, BS_, V_, D_, 1.f, 0);
    loss_rows_kernel<<<BS_, 256>>>(lm_bias, target_ids);
    loss_reduce_kernel<<<1, 256>>>(out);
}

// round 6
// speedup vs baseline: 9.4569x; 1.1270x over previous
#include <cuda_runtime.h>
#include <cuda_bf16.h>
#include <math.h>
#include <stdint.h>

// ---------------- problem constants ----------------
#define B_      2
#define S_      2048
#define BS_     (B_*S_)          // 4096 token rows
#define D_      1024
#define H_      16
#define HD_     64
#define HM_     4096
#define V_      32768
#define LG_     8
#define CHUNK_  64
#define NCHUNK_ (S_/CHUNK_)      // 32
#define QEPS_   1.1920929e-07f

typedef __nv_bfloat16 bf16;

// ---------------- static device scratch ----------------
__device__ float g_x   [BS_*D_];
__device__ bf16  g_xn  [BS_*D_];
__device__ float g_proj[BS_*5*D_];
__device__ float g_qh  [BS_*D_];
__device__ float g_u   [BS_*D_];
__device__ float g_a   [BS_*D_];
__device__ bf16  g_y   [BS_*D_];
__device__ bf16  g_hid [BS_*HM_];
__device__ float g_scanP[B_*D_*NCHUNK_];
__device__ float g_scanA[B_*D_*NCHUNK_];
__device__ float g_scanC[B_*D_*NCHUNK_];
__device__ float g_logits[(size_t)BS_*V_];   // 512 MB
__device__ float g_rowloss[BS_];

// bf16 weight mirrors (converted once per launch)
__device__ bf16 w_gdn_in [LG_*5*D_*D_];
__device__ bf16 w_gdn_out[LG_*D_*D_];
__device__ bf16 w_gdn_fc [LG_*HM_*D_];
__device__ bf16 w_gdn_pj [LG_*D_*HM_];
__device__ bf16 w_qkv    [3*D_*D_];
__device__ bf16 w_apj    [D_*D_];
__device__ bf16 w_afc    [HM_*D_];
__device__ bf16 w_ampj   [D_*HM_];
__device__ bf16 w_emb    [(size_t)V_*D_];

// =====================================================================
// helpers
// =====================================================================
__device__ __forceinline__ uint32_t smem_u32(const void* p) {
    uint32_t a;
    asm("{ .reg .u64 t; cvta.to.shared.u64 t, %1; cvt.u32.u64 %0, t; }"
        : "=r"(a) : "l"(p));
    return a;
}
__device__ __forceinline__ uint32_t pack_bf16(float lo, float hi) {
    __nv_bfloat162 h = __floats2bfloat162_rn(lo, hi);
    return *reinterpret_cast<uint32_t*>(&h);
}
__device__ __forceinline__ void cp16(uint32_t dst, const void* src) {
    asm volatile("cp.async.cg.shared.global [%0], [%1], 16;"
                 :: "r"(dst), "l"(src) : "memory");
}
#define CP_COMMIT() asm volatile("cp.async.commit_group;" ::: "memory")
#define CP_WAIT1()  asm volatile("cp.async.wait_group 1;" ::: "memory")

__device__ __forceinline__ void ldsm4(uint32_t r[4], uint32_t addr) {
    asm volatile("ldmatrix.sync.aligned.m8n8.x4.shared.b16 {%0,%1,%2,%3}, [%4];"
                 : "=r"(r[0]), "=r"(r[1]), "=r"(r[2]), "=r"(r[3]) : "r"(addr));
}
__device__ __forceinline__ void mma_bf16(float c[4], const uint32_t a[4],
                                         const uint32_t b[2]) {
    asm volatile(
        "mma.sync.aligned.m16n8k16.row.col.f32.bf16.bf16.f32 "
        "{%0,%1,%2,%3}, {%4,%5,%6,%7}, {%8,%9}, {%0,%1,%2,%3};"
        : "+f"(c[0]), "+f"(c[1]), "+f"(c[2]), "+f"(c[3])
        : "r"(a[0]), "r"(a[1]), "r"(a[2]), "r"(a[3]), "r"(b[0]), "r"(b[1]));
}

// =====================================================================
// bf16 GEMM: C[M,N] = op(alpha * A[M,K] @ W[N,K]^T)
// 128x128 block tile, K-tile 64 halves, 3-stage cp.async pipeline,
// XOR-swizzled smem + ldmatrix, 2 CTAs/SM.
// mode: 0 = fp32 overwrite, 1 = fp32 accumulate, 2 = bf16 silu
// =====================================================================
#define TILE_B  16384u
#define STAGE_B 32768u
#define GT_SMEM_BYTES (3*STAGE_B) // 98304

__global__ __launch_bounds__(256, 2)
void gemm_tc(const bf16* __restrict__ A, const bf16* __restrict__ W,
             void* __restrict__ Cv, int M, int N, int K, float alpha, int mode) {
    extern __shared__ char smraw[];
    const uint32_t sb = smem_u32(smraw);
    const int tid  = threadIdx.x;
    const int lane = tid & 31;
    const int wid  = tid >> 5;
    const int wm   = wid & 3;
    const int wn   = wid >> 2;
    const int bm   = blockIdx.y * 128, bn = blockIdx.x * 128;
    const int gid  = lane >> 2;
    const int tig  = lane & 3;

    float acc[2][8][4];
#pragma unroll
    for (int mt = 0; mt < 2; mt++)
#pragma unroll
        for (int nt = 0; nt < 8; nt++)
#pragma unroll
            for (int j = 0; j < 4; j++) acc[mt][nt][j] = 0.f;

    const int nIter = K >> 6;
    const int lrow  = tid >> 3;
    const int lc    = tid & 7;

#define LOAD_STAGE(it, s) do {                                               \
        int k0 = (it) * 64;                                                   \
        uint32_t base = sb + (uint32_t)(s) * STAGE_B;                         \
        _Pragma("unroll")                                                     \
        for (int i = 0; i < 4; i++) {                                         \
            int r = lrow + i * 32;                                            \
            uint32_t sw = (uint32_t)((lc ^ (r & 7)) << 4);                    \
            cp16(base + (uint32_t)r * 128u + sw,                              \
                 A + (size_t)(bm + r) * K + k0 + lc * 8);                     \
            cp16(base + TILE_B + (uint32_t)r * 128u + sw,                     \
                 W + (size_t)(bn + r) * K + k0 + lc * 8);                     \
        }                                                                     \
    } while (0)

    LOAD_STAGE(0, 0); CP_COMMIT();
    LOAD_STAGE(1, 1); CP_COMMIT();

    const int lg  = lane >> 3;
    const int lgi = lane & 7;

    for (int it = 0; it < nIter; it++) {
        CP_WAIT1();
        __syncthreads();
        if (it + 2 < nIter) LOAD_STAGE(it + 2, (it + 2) % 3);
        CP_COMMIT();

        const uint32_t sA = sb + (uint32_t)(it % 3) * STAGE_B;
        const uint32_t sW = sA + TILE_B;

#pragma unroll
        for (int kk = 0; kk < 4; kk++) {
            uint32_t afr[2][4], bfr[8][2];
#pragma unroll
            for (int mt = 0; mt < 2; mt++) {
                int row = wm * 32 + mt * 16 + lgi + (lg & 1) * 8;
                int chunk = kk * 2 + (lg >> 1);
                ldsm4(afr[mt], sA + (uint32_t)row * 128u +
                               (uint32_t)((chunk ^ (row & 7)) << 4));
            }
#pragma unroll
            for (int ntp = 0; ntp < 4; ntp++) {
                int row = wn * 64 + ntp * 16 + lgi + (lg >> 1) * 8;
                int chunk = kk * 2 + (lg & 1);
                uint32_t t4[4];
                ldsm4(t4, sW + (uint32_t)row * 128u +
                          (uint32_t)((chunk ^ (row & 7)) << 4));
                bfr[2 * ntp][0] = t4[0]; bfr[2 * ntp][1] = t4[1];
                bfr[2 * ntp + 1][0] = t4[2]; bfr[2 * ntp + 1][1] = t4[3];
            }
#pragma unroll
            for (int mt = 0; mt < 2; mt++)
#pragma unroll
                for (int nt = 0; nt < 8; nt++)
                    mma_bf16(acc[mt][nt], afr[mt], bfr[nt]);
        }
        // no trailing sync: the top-of-loop sync (after CP_WAIT1) already
        // guarantees all warps finished computing the stage that the next
        // iteration's LOAD_STAGE overwrites.
    }

    // ---- epilogue ----
#pragma unroll
    for (int mt = 0; mt < 2; mt++) {
        int r0 = bm + wm * 32 + mt * 16 + gid;
#pragma unroll
        for (int nt = 0; nt < 8; nt++) {
            int col = bn + wn * 64 + nt * 8 + tig * 2;
            if (mode == 2) {
                bf16* hp0 = (bf16*)Cv + (size_t)r0 * N + col;
                bf16* hp1 = (bf16*)Cv + (size_t)(r0 + 8) * N + col;
                float v0 = acc[mt][nt][0], v1 = acc[mt][nt][1];
                float v2 = acc[mt][nt][2], v3 = acc[mt][nt][3];
                *reinterpret_cast<uint32_t*>(hp0) =
                    pack_bf16(v0 / (1.f + expf(-v0)), v1 / (1.f + expf(-v1)));
                *reinterpret_cast<uint32_t*>(hp1) =
                    pack_bf16(v2 / (1.f + expf(-v2)), v3 / (1.f + expf(-v3)));
            } else {
                float* p0 = (float*)Cv + (size_t)r0 * N + col;
                float* p1 = (float*)Cv + (size_t)(r0 + 8) * N + col;
                if (mode == 1) {
                    float2 o0 = *reinterpret_cast<float2*>(p0);
                    float2 o1 = *reinterpret_cast<float2*>(p1);
                    o0.x += alpha * acc[mt][nt][0];
                    o0.y += alpha * acc[mt][nt][1];
                    o1.x += alpha * acc[mt][nt][2];
                    o1.y += alpha * acc[mt][nt][3];
                    *reinterpret_cast<float2*>(p0) = o0;
                    *reinterpret_cast<float2*>(p1) = o1;
                } else {
                    *reinterpret_cast<float2*>(p0) =
                        make_float2(alpha * acc[mt][nt][0], alpha * acc[mt][nt][1]);
                    *reinterpret_cast<float2*>(p1) =
                        make_float2(alpha * acc[mt][nt][2], alpha * acc[mt][nt][3]);
                }
            }
        }
    }
}

// =====================================================================
// conversion + non-GEMM kernels
// =====================================================================
__global__ void f2bf_kernel(const float* __restrict__ src,
                            bf16* __restrict__ dst, int n4) {
    int i = blockIdx.x * blockDim.x + threadIdx.x;
    if (i < n4) {
        float4 v = reinterpret_cast<const float4*>(src)[i];
        uint2 o = make_uint2(pack_bf16(v.x, v.y), pack_bf16(v.z, v.w));
        reinterpret_cast<uint2*>(dst)[i] = o;
    }
}

__global__ void embed_kernel(const int* __restrict__ ids,
                             const float* __restrict__ emb,
                             float* __restrict__ x) {
    int row = blockIdx.x;
    int id = ids[row];
    const float* src = emb + (size_t)id * D_;
    float* dst = x + (size_t)row * D_;
    for (int d = threadIdx.x; d < D_; d += blockDim.x) dst[d] = src[d];
}

__global__ void rmsnorm_kernel(const float* __restrict__ x,
                               const float* __restrict__ w,
                               bf16* __restrict__ y, float eps) {
    __shared__ float red[256];
    int row = blockIdx.x;
    const float* xr = x + (size_t)row * D_;
    float s = 0.f;
    for (int d = threadIdx.x; d < D_; d += 256) { float v = xr[d]; s += v * v; }
    red[threadIdx.x] = s; __syncthreads();
    for (int o = 128; o > 0; o >>= 1) {
        if (threadIdx.x < o) red[threadIdx.x] += red[threadIdx.x + o];
        __syncthreads();
    }
    float r = rsqrtf(red[0] / D_ + eps);
    bf16* yr = y + (size_t)row * D_;
    for (int d = threadIdx.x; d < 256 * 4; d += 256)
        ;
    for (int d = threadIdx.x; d < D_; d += 256)
        yr[d] = __float2bfloat16(w[d] * xr[d] * r);
}

// one warp per (row, head)
__global__ void gdn_pre_kernel() {
    int gw = blockIdx.x * 8 + (threadIdx.x >> 5);
    int lid = threadIdx.x & 31;
    int row = gw >> 4;
    int h = gw & 15;
    size_t base = (size_t)row * (5 * D_) + h * 64;
    float q0 = g_proj[base + lid];
    float q1 = g_proj[base + 32 + lid];
    float s = q0 * q0 + q1 * q1;
#pragma unroll
    for (int o = 16; o > 0; o >>= 1) s += __shfl_xor_sync(0xffffffffu, s, o);
    float r = rsqrtf(s / 64.f + QEPS_);
    size_t ob = (size_t)row * D_ + h * 64;
#pragma unroll
    for (int half = 0; half < 2; half++) {
        int d = half * 32 + lid;
        float q = half ? q1 : q0;
        g_qh[ob + d] = q * r;
        float kv = tanhf(g_proj[base + D_ + d]);
        float vv = g_proj[base + 2 * D_ + d];
        float av = 1.f / (1.f + expf(-(g_proj[base + 3 * D_ + d] + 2.f)));
        av = fminf(fmaxf(av, 0.6f), 0.9995f);
        g_u[ob + d] = kv * vv;
        g_a[ob + d] = av;
    }
}

// ---- chunked gated scan ----
__global__ void scan_phase1() {
    int g = blockIdx.x * blockDim.x + threadIdx.x;
    int lane = g & 2047;
    int c = g >> 11;
    int b = lane >> 10, col = lane & 1023;
    float p = 1.f, acc = 0.f;
    size_t idx0 = (size_t)(b * S_ + c * CHUNK_) * D_ + col;
    for (int t = 0; t < CHUNK_; t++) {
        size_t idx = idx0 + (size_t)t * D_;
        p *= g_a[idx];
        acc += g_u[idx] / fmaxf(p, 1e-6f);
    }
    g_scanP[g] = p; g_scanA[g] = acc;
}
__global__ void scan_phase2() {
    int lane = blockIdx.x * blockDim.x + threadIdx.x;
    float carry = 0.f;
    for (int c = 0; c < NCHUNK_; c++) {
        int i = c * 2048 + lane;
        g_scanC[i] = carry;
        carry = g_scanP[i] * (carry + g_scanA[i]);
    }
}
__global__ void scan_phase3_post() {
    int g = blockIdx.x * blockDim.x + threadIdx.x;
    int lane = g & 2047;
    int c = g >> 11;
    int b = lane >> 10, col = lane & 1023;
    float carry = g_scanC[g];
    float p = 1.f, acc = 0.f;
    int row0 = b * S_ + c * CHUNK_;
    for (int t = 0; t < CHUNK_; t++) {
        int row = row0 + t;
        size_t idx = (size_t)row * D_ + col;
        p *= g_a[idx];
        acc += g_u[idx] / fmaxf(p, 1e-6f);
        float mem = p * (carry + acc);
        size_t b5 = (size_t)row * (5 * D_);
        float gate = 1.f / (1.f + expf(-g_proj[b5 + 4 * D_ + col]));
        float vv = g_proj[b5 + 2 * D_ + col];
        g_y[idx] = __float2bfloat16(gate * (g_qh[idx] * mem) + (1.f - gate) * vv);
    }
}

// ---- flash causal attention (fp32 SIMT) ----
__global__ __launch_bounds__(128)
void flash_attn_kernel() {
    __shared__ float Ks[64][64];
    __shared__ float Vs[64][64];
    const int qt = blockIdx.x & 15;
    const int h  = (blockIdx.x >> 4) & 15;
    const int b  = blockIdx.x >> 8;
    const int qi = qt * 128 + threadIdx.x;
    const float scale = 0.125f;

    float qr[64], acc[64];
    {
        const float* qp = g_proj + (size_t)(b * S_ + qi) * (3 * D_) + h * HD_;
#pragma unroll
        for (int d = 0; d < 64; d++) { qr[d] = qp[d]; acc[d] = 0.f; }
    }
    float m = -1e30f, l = 0.f;
    const int last_tile = (qt * 128 + 127) / 64;

    for (int kt = 0; kt <= last_tile; kt++) {
#pragma unroll
        for (int ld = 0; ld < 32; ld++) {
            int idx = threadIdx.x + ld * 128;
            int kr = idx >> 6, kc = idx & 63;
            size_t base = (size_t)(b * S_ + kt * 64 + kr) * (3 * D_) + h * HD_ + kc;
            Ks[kr][kc] = g_proj[base + D_];
            Vs[kr][kc] = g_proj[base + 2 * D_];
        }
        __syncthreads();
        int jmax = min(64, qi - kt * 64 + 1);
        for (int j = 0; j < jmax; j++) {
            float s = 0.f;
#pragma unroll
            for (int d = 0; d < 64; d++) s = fmaf(qr[d], Ks[j][d], s);
            s *= scale;
            if (s > m) {
                float corr = __expf(m - s);
                l *= corr;
#pragma unroll
                for (int d = 0; d < 64; d++) acc[d] *= corr;
                m = s;
            }
            float p = __expf(s - m);
            l += p;
#pragma unroll
            for (int d = 0; d < 64; d++) acc[d] = fmaf(p, Vs[j][d], acc[d]);
        }
        __syncthreads();
    }
    float inv = 1.f / l;
    bf16* yp = g_y + (size_t)(b * S_ + qi) * D_ + h * HD_;
#pragma unroll
    for (int d = 0; d < 64; d++) yp[d] = __float2bfloat16(acc[d] * inv);
}

// ---- loss: single-pass online logsumexp ----
__global__ void loss_rows_kernel(const float* __restrict__ bias,
                                 const int* __restrict__ tgt) {
    __shared__ float mred[256], sred[256];
    int row = blockIdx.x;
    const float4* lr4 = reinterpret_cast<const float4*>(g_logits + (size_t)row * V_);
    const float4* b4  = reinterpret_cast<const float4*>(bias);
    float m = -1e30f, s = 0.f;
    for (int v = threadIdx.x; v < V_ / 4; v += 256) {
        float4 lv = lr4[v];
        float4 bv = b4[v];
        float x0 = lv.x + bv.x, x1 = lv.y + bv.y;
        float x2 = lv.z + bv.z, x3 = lv.w + bv.w;
        float cm = fmaxf(fmaxf(x0, x1), fmaxf(x2, x3));
        if (cm > m) { s *= __expf(m - cm); m = cm; }
        s += __expf(x0 - m) + __expf(x1 - m) + __expf(x2 - m) + __expf(x3 - m);
    }
    mred[threadIdx.x] = m; sred[threadIdx.x] = s;
    __syncthreads();
    for (int o = 128; o > 0; o >>= 1) {
        if (threadIdx.x < o) {
            float m2 = mred[threadIdx.x + o], s2 = sred[threadIdx.x + o];
            float m1 = mred[threadIdx.x],     s1 = sred[threadIdx.x];
            float nm = fmaxf(m1, m2);
            mred[threadIdx.x] = nm;
            sred[threadIdx.x] = s1 * __expf(m1 - nm) + s2 * __expf(m2 - nm);
        }
        __syncthreads();
    }
    if (threadIdx.x == 0) {
        int t = tgt[row];
        float lt = g_logits[(size_t)row * V_ + t] + bias[t];
        g_rowloss[row] = -(lt - mred[0] - logf(sred[0]));
    }
}

__global__ void loss_reduce_kernel(float* __restrict__ out) {
    __shared__ float red[256];
    float s = 0.f;
    for (int i = threadIdx.x; i < BS_; i += 256) s += g_rowloss[i];
    red[threadIdx.x] = s; __syncthreads();
    for (int o = 128; o > 0; o >>= 1) {
        if (threadIdx.x < o) red[threadIdx.x] += red[threadIdx.x + o];
        __syncthreads();
    }
    if (threadIdx.x == 0) out[0] = red[0] / (float)BS_;
}

// =====================================================================
// host orchestration
// =====================================================================
static void launch_gemm(const bf16* A, const bf16* W, void* C,
                        int M, int N, int K, float alpha, int mode) {
    dim3 grid(N / 128, M / 128);
    gemm_tc<<<grid, 256, GT_SMEM_BYTES>>>(A, W, C, M, N, K, alpha, mode);
}
static void convert(const float* src, bf16* dst, size_t n) {
    int n4 = (int)(n / 4);
    f2bf_kernel<<<(n4 + 255) / 256, 256>>>(src, dst, n4);
}

extern "C" void kernel_launch(void* const* d_in, const int* in_sizes, int n_in,
                              void* d_out, int out_size) {
    const int*   input_ids   = (const int*)  d_in[0];
    const int*   target_ids  = (const int*)  d_in[1];
    const float* tok_emb     = (const float*)d_in[2];
    const float* lm_bias     = (const float*)d_in[3];
    const float* gdn_in_w    = (const float*)d_in[4];
    const float* gdn_out_w   = (const float*)d_in[5];
    const float* gdn_norm1   = (const float*)d_in[6];
    const float* gdn_norm2   = (const float*)d_in[7];
    const float* gdn_fc_w    = (const float*)d_in[8];
    const float* gdn_proj_w  = (const float*)d_in[9];
    const float* attn_qkv_w  = (const float*)d_in[10];
    const float* attn_proj_w = (const float*)d_in[11];
    const float* attn_norm1  = (const float*)d_in[12];
    const float* attn_norm2  = (const float*)d_in[13];
    const float* attn_fc_w   = (const float*)d_in[14];
    const float* attn_mlp_w  = (const float*)d_in[15];
    const float* final_norm  = (const float*)d_in[16];
    float* out = (float*)d_out;

    cudaFuncSetAttribute(gemm_tc, cudaFuncAttributeMaxDynamicSharedMemorySize,
                         GT_SMEM_BYTES);

    float *x, *proj, *logits;
    bf16 *xn, *y, *hid;
    bf16 *bw_in, *bw_out, *bw_fc, *bw_pj, *bw_qkv, *bw_apj, *bw_afc, *bw_ampj, *bw_emb;
    cudaGetSymbolAddress((void**)&x,      g_x);
    cudaGetSymbolAddress((void**)&xn,     g_xn);
    cudaGetSymbolAddress((void**)&proj,   g_proj);
    cudaGetSymbolAddress((void**)&y,      g_y);
    cudaGetSymbolAddress((void**)&hid,    g_hid);
    cudaGetSymbolAddress((void**)&logits, g_logits);
    cudaGetSymbolAddress((void**)&bw_in,   w_gdn_in);
    cudaGetSymbolAddress((void**)&bw_out,  w_gdn_out);
    cudaGetSymbolAddress((void**)&bw_fc,   w_gdn_fc);
    cudaGetSymbolAddress((void**)&bw_pj,   w_gdn_pj);
    cudaGetSymbolAddress((void**)&bw_qkv,  w_qkv);
    cudaGetSymbolAddress((void**)&bw_apj,  w_apj);
    cudaGetSymbolAddress((void**)&bw_afc,  w_afc);
    cudaGetSymbolAddress((void**)&bw_ampj, w_ampj);
    cudaGetSymbolAddress((void**)&bw_emb,  w_emb);

    convert(gdn_in_w,   bw_in,   (size_t)LG_ * 5 * D_ * D_);
    convert(gdn_out_w,  bw_out,  (size_t)LG_ * D_ * D_);
    convert(gdn_fc_w,   bw_fc,   (size_t)LG_ * HM_ * D_);
    convert(gdn_proj_w, bw_pj,   (size_t)LG_ * D_ * HM_);
    convert(attn_qkv_w, bw_qkv,  (size_t)3 * D_ * D_);
    convert(attn_proj_w, bw_apj, (size_t)D_ * D_);
    convert(attn_fc_w,  bw_afc,  (size_t)HM_ * D_);
    convert(attn_mlp_w, bw_ampj, (size_t)D_ * HM_);
    convert(tok_emb,    bw_emb,  (size_t)V_ * D_);

    embed_kernel<<<BS_, 256>>>(input_ids, tok_emb, x);

    for (int i = 0; i < LG_; i++) {
        float rsc = rsqrtf(2.0f * (i + 1));
        rmsnorm_kernel<<<BS_, 256>>>(x, gdn_norm1 + (size_t)i * D_, xn, 1e-6f);
        launch_gemm(xn, bw_in + (size_t)i * 5 * D_ * D_, proj, BS_, 5 * D_, D_, 1.f, 0);
        gdn_pre_kernel<<<BS_ * H_ / 8, 256>>>();
        scan_phase1<<<B_ * D_ * NCHUNK_ / 256, 256>>>();
        scan_phase2<<<B_ * D_ / 256, 256>>>();
        scan_phase3_post<<<B_ * D_ * NCHUNK_ / 256, 256>>>();
        launch_gemm(y, bw_out + (size_t)i * D_ * D_, x, BS_, D_, D_, rsc, 1);
        rmsnorm_kernel<<<BS_, 256>>>(x, gdn_norm2 + (size_t)i * D_, xn, 1e-6f);
        launch_gemm(xn, bw_fc + (size_t)i * HM_ * D_, hid, BS_, HM_, D_, 1.f, 2);
        launch_gemm(hid, bw_pj + (size_t)i * D_ * HM_, x, BS_, D_, HM_, rsc, 1);
    }

    float rsc = rsqrtf(2.0f * (LG_ + 1));
    rmsnorm_kernel<<<BS_, 256>>>(x, attn_norm1, xn, 1e-6f);
    launch_gemm(xn, bw_qkv, proj, BS_, 3 * D_, D_, 1.f, 0);
    flash_attn_kernel<<<B_ * H_ * (S_ / 128), 128>>>();
    launch_gemm(y, bw_apj, x, BS_, D_, D_, rsc, 1);
    rmsnorm_kernel<<<BS_, 256>>>(x, attn_norm2, xn, 1e-6f);
    launch_gemm(xn, bw_afc, hid, BS_, HM_, D_, 1.f, 2);
    launch_gemm(hid, bw_ampj, x, BS_, D_, HM_, rsc, 1);

    rmsnorm_kernel<<<BS_, 256>>>(x, final_norm, xn, 1e-6f);
    launch_gemm(xn, bw_emb, logits, BS_, V_, D_, 1.f, 0);
    loss_rows_kernel<<<BS_, 256>>>(lm_bias, target_ids);
    loss_reduce_kernel<<<1, 256>>>(out);
}

// round 7
// speedup vs baseline: 11.5983x; 1.2264x over previous
#include <cuda_runtime.h>
#include <cuda_bf16.h>
#include <math.h>
#include <stdint.h>

// ---------------- problem constants ----------------
#define B_      2
#define S_      2048
#define BS_     (B_*S_)          // 4096 token rows
#define D_      1024
#define H_      16
#define HD_     64
#define HM_     4096
#define V_      32768
#define LG_     8
#define CHUNK_  64
#define NCHUNK_ (S_/CHUNK_)      // 32
#define QEPS_   1.1920929e-07f

typedef __nv_bfloat16 bf16;

// ---------------- static device scratch ----------------
__device__ float g_x   [BS_*D_];
__device__ bf16  g_xn  [BS_*D_];
__device__ float g_proj[BS_*5*D_];
__device__ float g_qh  [BS_*D_];
__device__ float g_u   [BS_*D_];
__device__ float g_a   [BS_*D_];
__device__ bf16  g_y   [BS_*D_];
__device__ bf16  g_hid [BS_*HM_];
__device__ bf16  g_qkv [BS_*3*D_];
__device__ float g_scanP[B_*D_*NCHUNK_];
__device__ float g_scanA[B_*D_*NCHUNK_];
__device__ float g_scanC[B_*D_*NCHUNK_];
__device__ float g_logits[(size_t)BS_*V_];   // 512 MB
__device__ float g_rowloss[BS_];

// bf16 weight mirrors (converted once per launch)
__device__ bf16 w_gdn_in [LG_*5*D_*D_];
__device__ bf16 w_gdn_out[LG_*D_*D_];
__device__ bf16 w_gdn_fc [LG_*HM_*D_];
__device__ bf16 w_gdn_pj [LG_*D_*HM_];
__device__ bf16 w_qkv    [3*D_*D_];
__device__ bf16 w_apj    [D_*D_];
__device__ bf16 w_afc    [HM_*D_];
__device__ bf16 w_ampj   [D_*HM_];
__device__ bf16 w_emb    [(size_t)V_*D_];

// =====================================================================
// helpers
// =====================================================================
__device__ __forceinline__ uint32_t smem_u32(const void* p) {
    uint32_t a;
    asm("{ .reg .u64 t; cvta.to.shared.u64 t, %1; cvt.u32.u64 %0, t; }"
        : "=r"(a) : "l"(p));
    return a;
}
__device__ __forceinline__ uint32_t pack_bf16(float lo, float hi) {
    __nv_bfloat162 h = __floats2bfloat162_rn(lo, hi);
    return *reinterpret_cast<uint32_t*>(&h);
}
__device__ __forceinline__ void cp16(uint32_t dst, const void* src) {
    asm volatile("cp.async.cg.shared.global [%0], [%1], 16;"
                 :: "r"(dst), "l"(src) : "memory");
}
#define CP_COMMIT() asm volatile("cp.async.commit_group;" ::: "memory")
#define CP_WAIT1()  asm volatile("cp.async.wait_group 1;" ::: "memory")

__device__ __forceinline__ void ldsm4(uint32_t r[4], uint32_t addr) {
    asm volatile("ldmatrix.sync.aligned.m8n8.x4.shared.b16 {%0,%1,%2,%3}, [%4];"
                 : "=r"(r[0]), "=r"(r[1]), "=r"(r[2]), "=r"(r[3]) : "r"(addr));
}
__device__ __forceinline__ void ldsm4t(uint32_t r[4], uint32_t addr) {
    asm volatile("ldmatrix.sync.aligned.m8n8.x4.trans.shared.b16 {%0,%1,%2,%3}, [%4];"
                 : "=r"(r[0]), "=r"(r[1]), "=r"(r[2]), "=r"(r[3]) : "r"(addr));
}
__device__ __forceinline__ void mma_bf16(float c[4], const uint32_t a[4],
                                         const uint32_t b[2]) {
    asm volatile(
        "mma.sync.aligned.m16n8k16.row.col.f32.bf16.bf16.f32 "
        "{%0,%1,%2,%3}, {%4,%5,%6,%7}, {%8,%9}, {%0,%1,%2,%3};"
        : "+f"(c[0]), "+f"(c[1]), "+f"(c[2]), "+f"(c[3])
        : "r"(a[0]), "r"(a[1]), "r"(a[2]), "r"(a[3]), "r"(b[0]), "r"(b[1]));
}

// =====================================================================
// bf16 GEMM: C[M,N] = op(alpha * A[M,K] @ W[N,K]^T)
// mode: 0 fp32 overwrite, 1 fp32 accumulate, 2 bf16 silu, 3 bf16 overwrite
// =====================================================================
#define TILE_B  16384u
#define STAGE_B 32768u
#define GT_SMEM_BYTES (3*STAGE_B) // 98304

__global__ __launch_bounds__(256, 2)
void gemm_tc(const bf16* __restrict__ A, const bf16* __restrict__ W,
             void* __restrict__ Cv, int M, int N, int K, float alpha, int mode) {
    extern __shared__ char smraw[];
    const uint32_t sb = smem_u32(smraw);
    const int tid  = threadIdx.x;
    const int lane = tid & 31;
    const int wid  = tid >> 5;
    const int wm   = wid & 3;
    const int wn   = wid >> 2;
    const int bm   = blockIdx.y * 128, bn = blockIdx.x * 128;
    const int gid  = lane >> 2;
    const int tig  = lane & 3;

    float acc[2][8][4];
#pragma unroll
    for (int mt = 0; mt < 2; mt++)
#pragma unroll
        for (int nt = 0; nt < 8; nt++)
#pragma unroll
            for (int j = 0; j < 4; j++) acc[mt][nt][j] = 0.f;

    const int nIter = K >> 6;
    const int lrow  = tid >> 3;
    const int lc    = tid & 7;

#define LOAD_STAGE(it, s) do {                                               \
        int k0 = (it) * 64;                                                   \
        uint32_t base = sb + (uint32_t)(s) * STAGE_B;                         \
        _Pragma("unroll")                                                     \
        for (int i = 0; i < 4; i++) {                                         \
            int r = lrow + i * 32;                                            \
            uint32_t sw = (uint32_t)((lc ^ (r & 7)) << 4);                    \
            cp16(base + (uint32_t)r * 128u + sw,                              \
                 A + (size_t)(bm + r) * K + k0 + lc * 8);                     \
            cp16(base + TILE_B + (uint32_t)r * 128u + sw,                     \
                 W + (size_t)(bn + r) * K + k0 + lc * 8);                     \
        }                                                                     \
    } while (0)

    LOAD_STAGE(0, 0); CP_COMMIT();
    LOAD_STAGE(1, 1); CP_COMMIT();

    const int lg  = lane >> 3;
    const int lgi = lane & 7;

    for (int it = 0; it < nIter; it++) {
        CP_WAIT1();
        __syncthreads();
        if (it + 2 < nIter) LOAD_STAGE(it + 2, (it + 2) % 3);
        CP_COMMIT();

        const uint32_t sA = sb + (uint32_t)(it % 3) * STAGE_B;
        const uint32_t sW = sA + TILE_B;

#pragma unroll
        for (int kk = 0; kk < 4; kk++) {
            uint32_t afr[2][4], bfr[8][2];
#pragma unroll
            for (int mt = 0; mt < 2; mt++) {
                int row = wm * 32 + mt * 16 + lgi + (lg & 1) * 8;
                int chunk = kk * 2 + (lg >> 1);
                ldsm4(afr[mt], sA + (uint32_t)row * 128u +
                               (uint32_t)((chunk ^ (row & 7)) << 4));
            }
#pragma unroll
            for (int ntp = 0; ntp < 4; ntp++) {
                int row = wn * 64 + ntp * 16 + lgi + (lg >> 1) * 8;
                int chunk = kk * 2 + (lg & 1);
                uint32_t t4[4];
                ldsm4(t4, sW + (uint32_t)row * 128u +
                          (uint32_t)((chunk ^ (row & 7)) << 4));
                bfr[2 * ntp][0] = t4[0]; bfr[2 * ntp][1] = t4[1];
                bfr[2 * ntp + 1][0] = t4[2]; bfr[2 * ntp + 1][1] = t4[3];
            }
#pragma unroll
            for (int mt = 0; mt < 2; mt++)
#pragma unroll
                for (int nt = 0; nt < 8; nt++)
                    mma_bf16(acc[mt][nt], afr[mt], bfr[nt]);
        }
    }

    // ---- epilogue ----
#pragma unroll
    for (int mt = 0; mt < 2; mt++) {
        int r0 = bm + wm * 32 + mt * 16 + gid;
#pragma unroll
        for (int nt = 0; nt < 8; nt++) {
            int col = bn + wn * 64 + nt * 8 + tig * 2;
            float v0 = acc[mt][nt][0], v1 = acc[mt][nt][1];
            float v2 = acc[mt][nt][2], v3 = acc[mt][nt][3];
            if (mode == 2) {
                bf16* hp0 = (bf16*)Cv + (size_t)r0 * N + col;
                bf16* hp1 = (bf16*)Cv + (size_t)(r0 + 8) * N + col;
                *reinterpret_cast<uint32_t*>(hp0) =
                    pack_bf16(v0 / (1.f + expf(-v0)), v1 / (1.f + expf(-v1)));
                *reinterpret_cast<uint32_t*>(hp1) =
                    pack_bf16(v2 / (1.f + expf(-v2)), v3 / (1.f + expf(-v3)));
            } else if (mode == 3) {
                bf16* hp0 = (bf16*)Cv + (size_t)r0 * N + col;
                bf16* hp1 = (bf16*)Cv + (size_t)(r0 + 8) * N + col;
                *reinterpret_cast<uint32_t*>(hp0) = pack_bf16(v0, v1);
                *reinterpret_cast<uint32_t*>(hp1) = pack_bf16(v2, v3);
            } else {
                float* p0 = (float*)Cv + (size_t)r0 * N + col;
                float* p1 = (float*)Cv + (size_t)(r0 + 8) * N + col;
                if (mode == 1) {
                    float2 o0 = *reinterpret_cast<float2*>(p0);
                    float2 o1 = *reinterpret_cast<float2*>(p1);
                    o0.x += alpha * v0; o0.y += alpha * v1;
                    o1.x += alpha * v2; o1.y += alpha * v3;
                    *reinterpret_cast<float2*>(p0) = o0;
                    *reinterpret_cast<float2*>(p1) = o1;
                } else {
                    *reinterpret_cast<float2*>(p0) = make_float2(alpha * v0, alpha * v1);
                    *reinterpret_cast<float2*>(p1) = make_float2(alpha * v2, alpha * v3);
                }
            }
        }
    }
}

// =====================================================================
// tensor-core flash attention
// block = (qt, h, b); 256 threads = 8 warps; warp = 16 q rows.
// smem: Q 16KB + 3 stages x (K 8KB + V 8KB) = 64KB dynamic.
// =====================================================================
#define FA_QTILE  128
#define FA_KTILE  64
#define FA_QBYTES 16384u
#define FA_STAGE  16384u          // K 8KB + V 8KB
#define FA_SMEM_BYTES (FA_QBYTES + 3*FA_STAGE)

__global__ __launch_bounds__(256, 1)
void flash_attn_tc() {
    extern __shared__ char smraw[];
    const uint32_t sQ = smem_u32(smraw);
    const int tid  = threadIdx.x;
    const int lane = tid & 31;
    const int wq   = tid >> 5;       // warp 0..7: q rows wq*16..+15
    const int gid  = lane >> 2;
    const int tig  = lane & 3;
    const int lg   = lane >> 3;
    const int lgi  = lane & 7;
    const int qt = blockIdx.x, h = blockIdx.y, b = blockIdx.z;

    const bf16* qkv = g_qkv;
    const size_t rowstride = 3 * D_;
    const size_t qbase = (size_t)(b * S_ + qt * FA_QTILE) * rowstride + h * HD_;

    // ---- cp.async Q tile (128x64) : group 0 together with K/V stage 0 ----
    {
        // 1024 chunks of 16B; 4 per thread
#pragma unroll
        for (int i = 0; i < 4; i++) {
            int idx = tid + i * 256;
            int r = idx >> 3, ch = idx & 7;
            cp16(sQ + (uint32_t)r * 128u + (uint32_t)((ch ^ (r & 7)) << 4),
                 qkv + qbase + (size_t)r * rowstride + ch * 8);
        }
    }
    const int nK = 2 * (qt + 1);     // number of 64-key tiles

#define FA_LOAD(kt, s) do {                                                  \
        size_t kbase = (size_t)(b * S_ + (kt) * FA_KTILE) * rowstride         \
                       + h * HD_ + D_;                                         \
        uint32_t base = sQ + FA_QBYTES + (uint32_t)(s) * FA_STAGE;            \
        _Pragma("unroll")                                                     \
        for (int i = 0; i < 2; i++) {                                         \
            int idx = tid + i * 256;                                          \
            int r = idx >> 3, ch = idx & 7;                                   \
            uint32_t sw = (uint32_t)((ch ^ (r & 7)) << 4);                    \
            cp16(base + (uint32_t)r * 128u + sw,                              \
                 qkv + kbase + (size_t)r * rowstride + ch * 8);               \
            cp16(base + 8192u + (uint32_t)r * 128u + sw,                      \
                 qkv + kbase + D_ + (size_t)r * rowstride + ch * 8);          \
        }                                                                     \
    } while (0)

    FA_LOAD(0, 0); CP_COMMIT();
    FA_LOAD(1, 1); CP_COMMIT();

    uint32_t aQ[4][4];
    float O[8][4];
#pragma unroll
    for (int dt = 0; dt < 8; dt++)
#pragma unroll
        for (int j = 0; j < 4; j++) O[dt][j] = 0.f;
    float m0 = -1e30f, m1 = -1e30f, l0 = 0.f, l1 = 0.f;
    const int qr0 = qt * FA_QTILE + wq * 16 + gid;   // row of c0,c1
    bool qload = false;

    for (int kt = 0; kt < nK; kt++) {
        CP_WAIT1();
        __syncthreads();
        if (!qload) {
            // preload Q fragments (4 k-chunks of 16)
#pragma unroll
            for (int c = 0; c < 4; c++) {
                int row = wq * 16 + (lg & 1) * 8 + lgi;
                int chunk = c * 2 + (lg >> 1);
                ldsm4(aQ[c], sQ + (uint32_t)row * 128u +
                             (uint32_t)((chunk ^ (row & 7)) << 4));
            }
            qload = true;
        }
        if (kt + 2 < nK) FA_LOAD(kt + 2, (kt + 2) % 3);
        CP_COMMIT();

        const uint32_t sK = sQ + FA_QBYTES + (uint32_t)(kt % 3) * FA_STAGE;
        const uint32_t sV = sK + 8192u;

        // ---- scores S[16x64] ----
        float sc[8][4];
#pragma unroll
        for (int nt = 0; nt < 8; nt++)
#pragma unroll
            for (int j = 0; j < 4; j++) sc[nt][j] = 0.f;
#pragma unroll
        for (int c = 0; c < 4; c++) {
            uint32_t bK[8][2];
#pragma unroll
            for (int ntp = 0; ntp < 4; ntp++) {
                int row = ntp * 16 + lgi + (lg >> 1) * 8;
                int chunk = c * 2 + (lg & 1);
                uint32_t t4[4];
                ldsm4(t4, sK + (uint32_t)row * 128u +
                          (uint32_t)((chunk ^ (row & 7)) << 4));
                bK[2 * ntp][0] = t4[0]; bK[2 * ntp][1] = t4[1];
                bK[2 * ntp + 1][0] = t4[2]; bK[2 * ntp + 1][1] = t4[3];
            }
#pragma unroll
            for (int nt = 0; nt < 8; nt++)
                mma_bf16(sc[nt], aQ[c], bK[nt]);
        }

        // scale + causal mask
        const bool boundary = (kt >= 2 * qt);
#pragma unroll
        for (int nt = 0; nt < 8; nt++) {
            int key = kt * FA_KTILE + nt * 8 + tig * 2;
#pragma unroll
            for (int j = 0; j < 4; j++) {
                sc[nt][j] *= 0.125f;
                if (boundary) {
                    int kj = key + (j & 1);
                    int rq = qr0 + (j >> 1) * 8;
                    if (kj > rq) sc[nt][j] = -1e30f;
                }
            }
        }

        // ---- online softmax (rows qr0, qr0+8) ----
        float rmax0 = -1e30f, rmax1 = -1e30f;
#pragma unroll
        for (int nt = 0; nt < 8; nt++) {
            rmax0 = fmaxf(rmax0, fmaxf(sc[nt][0], sc[nt][1]));
            rmax1 = fmaxf(rmax1, fmaxf(sc[nt][2], sc[nt][3]));
        }
#pragma unroll
        for (int o = 1; o <= 2; o <<= 1) {
            rmax0 = fmaxf(rmax0, __shfl_xor_sync(0xffffffffu, rmax0, o));
            rmax1 = fmaxf(rmax1, __shfl_xor_sync(0xffffffffu, rmax1, o));
        }
        float mn0 = fmaxf(m0, rmax0), mn1 = fmaxf(m1, rmax1);
        float c0 = __expf(m0 - mn0), c1 = __expf(m1 - mn1);
        float s0 = 0.f, s1 = 0.f;
        uint32_t pfr[8][2];   // bf16 P, per nt: {rows gid | gid+8} packed pairs
#pragma unroll
        for (int nt = 0; nt < 8; nt++) {
            float p0 = __expf(sc[nt][0] - mn0);
            float p1 = __expf(sc[nt][1] - mn0);
            float p2 = __expf(sc[nt][2] - mn1);
            float p3 = __expf(sc[nt][3] - mn1);
            s0 += p0 + p1; s1 += p2 + p3;
            pfr[nt][0] = pack_bf16(p0, p1);
            pfr[nt][1] = pack_bf16(p2, p3);
        }
#pragma unroll
        for (int o = 1; o <= 2; o <<= 1) {
            s0 += __shfl_xor_sync(0xffffffffu, s0, o);
            s1 += __shfl_xor_sync(0xffffffffu, s1, o);
        }
        l0 = l0 * c0 + s0;  l1 = l1 * c1 + s1;
        m0 = mn0; m1 = mn1;
#pragma unroll
        for (int dt = 0; dt < 8; dt++) {
            O[dt][0] *= c0; O[dt][1] *= c0;
            O[dt][2] *= c1; O[dt][3] *= c1;
        }

        // ---- O += P @ V ----
#pragma unroll
        for (int c = 0; c < 4; c++) {
            uint32_t aP[4] = { pfr[2 * c][0], pfr[2 * c][1],
                               pfr[2 * c + 1][0], pfr[2 * c + 1][1] };
            uint32_t bV[8][2];
#pragma unroll
            for (int dtp = 0; dtp < 4; dtp++) {
                int row = c * 16 + (lg & 1) * 8 + lgi;   // key row
                int chunk = dtp * 2 + (lg >> 1);          // d chunk
                uint32_t t4[4];
                ldsm4t(t4, sV + (uint32_t)row * 128u +
                           (uint32_t)((chunk ^ (row & 7)) << 4));
                bV[2 * dtp][0] = t4[0]; bV[2 * dtp][1] = t4[1];
                bV[2 * dtp + 1][0] = t4[2]; bV[2 * dtp + 1][1] = t4[3];
            }
#pragma unroll
            for (int dt = 0; dt < 8; dt++)
                mma_bf16(O[dt], aP, bV[dt]);
        }
    }

    // ---- write y (bf16) ----
    float inv0 = 1.f / l0, inv1 = 1.f / l1;
    bf16* y0 = g_y + (size_t)(b * S_ + qr0) * D_ + h * HD_;
    bf16* y1 = y0 + (size_t)8 * D_;
#pragma unroll
    for (int dt = 0; dt < 8; dt++) {
        int col = dt * 8 + tig * 2;
        *reinterpret_cast<uint32_t*>(y0 + col) =
            pack_bf16(O[dt][0] * inv0, O[dt][1] * inv0);
        *reinterpret_cast<uint32_t*>(y1 + col) =
            pack_bf16(O[dt][2] * inv1, O[dt][3] * inv1);
    }
}

// =====================================================================
// conversion + non-GEMM kernels
// =====================================================================
__global__ void f2bf_kernel(const float* __restrict__ src,
                            bf16* __restrict__ dst, int n4) {
    int i = blockIdx.x * blockDim.x + threadIdx.x;
    if (i < n4) {
        float4 v = reinterpret_cast<const float4*>(src)[i];
        uint2 o = make_uint2(pack_bf16(v.x, v.y), pack_bf16(v.z, v.w));
        reinterpret_cast<uint2*>(dst)[i] = o;
    }
}

__global__ void embed_kernel(const int* __restrict__ ids,
                             const float* __restrict__ emb,
                             float* __restrict__ x) {
    int row = blockIdx.x;
    int id = ids[row];
    const float* src = emb + (size_t)id * D_;
    float* dst = x + (size_t)row * D_;
    for (int d = threadIdx.x; d < D_; d += blockDim.x) dst[d] = src[d];
}

__global__ void rmsnorm_kernel(const float* __restrict__ x,
                               const float* __restrict__ w,
                               bf16* __restrict__ y, float eps) {
    __shared__ float red[256];
    int row = blockIdx.x;
    const float* xr = x + (size_t)row * D_;
    float s = 0.f;
    for (int d = threadIdx.x; d < D_; d += 256) { float v = xr[d]; s += v * v; }
    red[threadIdx.x] = s; __syncthreads();
    for (int o = 128; o > 0; o >>= 1) {
        if (threadIdx.x < o) red[threadIdx.x] += red[threadIdx.x + o];
        __syncthreads();
    }
    float r = rsqrtf(red[0] / D_ + eps);
    bf16* yr = y + (size_t)row * D_;
    for (int d = threadIdx.x; d < D_; d += 256)
        yr[d] = __float2bfloat16(w[d] * xr[d] * r);
}

// one warp per (row, head)
__global__ void gdn_pre_kernel() {
    int gw = blockIdx.x * 8 + (threadIdx.x >> 5);
    int lid = threadIdx.x & 31;
    int row = gw >> 4;
    int h = gw & 15;
    size_t base = (size_t)row * (5 * D_) + h * 64;
    float q0 = g_proj[base + lid];
    float q1 = g_proj[base + 32 + lid];
    float s = q0 * q0 + q1 * q1;
#pragma unroll
    for (int o = 16; o > 0; o >>= 1) s += __shfl_xor_sync(0xffffffffu, s, o);
    float r = rsqrtf(s / 64.f + QEPS_);
    size_t ob = (size_t)row * D_ + h * 64;
#pragma unroll
    for (int half = 0; half < 2; half++) {
        int d = half * 32 + lid;
        float q = half ? q1 : q0;
        g_qh[ob + d] = q * r;
        float kv = tanhf(g_proj[base + D_ + d]);
        float vv = g_proj[base + 2 * D_ + d];
        float av = 1.f / (1.f + expf(-(g_proj[base + 3 * D_ + d] + 2.f)));
        av = fminf(fmaxf(av, 0.6f), 0.9995f);
        g_u[ob + d] = kv * vv;
        g_a[ob + d] = av;
    }
}

// ---- chunked gated scan ----
__global__ void scan_phase1() {
    int g = blockIdx.x * blockDim.x + threadIdx.x;
    int lane = g & 2047;
    int c = g >> 11;
    int b = lane >> 10, col = lane & 1023;
    float p = 1.f, acc = 0.f;
    size_t idx0 = (size_t)(b * S_ + c * CHUNK_) * D_ + col;
    for (int t = 0; t < CHUNK_; t++) {
        size_t idx = idx0 + (size_t)t * D_;
        p *= g_a[idx];
        acc += g_u[idx] / fmaxf(p, 1e-6f);
    }
    g_scanP[g] = p; g_scanA[g] = acc;
}
__global__ void scan_phase2() {
    int lane = blockIdx.x * blockDim.x + threadIdx.x;
    float carry = 0.f;
    for (int c = 0; c < NCHUNK_; c++) {
        int i = c * 2048 + lane;
        g_scanC[i] = carry;
        carry = g_scanP[i] * (carry + g_scanA[i]);
    }
}
__global__ void scan_phase3_post() {
    int g = blockIdx.x * blockDim.x + threadIdx.x;
    int lane = g & 2047;
    int c = g >> 11;
    int b = lane >> 10, col = lane & 1023;
    float carry = g_scanC[g];
    float p = 1.f, acc = 0.f;
    int row0 = b * S_ + c * CHUNK_;
    for (int t = 0; t < CHUNK_; t++) {
        int row = row0 + t;
        size_t idx = (size_t)row * D_ + col;
        p *= g_a[idx];
        acc += g_u[idx] / fmaxf(p, 1e-6f);
        float mem = p * (carry + acc);
        size_t b5 = (size_t)row * (5 * D_);
        float gate = 1.f / (1.f + expf(-g_proj[b5 + 4 * D_ + col]));
        float vv = g_proj[b5 + 2 * D_ + col];
        g_y[idx] = __float2bfloat16(gate * (g_qh[idx] * mem) + (1.f - gate) * vv);
    }
}

// ---- loss: single-pass online logsumexp ----
__global__ void loss_rows_kernel(const float* __restrict__ bias,
                                 const int* __restrict__ tgt) {
    __shared__ float mred[256], sred[256];
    int row = blockIdx.x;
    const float4* lr4 = reinterpret_cast<const float4*>(g_logits + (size_t)row * V_);
    const float4* b4  = reinterpret_cast<const float4*>(bias);
    float m = -1e30f, s = 0.f;
    for (int v = threadIdx.x; v < V_ / 4; v += 256) {
        float4 lv = lr4[v];
        float4 bv = b4[v];
        float x0 = lv.x + bv.x, x1 = lv.y + bv.y;
        float x2 = lv.z + bv.z, x3 = lv.w + bv.w;
        float cm = fmaxf(fmaxf(x0, x1), fmaxf(x2, x3));
        if (cm > m) { s *= __expf(m - cm); m = cm; }
        s += __expf(x0 - m) + __expf(x1 - m) + __expf(x2 - m) + __expf(x3 - m);
    }
    mred[threadIdx.x] = m; sred[threadIdx.x] = s;
    __syncthreads();
    for (int o = 128; o > 0; o >>= 1) {
        if (threadIdx.x < o) {
            float m2 = mred[threadIdx.x + o], s2 = sred[threadIdx.x + o];
            float m1 = mred[threadIdx.x],     s1 = sred[threadIdx.x];
            float nm = fmaxf(m1, m2);
            mred[threadIdx.x] = nm;
            sred[threadIdx.x] = s1 * __expf(m1 - nm) + s2 * __expf(m2 - nm);
        }
        __syncthreads();
    }
    if (threadIdx.x == 0) {
        int t = tgt[row];
        float lt = g_logits[(size_t)row * V_ + t] + bias[t];
        g_rowloss[row] = -(lt - mred[0] - logf(sred[0]));
    }
}

__global__ void loss_reduce_kernel(float* __restrict__ out) {
    __shared__ float red[256];
    float s = 0.f;
    for (int i = threadIdx.x; i < BS_; i += 256) s += g_rowloss[i];
    red[threadIdx.x] = s; __syncthreads();
    for (int o = 128; o > 0; o >>= 1) {
        if (threadIdx.x < o) red[threadIdx.x] += red[threadIdx.x + o];
        __syncthreads();
    }
    if (threadIdx.x == 0) out[0] = red[0] / (float)BS_;
}

// =====================================================================
// host orchestration
// =====================================================================
static void launch_gemm(const bf16* A, const bf16* W, void* C,
                        int M, int N, int K, float alpha, int mode) {
    dim3 grid(N / 128, M / 128);
    gemm_tc<<<grid, 256, GT_SMEM_BYTES>>>(A, W, C, M, N, K, alpha, mode);
}
static void convert(const float* src, bf16* dst, size_t n) {
    int n4 = (int)(n / 4);
    f2bf_kernel<<<(n4 + 255) / 256, 256>>>(src, dst, n4);
}

extern "C" void kernel_launch(void* const* d_in, const int* in_sizes, int n_in,
                              void* d_out, int out_size) {
    const int*   input_ids   = (const int*)  d_in[0];
    const int*   target_ids  = (const int*)  d_in[1];
    const float* tok_emb     = (const float*)d_in[2];
    const float* lm_bias     = (const float*)d_in[3];
    const float* gdn_in_w    = (const float*)d_in[4];
    const float* gdn_out_w   = (const float*)d_in[5];
    const float* gdn_norm1   = (const float*)d_in[6];
    const float* gdn_norm2   = (const float*)d_in[7];
    const float* gdn_fc_w    = (const float*)d_in[8];
    const float* gdn_proj_w  = (const float*)d_in[9];
    const float* attn_qkv_w  = (const float*)d_in[10];
    const float* attn_proj_w = (const float*)d_in[11];
    const float* attn_norm1  = (const float*)d_in[12];
    const float* attn_norm2  = (const float*)d_in[13];
    const float* attn_fc_w   = (const float*)d_in[14];
    const float* attn_mlp_w  = (const float*)d_in[15];
    const float* final_norm  = (const float*)d_in[16];
    float* out = (float*)d_out;

    cudaFuncSetAttribute(gemm_tc, cudaFuncAttributeMaxDynamicSharedMemorySize,
                         GT_SMEM_BYTES);
    cudaFuncSetAttribute(flash_attn_tc, cudaFuncAttributeMaxDynamicSharedMemorySize,
                         FA_SMEM_BYTES);

    float *x, *proj, *logits;
    bf16 *xn, *y, *hid, *qkvb;
    bf16 *bw_in, *bw_out, *bw_fc, *bw_pj, *bw_qkv, *bw_apj, *bw_afc, *bw_ampj, *bw_emb;
    cudaGetSymbolAddress((void**)&x,      g_x);
    cudaGetSymbolAddress((void**)&xn,     g_xn);
    cudaGetSymbolAddress((void**)&proj,   g_proj);
    cudaGetSymbolAddress((void**)&y,      g_y);
    cudaGetSymbolAddress((void**)&hid,    g_hid);
    cudaGetSymbolAddress((void**)&qkvb,   g_qkv);
    cudaGetSymbolAddress((void**)&logits, g_logits);
    cudaGetSymbolAddress((void**)&bw_in,   w_gdn_in);
    cudaGetSymbolAddress((void**)&bw_out,  w_gdn_out);
    cudaGetSymbolAddress((void**)&bw_fc,   w_gdn_fc);
    cudaGetSymbolAddress((void**)&bw_pj,   w_gdn_pj);
    cudaGetSymbolAddress((void**)&bw_qkv,  w_qkv);
    cudaGetSymbolAddress((void**)&bw_apj,  w_apj);
    cudaGetSymbolAddress((void**)&bw_afc,  w_afc);
    cudaGetSymbolAddress((void**)&bw_ampj, w_ampj);
    cudaGetSymbolAddress((void**)&bw_emb,  w_emb);

    convert(gdn_in_w,   bw_in,   (size_t)LG_ * 5 * D_ * D_);
    convert(gdn_out_w,  bw_out,  (size_t)LG_ * D_ * D_);
    convert(gdn_fc_w,   bw_fc,   (size_t)LG_ * HM_ * D_);
    convert(gdn_proj_w, bw_pj,   (size_t)LG_ * D_ * HM_);
    convert(attn_qkv_w, bw_qkv,  (size_t)3 * D_ * D_);
    convert(attn_proj_w, bw_apj, (size_t)D_ * D_);
    convert(attn_fc_w,  bw_afc,  (size_t)HM_ * D_);
    convert(attn_mlp_w, bw_ampj, (size_t)D_ * HM_);
    convert(tok_emb,    bw_emb,  (size_t)V_ * D_);

    embed_kernel<<<BS_, 256>>>(input_ids, tok_emb, x);

    for (int i = 0; i < LG_; i++) {
        float rsc = rsqrtf(2.0f * (i + 1));
        rmsnorm_kernel<<<BS_, 256>>>(x, gdn_norm1 + (size_t)i * D_, xn, 1e-6f);
        launch_gemm(xn, bw_in + (size_t)i * 5 * D_ * D_, proj, BS_, 5 * D_, D_, 1.f, 0);
        gdn_pre_kernel<<<BS_ * H_ / 8, 256>>>();
        scan_phase1<<<B_ * D_ * NCHUNK_ / 256, 256>>>();
        scan_phase2<<<B_ * D_ / 256, 256>>>();
        scan_phase3_post<<<B_ * D_ * NCHUNK_ / 256, 256>>>();
        launch_gemm(y, bw_out + (size_t)i * D_ * D_, x, BS_, D_, D_, rsc, 1);
        rmsnorm_kernel<<<BS_, 256>>>(x, gdn_norm2 + (size_t)i * D_, xn, 1e-6f);
        launch_gemm(xn, bw_fc + (size_t)i * HM_ * D_, hid, BS_, HM_, D_, 1.f, 2);
        launch_gemm(hid, bw_pj + (size_t)i * D_ * HM_, x, BS_, D_, HM_, rsc, 1);
    }

    float rsc = rsqrtf(2.0f * (LG_ + 1));
    rmsnorm_kernel<<<BS_, 256>>>(x, attn_norm1, xn, 1e-6f);
    launch_gemm(xn, bw_qkv, qkvb, BS_, 3 * D_, D_, 1.f, 3);
    {
        dim3 fgrid(S_ / FA_QTILE, H_, B_);
        flash_attn_tc<<<fgrid, 256, FA_SMEM_BYTES>>>();
    }
    launch_gemm(y, bw_apj, x, BS_, D_, D_, rsc, 1);
    rmsnorm_kernel<<<BS_, 256>>>(x, attn_norm2, xn, 1e-6f);
    launch_gemm(xn, bw_afc, hid, BS_, HM_, D_, 1.f, 2);
    launch_gemm(hid, bw_ampj, x, BS_, D_, HM_, rsc, 1);

    rmsnorm_kernel<<<BS_, 256>>>(x, final_norm, xn, 1e-6f);
    launch_gemm(xn, bw_emb, logits, BS_, V_, D_, 1.f, 0);
    loss_rows_kernel<<<BS_, 256>>>(lm_bias, target_ids);
    loss_reduce_kernel<<<1, 256>>>(out);
}

// round 8
// speedup vs baseline: 11.9911x; 1.0339x over previous
#include <cuda_runtime.h>
#include <cuda_bf16.h>
#include <math.h>
#include <stdint.h>

// ---------------- problem constants ----------------
#define B_      2
#define S_      2048
#define BS_     (B_*S_)          // 4096 token rows
#define D_      1024
#define H_      16
#define HD_     64
#define HM_     4096
#define V_      32768
#define LG_     8
#define CHUNK_  64
#define NCHUNK_ (S_/CHUNK_)      // 32
#define QEPS_   1.1920929e-07f

typedef __nv_bfloat16 bf16;

// ---------------- static device scratch ----------------
__device__ float g_x   [BS_*D_];
__device__ bf16  g_xn  [BS_*D_];
__device__ float g_proj[BS_*5*D_];
__device__ float g_qh  [BS_*D_];
__device__ bf16  g_y   [BS_*D_];
__device__ bf16  g_hid [BS_*HM_];
__device__ bf16  g_qkv [BS_*3*D_];
__device__ float g_scanP[B_*D_*NCHUNK_];
__device__ float g_scanA[B_*D_*NCHUNK_];
__device__ float g_scanC[B_*D_*NCHUNK_];
__device__ float2 g_ls[BS_*(V_/128)];   // per-(row, col-block) logsumexp partials
__device__ float g_tgtlog[BS_];
__device__ float g_rowloss[BS_];

// bf16 weight mirrors (converted once per launch)
__device__ bf16 w_gdn_in [LG_*5*D_*D_];
__device__ bf16 w_gdn_out[LG_*D_*D_];
__device__ bf16 w_gdn_fc [LG_*HM_*D_];
__device__ bf16 w_gdn_pj [LG_*D_*HM_];
__device__ bf16 w_qkv    [3*D_*D_];
__device__ bf16 w_apj    [D_*D_];
__device__ bf16 w_afc    [HM_*D_];
__device__ bf16 w_ampj   [D_*HM_];
__device__ bf16 w_emb    [(size_t)V_*D_];

// =====================================================================
// helpers
// =====================================================================
__device__ __forceinline__ uint32_t smem_u32(const void* p) {
    uint32_t a;
    asm("{ .reg .u64 t; cvta.to.shared.u64 t, %1; cvt.u32.u64 %0, t; }"
        : "=r"(a) : "l"(p));
    return a;
}
__device__ __forceinline__ uint32_t pack_bf16(float lo, float hi) {
    __nv_bfloat162 h = __floats2bfloat162_rn(lo, hi);
    return *reinterpret_cast<uint32_t*>(&h);
}
__device__ __forceinline__ void cp16(uint32_t dst, const void* src) {
    asm volatile("cp.async.cg.shared.global [%0], [%1], 16;"
                 :: "r"(dst), "l"(src) : "memory");
}
#define CP_COMMIT() asm volatile("cp.async.commit_group;" ::: "memory")
#define CP_WAIT1()  asm volatile("cp.async.wait_group 1;" ::: "memory")

__device__ __forceinline__ void ldsm4(uint32_t r[4], uint32_t addr) {
    asm volatile("ldmatrix.sync.aligned.m8n8.x4.shared.b16 {%0,%1,%2,%3}, [%4];"
                 : "=r"(r[0]), "=r"(r[1]), "=r"(r[2]), "=r"(r[3]) : "r"(addr));
}
__device__ __forceinline__ void ldsm4t(uint32_t r[4], uint32_t addr) {
    asm volatile("ldmatrix.sync.aligned.m8n8.x4.trans.shared.b16 {%0,%1,%2,%3}, [%4];"
                 : "=r"(r[0]), "=r"(r[1]), "=r"(r[2]), "=r"(r[3]) : "r"(addr));
}
__device__ __forceinline__ void mma_bf16(float c[4], const uint32_t a[4],
                                         const uint32_t b[2]) {
    asm volatile(
        "mma.sync.aligned.m16n8k16.row.col.f32.bf16.bf16.f32 "
        "{%0,%1,%2,%3}, {%4,%5,%6,%7}, {%8,%9}, {%0,%1,%2,%3};"
        : "+f"(c[0]), "+f"(c[1]), "+f"(c[2]), "+f"(c[3])
        : "r"(a[0]), "r"(a[1]), "r"(a[2]), "r"(a[3]), "r"(b[0]), "r"(b[1]));
}

// =====================================================================
// bf16 GEMM: C[M,N] = op(alpha * A[M,K] @ W[N,K]^T)
// mode: 0 fp32 overwrite, 1 fp32 accumulate, 2 bf16 silu, 3 bf16 overwrite,
//       4 logsumexp-partial epilogue (LM head + loss fusion)
// =====================================================================
#define TILE_B  16384u
#define STAGE_B 32768u
#define GT_SMEM_BYTES (3*STAGE_B) // 98304

__global__ __launch_bounds__(256, 2)
void gemm_tc(const bf16* __restrict__ A, const bf16* __restrict__ W,
             void* __restrict__ Cv, int M, int N, int K, float alpha, int mode,
             const float* __restrict__ bias, const int* __restrict__ tgt) {
    extern __shared__ char smraw[];
    const uint32_t sb = smem_u32(smraw);
    const int tid  = threadIdx.x;
    const int lane = tid & 31;
    const int wid  = tid >> 5;
    const int wm   = wid & 3;
    const int wn   = wid >> 2;
    const int bm   = blockIdx.y * 128, bn = blockIdx.x * 128;
    const int gid  = lane >> 2;
    const int tig  = lane & 3;

    float acc[2][8][4];
#pragma unroll
    for (int mt = 0; mt < 2; mt++)
#pragma unroll
        for (int nt = 0; nt < 8; nt++)
#pragma unroll
            for (int j = 0; j < 4; j++) acc[mt][nt][j] = 0.f;

    const int nIter = K >> 6;
    const int lrow  = tid >> 3;
    const int lc    = tid & 7;

#define LOAD_STAGE(it, s) do {                                               \
        int k0 = (it) * 64;                                                   \
        uint32_t base = sb + (uint32_t)(s) * STAGE_B;                         \
        _Pragma("unroll")                                                     \
        for (int i = 0; i < 4; i++) {                                         \
            int r = lrow + i * 32;                                            \
            uint32_t sw = (uint32_t)((lc ^ (r & 7)) << 4);                    \
            cp16(base + (uint32_t)r * 128u + sw,                              \
                 A + (size_t)(bm + r) * K + k0 + lc * 8);                     \
            cp16(base + TILE_B + (uint32_t)r * 128u + sw,                     \
                 W + (size_t)(bn + r) * K + k0 + lc * 8);                     \
        }                                                                     \
    } while (0)

    LOAD_STAGE(0, 0); CP_COMMIT();
    LOAD_STAGE(1, 1); CP_COMMIT();

    const int lg  = lane >> 3;
    const int lgi = lane & 7;

    for (int it = 0; it < nIter; it++) {
        CP_WAIT1();
        __syncthreads();
        if (it + 2 < nIter) LOAD_STAGE(it + 2, (it + 2) % 3);
        CP_COMMIT();

        const uint32_t sA = sb + (uint32_t)(it % 3) * STAGE_B;
        const uint32_t sW = sA + TILE_B;

#pragma unroll
        for (int kk = 0; kk < 4; kk++) {
            uint32_t afr[2][4], bfr[8][2];
#pragma unroll
            for (int mt = 0; mt < 2; mt++) {
                int row = wm * 32 + mt * 16 + lgi + (lg & 1) * 8;
                int chunk = kk * 2 + (lg >> 1);
                ldsm4(afr[mt], sA + (uint32_t)row * 128u +
                               (uint32_t)((chunk ^ (row & 7)) << 4));
            }
#pragma unroll
            for (int ntp = 0; ntp < 4; ntp++) {
                int row = wn * 64 + ntp * 16 + lgi + (lg >> 1) * 8;
                int chunk = kk * 2 + (lg & 1);
                uint32_t t4[4];
                ldsm4(t4, sW + (uint32_t)row * 128u +
                          (uint32_t)((chunk ^ (row & 7)) << 4));
                bfr[2 * ntp][0] = t4[0]; bfr[2 * ntp][1] = t4[1];
                bfr[2 * ntp + 1][0] = t4[2]; bfr[2 * ntp + 1][1] = t4[3];
            }
#pragma unroll
            for (int mt = 0; mt < 2; mt++)
#pragma unroll
                for (int nt = 0; nt < 8; nt++)
                    mma_bf16(acc[mt][nt], afr[mt], bfr[nt]);
        }
    }

    if (mode == 4) {
        // ---- fused logsumexp-partial epilogue (LM head) ----
        __syncthreads();                           // mainloop smem reads done
        float2* sm_ls = reinterpret_cast<float2*>(smraw);  // [4][2][2][8][2]
#pragma unroll
        for (int mt = 0; mt < 2; mt++) {
            int rA = bm + wm * 32 + mt * 16 + gid;
            int rB = rA + 8;
            float vA[16], vB[16];
            float mA = -1e30f, mB = -1e30f;
#pragma unroll
            for (int nt = 0; nt < 8; nt++) {
                int col = bn + wn * 64 + nt * 8 + tig * 2;
                float2 bv = *reinterpret_cast<const float2*>(bias + col);
                vA[2 * nt]     = acc[mt][nt][0] + bv.x;
                vA[2 * nt + 1] = acc[mt][nt][1] + bv.y;
                vB[2 * nt]     = acc[mt][nt][2] + bv.x;
                vB[2 * nt + 1] = acc[mt][nt][3] + bv.y;
                mA = fmaxf(mA, fmaxf(vA[2 * nt], vA[2 * nt + 1]));
                mB = fmaxf(mB, fmaxf(vB[2 * nt], vB[2 * nt + 1]));
            }
#pragma unroll
            for (int o = 1; o <= 2; o <<= 1) {
                mA = fmaxf(mA, __shfl_xor_sync(0xffffffffu, mA, o));
                mB = fmaxf(mB, __shfl_xor_sync(0xffffffffu, mB, o));
            }
            float sA = 0.f, sB = 0.f;
#pragma unroll
            for (int i = 0; i < 16; i++) {
                sA += __expf(vA[i] - mA);
                sB += __expf(vB[i] - mB);
            }
#pragma unroll
            for (int o = 1; o <= 2; o <<= 1) {
                sA += __shfl_xor_sync(0xffffffffu, sA, o);
                sB += __shfl_xor_sync(0xffffffffu, sB, o);
            }
            if (tig == 0) {
                sm_ls[(((wm * 2 + mt) * 2 + 0) * 8 + gid) * 2 + wn] =
                    make_float2(mA, sA);
                sm_ls[(((wm * 2 + mt) * 2 + 1) * 8 + gid) * 2 + wn] =
                    make_float2(mB, sB);
            }
            // capture target logit (exactly one thread grid-wide per row)
            {
                int t = tgt[rA];
                int local = t - bn - wn * 64;
                if (local >= 0 && local < 64 && ((local >> 1) & 3) == tig)
                    g_tgtlog[rA] = vA[(local >> 3) * 2 + (local & 1)];
                t = tgt[rB];
                local = t - bn - wn * 64;
                if (local >= 0 && local < 64 && ((local >> 1) & 3) == tig)
                    g_tgtlog[rB] = vB[(local >> 3) * 2 + (local & 1)];
            }
        }
        __syncthreads();
        if (tid < 128) {
            int wm2 = tid >> 5, rest = tid & 31;
            int mt = rest >> 4, ab = (rest >> 3) & 1, gd = rest & 7;
            int row = bm + wm2 * 32 + mt * 16 + ab * 8 + gd;
            float2 h0 = sm_ls[(((wm2 * 2 + mt) * 2 + ab) * 8 + gd) * 2 + 0];
            float2 h1 = sm_ls[(((wm2 * 2 + mt) * 2 + ab) * 8 + gd) * 2 + 1];
            float mm = fmaxf(h0.x, h1.x);
            float ss = h0.y * __expf(h0.x - mm) + h1.y * __expf(h1.x - mm);
            g_ls[(size_t)row * (N >> 7) + blockIdx.x] = make_float2(mm, ss);
        }
        return;
    }

    // ---- standard epilogues ----
#pragma unroll
    for (int mt = 0; mt < 2; mt++) {
        int r0 = bm + wm * 32 + mt * 16 + gid;
#pragma unroll
        for (int nt = 0; nt < 8; nt++) {
            int col = bn + wn * 64 + nt * 8 + tig * 2;
            float v0 = acc[mt][nt][0], v1 = acc[mt][nt][1];
            float v2 = acc[mt][nt][2], v3 = acc[mt][nt][3];
            if (mode == 2) {
                bf16* hp0 = (bf16*)Cv + (size_t)r0 * N + col;
                bf16* hp1 = (bf16*)Cv + (size_t)(r0 + 8) * N + col;
                *reinterpret_cast<uint32_t*>(hp0) =
                    pack_bf16(v0 / (1.f + expf(-v0)), v1 / (1.f + expf(-v1)));
                *reinterpret_cast<uint32_t*>(hp1) =
                    pack_bf16(v2 / (1.f + expf(-v2)), v3 / (1.f + expf(-v3)));
            } else if (mode == 3) {
                bf16* hp0 = (bf16*)Cv + (size_t)r0 * N + col;
                bf16* hp1 = (bf16*)Cv + (size_t)(r0 + 8) * N + col;
                *reinterpret_cast<uint32_t*>(hp0) = pack_bf16(v0, v1);
                *reinterpret_cast<uint32_t*>(hp1) = pack_bf16(v2, v3);
            } else {
                float* p0 = (float*)Cv + (size_t)r0 * N + col;
                float* p1 = (float*)Cv + (size_t)(r0 + 8) * N + col;
                if (mode == 1) {
                    float2 o0 = *reinterpret_cast<float2*>(p0);
                    float2 o1 = *reinterpret_cast<float2*>(p1);
                    o0.x += alpha * v0; o0.y += alpha * v1;
                    o1.x += alpha * v2; o1.y += alpha * v3;
                    *reinterpret_cast<float2*>(p0) = o0;
                    *reinterpret_cast<float2*>(p1) = o1;
                } else {
                    *reinterpret_cast<float2*>(p0) = make_float2(alpha * v0, alpha * v1);
                    *reinterpret_cast<float2*>(p1) = make_float2(alpha * v2, alpha * v3);
                }
            }
        }
    }
}

// =====================================================================
// tensor-core flash attention (unchanged from R7)
// =====================================================================
#define FA_QTILE  128
#define FA_KTILE  64
#define FA_QBYTES 16384u
#define FA_STAGE  16384u
#define FA_SMEM_BYTES (FA_QBYTES + 3*FA_STAGE)

__global__ __launch_bounds__(256, 1)
void flash_attn_tc() {
    extern __shared__ char smraw[];
    const uint32_t sQ = smem_u32(smraw);
    const int tid  = threadIdx.x;
    const int lane = tid & 31;
    const int wq   = tid >> 5;
    const int gid  = lane >> 2;
    const int tig  = lane & 3;
    const int lg   = lane >> 3;
    const int lgi  = lane & 7;
    const int qt = blockIdx.x, h = blockIdx.y, b = blockIdx.z;

    const bf16* qkv = g_qkv;
    const size_t rowstride = 3 * D_;
    const size_t qbase = (size_t)(b * S_ + qt * FA_QTILE) * rowstride + h * HD_;

    {
#pragma unroll
        for (int i = 0; i < 4; i++) {
            int idx = tid + i * 256;
            int r = idx >> 3, ch = idx & 7;
            cp16(sQ + (uint32_t)r * 128u + (uint32_t)((ch ^ (r & 7)) << 4),
                 qkv + qbase + (size_t)r * rowstride + ch * 8);
        }
    }
    const int nK = 2 * (qt + 1);

#define FA_LOAD(kt, s) do {                                                  \
        size_t kbase = (size_t)(b * S_ + (kt) * FA_KTILE) * rowstride         \
                       + h * HD_ + D_;                                         \
        uint32_t base = sQ + FA_QBYTES + (uint32_t)(s) * FA_STAGE;            \
        _Pragma("unroll")                                                     \
        for (int i = 0; i < 2; i++) {                                         \
            int idx = tid + i * 256;                                          \
            int r = idx >> 3, ch = idx & 7;                                   \
            uint32_t sw = (uint32_t)((ch ^ (r & 7)) << 4);                    \
            cp16(base + (uint32_t)r * 128u + sw,                              \
                 qkv + kbase + (size_t)r * rowstride + ch * 8);               \
            cp16(base + 8192u + (uint32_t)r * 128u + sw,                      \
                 qkv + kbase + D_ + (size_t)r * rowstride + ch * 8);          \
        }                                                                     \
    } while (0)

    FA_LOAD(0, 0); CP_COMMIT();
    FA_LOAD(1, 1); CP_COMMIT();

    uint32_t aQ[4][4];
    float O[8][4];
#pragma unroll
    for (int dt = 0; dt < 8; dt++)
#pragma unroll
        for (int j = 0; j < 4; j++) O[dt][j] = 0.f;
    float m0 = -1e30f, m1 = -1e30f, l0 = 0.f, l1 = 0.f;
    const int qr0 = qt * FA_QTILE + wq * 16 + gid;
    bool qload = false;

    for (int kt = 0; kt < nK; kt++) {
        CP_WAIT1();
        __syncthreads();
        if (!qload) {
#pragma unroll
            for (int c = 0; c < 4; c++) {
                int row = wq * 16 + (lg & 1) * 8 + lgi;
                int chunk = c * 2 + (lg >> 1);
                ldsm4(aQ[c], sQ + (uint32_t)row * 128u +
                             (uint32_t)((chunk ^ (row & 7)) << 4));
            }
            qload = true;
        }
        if (kt + 2 < nK) FA_LOAD(kt + 2, (kt + 2) % 3);
        CP_COMMIT();

        const uint32_t sK = sQ + FA_QBYTES + (uint32_t)(kt % 3) * FA_STAGE;
        const uint32_t sV = sK + 8192u;

        float sc[8][4];
#pragma unroll
        for (int nt = 0; nt < 8; nt++)
#pragma unroll
            for (int j = 0; j < 4; j++) sc[nt][j] = 0.f;
#pragma unroll
        for (int c = 0; c < 4; c++) {
            uint32_t bK[8][2];
#pragma unroll
            for (int ntp = 0; ntp < 4; ntp++) {
                int row = ntp * 16 + lgi + (lg >> 1) * 8;
                int chunk = c * 2 + (lg & 1);
                uint32_t t4[4];
                ldsm4(t4, sK + (uint32_t)row * 128u +
                          (uint32_t)((chunk ^ (row & 7)) << 4));
                bK[2 * ntp][0] = t4[0]; bK[2 * ntp][1] = t4[1];
                bK[2 * ntp + 1][0] = t4[2]; bK[2 * ntp + 1][1] = t4[3];
            }
#pragma unroll
            for (int nt = 0; nt < 8; nt++)
                mma_bf16(sc[nt], aQ[c], bK[nt]);
        }

        const bool boundary = (kt >= 2 * qt);
#pragma unroll
        for (int nt = 0; nt < 8; nt++) {
            int key = kt * FA_KTILE + nt * 8 + tig * 2;
#pragma unroll
            for (int j = 0; j < 4; j++) {
                sc[nt][j] *= 0.125f;
                if (boundary) {
                    int kj = key + (j & 1);
                    int rq = qr0 + (j >> 1) * 8;
                    if (kj > rq) sc[nt][j] = -1e30f;
                }
            }
        }

        float rmax0 = -1e30f, rmax1 = -1e30f;
#pragma unroll
        for (int nt = 0; nt < 8; nt++) {
            rmax0 = fmaxf(rmax0, fmaxf(sc[nt][0], sc[nt][1]));
            rmax1 = fmaxf(rmax1, fmaxf(sc[nt][2], sc[nt][3]));
        }
#pragma unroll
        for (int o = 1; o <= 2; o <<= 1) {
            rmax0 = fmaxf(rmax0, __shfl_xor_sync(0xffffffffu, rmax0, o));
            rmax1 = fmaxf(rmax1, __shfl_xor_sync(0xffffffffu, rmax1, o));
        }
        float mn0 = fmaxf(m0, rmax0), mn1 = fmaxf(m1, rmax1);
        float c0 = __expf(m0 - mn0), c1 = __expf(m1 - mn1);
        float s0 = 0.f, s1 = 0.f;
        uint32_t pfr[8][2];
#pragma unroll
        for (int nt = 0; nt < 8; nt++) {
            float p0 = __expf(sc[nt][0] - mn0);
            float p1 = __expf(sc[nt][1] - mn0);
            float p2 = __expf(sc[nt][2] - mn1);
            float p3 = __expf(sc[nt][3] - mn1);
            s0 += p0 + p1; s1 += p2 + p3;
            pfr[nt][0] = pack_bf16(p0, p1);
            pfr[nt][1] = pack_bf16(p2, p3);
        }
#pragma unroll
        for (int o = 1; o <= 2; o <<= 1) {
            s0 += __shfl_xor_sync(0xffffffffu, s0, o);
            s1 += __shfl_xor_sync(0xffffffffu, s1, o);
        }
        l0 = l0 * c0 + s0;  l1 = l1 * c1 + s1;
        m0 = mn0; m1 = mn1;
#pragma unroll
        for (int dt = 0; dt < 8; dt++) {
            O[dt][0] *= c0; O[dt][1] *= c0;
            O[dt][2] *= c1; O[dt][3] *= c1;
        }

#pragma unroll
        for (int c = 0; c < 4; c++) {
            uint32_t aP[4] = { pfr[2 * c][0], pfr[2 * c][1],
                               pfr[2 * c + 1][0], pfr[2 * c + 1][1] };
            uint32_t bV[8][2];
#pragma unroll
            for (int dtp = 0; dtp < 4; dtp++) {
                int row = c * 16 + (lg & 1) * 8 + lgi;
                int chunk = dtp * 2 + (lg >> 1);
                uint32_t t4[4];
                ldsm4t(t4, sV + (uint32_t)row * 128u +
                           (uint32_t)((chunk ^ (row & 7)) << 4));
                bV[2 * dtp][0] = t4[0]; bV[2 * dtp][1] = t4[1];
                bV[2 * dtp + 1][0] = t4[2]; bV[2 * dtp + 1][1] = t4[3];
            }
#pragma unroll
            for (int dt = 0; dt < 8; dt++)
                mma_bf16(O[dt], aP, bV[dt]);
        }
    }

    float inv0 = 1.f / l0, inv1 = 1.f / l1;
    bf16* y0 = g_y + (size_t)(b * S_ + qr0) * D_ + h * HD_;
    bf16* y1 = y0 + (size_t)8 * D_;
#pragma unroll
    for (int dt = 0; dt < 8; dt++) {
        int col = dt * 8 + tig * 2;
        *reinterpret_cast<uint32_t*>(y0 + col) =
            pack_bf16(O[dt][0] * inv0, O[dt][1] * inv0);
        *reinterpret_cast<uint32_t*>(y1 + col) =
            pack_bf16(O[dt][2] * inv1, O[dt][3] * inv1);
    }
}

// =====================================================================
// conversion + non-GEMM kernels
// =====================================================================
__global__ void f2bf_kernel(const float* __restrict__ src,
                            bf16* __restrict__ dst, int n4) {
    int i = blockIdx.x * blockDim.x + threadIdx.x;
    if (i < n4) {
        float4 v = reinterpret_cast<const float4*>(src)[i];
        uint2 o = make_uint2(pack_bf16(v.x, v.y), pack_bf16(v.z, v.w));
        reinterpret_cast<uint2*>(dst)[i] = o;
    }
}

__global__ void embed_kernel(const int* __restrict__ ids,
                             const float* __restrict__ emb,
                             float* __restrict__ x) {
    int row = blockIdx.x;
    int id = ids[row];
    const float* src = emb + (size_t)id * D_;
    float* dst = x + (size_t)row * D_;
    for (int d = threadIdx.x; d < D_; d += blockDim.x) dst[d] = src[d];
}

__global__ void rmsnorm_kernel(const float* __restrict__ x,
                               const float* __restrict__ w,
                               bf16* __restrict__ y, float eps) {
    __shared__ float red[256];
    int row = blockIdx.x;
    const float* xr = x + (size_t)row * D_;
    float s = 0.f;
    for (int d = threadIdx.x; d < D_; d += 256) { float v = xr[d]; s += v * v; }
    red[threadIdx.x] = s; __syncthreads();
    for (int o = 128; o > 0; o >>= 1) {
        if (threadIdx.x < o) red[threadIdx.x] += red[threadIdx.x + o];
        __syncthreads();
    }
    float r = rsqrtf(red[0] / D_ + eps);
    bf16* yr = y + (size_t)row * D_;
    for (int d = threadIdx.x; d < D_; d += 256)
        yr[d] = __float2bfloat16(w[d] * xr[d] * r);
}

// q-RMS only: one warp per (row, head)
__global__ void gdn_pre_q() {
    int gw = blockIdx.x * 8 + (threadIdx.x >> 5);
    int lid = threadIdx.x & 31;
    int row = gw >> 4;
    int h = gw & 15;
    size_t base = (size_t)row * (5 * D_) + h * 64;
    float q0 = g_proj[base + lid];
    float q1 = g_proj[base + 32 + lid];
    float s = q0 * q0 + q1 * q1;
#pragma unroll
    for (int o = 16; o > 0; o >>= 1) s += __shfl_xor_sync(0xffffffffu, s, o);
    float r = rsqrtf(s / 64.f + QEPS_);
    size_t ob = (size_t)row * D_ + h * 64;
    g_qh[ob + lid]      = q0 * r;
    g_qh[ob + 32 + lid] = q1 * r;
}

// ---- chunked gated scan (u,a recomputed from proj) ----
__device__ __forceinline__ void gdn_ua(size_t b5, int col, float& a, float& u) {
    float kv = tanhf(g_proj[b5 + D_ + col]);
    float vv = g_proj[b5 + 2 * D_ + col];
    float av = 1.f / (1.f + expf(-(g_proj[b5 + 3 * D_ + col] + 2.f)));
    a = fminf(fmaxf(av, 0.6f), 0.9995f);
    u = kv * vv;
}

__global__ void scan_phase1() {
    int g = blockIdx.x * blockDim.x + threadIdx.x;
    int lane = g & 2047;
    int c = g >> 11;
    int b = lane >> 10, col = lane & 1023;
    float p = 1.f, acc = 0.f;
    int row0 = b * S_ + c * CHUNK_;
    for (int t = 0; t < CHUNK_; t++) {
        size_t b5 = (size_t)(row0 + t) * (5 * D_);
        float a, u;
        gdn_ua(b5, col, a, u);
        p *= a;
        acc += u / fmaxf(p, 1e-6f);
    }
    g_scanP[g] = p; g_scanA[g] = acc;
}
__global__ void scan_phase2() {
    int lane = blockIdx.x * blockDim.x + threadIdx.x;
    float carry = 0.f;
    for (int c = 0; c < NCHUNK_; c++) {
        int i = c * 2048 + lane;
        g_scanC[i] = carry;
        carry = g_scanP[i] * (carry + g_scanA[i]);
    }
}
__global__ void scan_phase3_post() {
    int g = blockIdx.x * blockDim.x + threadIdx.x;
    int lane = g & 2047;
    int c = g >> 11;
    int b = lane >> 10, col = lane & 1023;
    float carry = g_scanC[g];
    float p = 1.f, acc = 0.f;
    int row0 = b * S_ + c * CHUNK_;
    for (int t = 0; t < CHUNK_; t++) {
        int row = row0 + t;
        size_t b5 = (size_t)row * (5 * D_);
        float a, u;
        gdn_ua(b5, col, a, u);
        p *= a;
        acc += u / fmaxf(p, 1e-6f);
        float mem = p * (carry + acc);
        size_t idx = (size_t)row * D_ + col;
        float gate = 1.f / (1.f + expf(-g_proj[b5 + 4 * D_ + col]));
        float vv = g_proj[b5 + 2 * D_ + col];
        g_y[idx] = __float2bfloat16(gate * (g_qh[idx] * mem) + (1.f - gate) * vv);
    }
}

// ---- loss finalization ----
__global__ void loss_final() {
    __shared__ float mred[256], sred[256];
    int row = blockIdx.x;
    float2 v = g_ls[(size_t)row * 256 + threadIdx.x];
    mred[threadIdx.x] = v.x; sred[threadIdx.x] = v.y;
    __syncthreads();
    for (int o = 128; o > 0; o >>= 1) {
        if (threadIdx.x < o) {
            float m2 = mred[threadIdx.x + o], s2 = sred[threadIdx.x + o];
            float m1 = mred[threadIdx.x],     s1 = sred[threadIdx.x];
            float nm = fmaxf(m1, m2);
            mred[threadIdx.x] = nm;
            sred[threadIdx.x] = s1 * __expf(m1 - nm) + s2 * __expf(m2 - nm);
        }
        __syncthreads();
    }
    if (threadIdx.x == 0)
        g_rowloss[row] = -(g_tgtlog[row] - mred[0] - logf(sred[0]));
}

__global__ void loss_reduce_kernel(float* __restrict__ out) {
    __shared__ float red[256];
    float s = 0.f;
    for (int i = threadIdx.x; i < BS_; i += 256) s += g_rowloss[i];
    red[threadIdx.x] = s; __syncthreads();
    for (int o = 128; o > 0; o >>= 1) {
        if (threadIdx.x < o) red[threadIdx.x] += red[threadIdx.x + o];
        __syncthreads();
    }
    if (threadIdx.x == 0) out[0] = red[0] / (float)BS_;
}

// =====================================================================
// host orchestration
// =====================================================================
static void launch_gemm(const bf16* A, const bf16* W, void* C,
                        int M, int N, int K, float alpha, int mode,
                        const float* bias = nullptr, const int* tgt = nullptr) {
    dim3 grid(N / 128, M / 128);
    gemm_tc<<<grid, 256, GT_SMEM_BYTES>>>(A, W, C, M, N, K, alpha, mode, bias, tgt);
}
static void convert(const float* src, bf16* dst, size_t n) {
    int n4 = (int)(n / 4);
    f2bf_kernel<<<(n4 + 255) / 256, 256>>>(src, dst, n4);
}

extern "C" void kernel_launch(void* const* d_in, const int* in_sizes, int n_in,
                              void* d_out, int out_size) {
    const int*   input_ids   = (const int*)  d_in[0];
    const int*   target_ids  = (const int*)  d_in[1];
    const float* tok_emb     = (const float*)d_in[2];
    const float* lm_bias     = (const float*)d_in[3];
    const float* gdn_in_w    = (const float*)d_in[4];
    const float* gdn_out_w   = (const float*)d_in[5];
    const float* gdn_norm1   = (const float*)d_in[6];
    const float* gdn_norm2   = (const float*)d_in[7];
    const float* gdn_fc_w    = (const float*)d_in[8];
    const float* gdn_proj_w  = (const float*)d_in[9];
    const float* attn_qkv_w  = (const float*)d_in[10];
    const float* attn_proj_w = (const float*)d_in[11];
    const float* attn_norm1  = (const float*)d_in[12];
    const float* attn_norm2  = (const float*)d_in[13];
    const float* attn_fc_w   = (const float*)d_in[14];
    const float* attn_mlp_w  = (const float*)d_in[15];
    const float* final_norm  = (const float*)d_in[16];
    float* out = (float*)d_out;

    cudaFuncSetAttribute(gemm_tc, cudaFuncAttributeMaxDynamicSharedMemorySize,
                         GT_SMEM_BYTES);
    cudaFuncSetAttribute(flash_attn_tc, cudaFuncAttributeMaxDynamicSharedMemorySize,
                         FA_SMEM_BYTES);

    float *x, *proj;
    bf16 *xn, *y, *hid, *qkvb;
    bf16 *bw_in, *bw_out, *bw_fc, *bw_pj, *bw_qkv, *bw_apj, *bw_afc, *bw_ampj, *bw_emb;
    cudaGetSymbolAddress((void**)&x,      g_x);
    cudaGetSymbolAddress((void**)&xn,     g_xn);
    cudaGetSymbolAddress((void**)&proj,   g_proj);
    cudaGetSymbolAddress((void**)&y,      g_y);
    cudaGetSymbolAddress((void**)&hid,    g_hid);
    cudaGetSymbolAddress((void**)&qkvb,   g_qkv);
    cudaGetSymbolAddress((void**)&bw_in,   w_gdn_in);
    cudaGetSymbolAddress((void**)&bw_out,  w_gdn_out);
    cudaGetSymbolAddress((void**)&bw_fc,   w_gdn_fc);
    cudaGetSymbolAddress((void**)&bw_pj,   w_gdn_pj);
    cudaGetSymbolAddress((void**)&bw_qkv,  w_qkv);
    cudaGetSymbolAddress((void**)&bw_apj,  w_apj);
    cudaGetSymbolAddress((void**)&bw_afc,  w_afc);
    cudaGetSymbolAddress((void**)&bw_ampj, w_ampj);
    cudaGetSymbolAddress((void**)&bw_emb,  w_emb);

    convert(gdn_in_w,   bw_in,   (size_t)LG_ * 5 * D_ * D_);
    convert(gdn_out_w,  bw_out,  (size_t)LG_ * D_ * D_);
    convert(gdn_fc_w,   bw_fc,   (size_t)LG_ * HM_ * D_);
    convert(gdn_proj_w, bw_pj,   (size_t)LG_ * D_ * HM_);
    convert(attn_qkv_w, bw_qkv,  (size_t)3 * D_ * D_);
    convert(attn_proj_w, bw_apj, (size_t)D_ * D_);
    convert(attn_fc_w,  bw_afc,  (size_t)HM_ * D_);
    convert(attn_mlp_w, bw_ampj, (size_t)D_ * HM_);
    convert(tok_emb,    bw_emb,  (size_t)V_ * D_);

    embed_kernel<<<BS_, 256>>>(input_ids, tok_emb, x);

    for (int i = 0; i < LG_; i++) {
        float rsc = rsqrtf(2.0f * (i + 1));
        rmsnorm_kernel<<<BS_, 256>>>(x, gdn_norm1 + (size_t)i * D_, xn, 1e-6f);
        launch_gemm(xn, bw_in + (size_t)i * 5 * D_ * D_, proj, BS_, 5 * D_, D_, 1.f, 0);
        gdn_pre_q<<<BS_ * H_ / 8, 256>>>();
        scan_phase1<<<B_ * D_ * NCHUNK_ / 256, 256>>>();
        scan_phase2<<<B_ * D_ / 256, 256>>>();
        scan_phase3_post<<<B_ * D_ * NCHUNK_ / 256, 256>>>();
        launch_gemm(y, bw_out + (size_t)i * D_ * D_, x, BS_, D_, D_, rsc, 1);
        rmsnorm_kernel<<<BS_, 256>>>(x, gdn_norm2 + (size_t)i * D_, xn, 1e-6f);
        launch_gemm(xn, bw_fc + (size_t)i * HM_ * D_, hid, BS_, HM_, D_, 1.f, 2);
        launch_gemm(hid, bw_pj + (size_t)i * D_ * HM_, x, BS_, D_, HM_, rsc, 1);
    }

    float rsc = rsqrtf(2.0f * (LG_ + 1));
    rmsnorm_kernel<<<BS_, 256>>>(x, attn_norm1, xn, 1e-6f);
    launch_gemm(xn, bw_qkv, qkvb, BS_, 3 * D_, D_, 1.f, 3);
    {
        dim3 fgrid(S_ / FA_QTILE, H_, B_);
        flash_attn_tc<<<fgrid, 256, FA_SMEM_BYTES>>>();
    }
    launch_gemm(y, bw_apj, x, BS_, D_, D_, rsc, 1);
    rmsnorm_kernel<<<BS_, 256>>>(x, attn_norm2, xn, 1e-6f);
    launch_gemm(xn, bw_afc, hid, BS_, HM_, D_, 1.f, 2);
    launch_gemm(hid, bw_ampj, x, BS_, D_, HM_, rsc, 1);

    rmsnorm_kernel<<<BS_, 256>>>(x, final_norm, xn, 1e-6f);
    launch_gemm(xn, bw_emb, nullptr, BS_, V_, D_, 1.f, 4, lm_bias, target_ids);
    loss_final<<<BS_, 256>>>();
    loss_reduce_kernel<<<1, 256>>>(out);
}

// round 9
// speedup vs baseline: 12.4482x; 1.0381x over previous
#include <cuda_runtime.h>
#include <cuda_bf16.h>
#include <math.h>
#include <stdint.h>

// ---------------- problem constants ----------------
#define B_      2
#define S_      2048
#define BS_     (B_*S_)          // 4096 token rows
#define D_      1024
#define H_      16
#define HD_     64
#define HM_     4096
#define V_      32768
#define LG_     8
#define CHUNK_  64
#define NCHUNK_ (S_/CHUNK_)      // 32
#define QEPS_   1.1920929e-07f

typedef __nv_bfloat16 bf16;

// ---------------- static device scratch ----------------
__device__ float g_x   [BS_*D_];
__device__ bf16  g_xn  [BS_*D_];
__device__ float g_proj[BS_*5*D_];
__device__ float g_rq  [BS_*H_];        // per-(row,head) q-rms reciprocal
__device__ bf16  g_y   [BS_*D_];
__device__ bf16  g_hid [BS_*HM_];
__device__ bf16  g_qkv [BS_*3*D_];
__device__ float g_scanP[B_*D_*NCHUNK_];
__device__ float g_scanA[B_*D_*NCHUNK_];
__device__ float g_scanC[B_*D_*NCHUNK_];
__device__ float2 g_ls[BS_*(V_/128)];
__device__ float g_tgtlog[BS_];
__device__ float g_rowloss[BS_];

// bf16 weight mirrors (converted once per launch)
__device__ bf16 w_gdn_in [LG_*5*D_*D_];
__device__ bf16 w_gdn_out[LG_*D_*D_];
__device__ bf16 w_gdn_fc [LG_*HM_*D_];
__device__ bf16 w_gdn_pj [LG_*D_*HM_];
__device__ bf16 w_qkv    [3*D_*D_];
__device__ bf16 w_apj    [D_*D_];
__device__ bf16 w_afc    [HM_*D_];
__device__ bf16 w_ampj   [D_*HM_];
__device__ bf16 w_emb    [(size_t)V_*D_];

// =====================================================================
// helpers
// =====================================================================
__device__ __forceinline__ uint32_t smem_u32(const void* p) {
    uint32_t a;
    asm("{ .reg .u64 t; cvta.to.shared.u64 t, %1; cvt.u32.u64 %0, t; }"
        : "=r"(a) : "l"(p));
    return a;
}
__device__ __forceinline__ uint32_t pack_bf16(float lo, float hi) {
    __nv_bfloat162 h = __floats2bfloat162_rn(lo, hi);
    return *reinterpret_cast<uint32_t*>(&h);
}
__device__ __forceinline__ void cp16(uint32_t dst, const void* src) {
    asm volatile("cp.async.cg.shared.global [%0], [%1], 16;"
                 :: "r"(dst), "l"(src) : "memory");
}
#define CP_COMMIT() asm volatile("cp.async.commit_group;" ::: "memory")
#define CP_WAIT1()  asm volatile("cp.async.wait_group 1;" ::: "memory")

__device__ __forceinline__ void ldsm4(uint32_t r[4], uint32_t addr) {
    asm volatile("ldmatrix.sync.aligned.m8n8.x4.shared.b16 {%0,%1,%2,%3}, [%4];"
                 : "=r"(r[0]), "=r"(r[1]), "=r"(r[2]), "=r"(r[3]) : "r"(addr));
}
__device__ __forceinline__ void ldsm4t(uint32_t r[4], uint32_t addr) {
    asm volatile("ldmatrix.sync.aligned.m8n8.x4.trans.shared.b16 {%0,%1,%2,%3}, [%4];"
                 : "=r"(r[0]), "=r"(r[1]), "=r"(r[2]), "=r"(r[3]) : "r"(addr));
}
__device__ __forceinline__ void mma_bf16(float c[4], const uint32_t a[4],
                                         const uint32_t b[2]) {
    asm volatile(
        "mma.sync.aligned.m16n8k16.row.col.f32.bf16.bf16.f32 "
        "{%0,%1,%2,%3}, {%4,%5,%6,%7}, {%8,%9}, {%0,%1,%2,%3};"
        : "+f"(c[0]), "+f"(c[1]), "+f"(c[2]), "+f"(c[3])
        : "r"(a[0]), "r"(a[1]), "r"(a[2]), "r"(a[3]), "r"(b[0]), "r"(b[1]));
}

// =====================================================================
// bf16 GEMM: C[M,N] = op(alpha * A[M,K] @ W[N,K]^T)
// mode: 0 fp32 overwrite, 1 fp32 accumulate, 2 bf16 silu, 3 bf16 overwrite,
//       4 logsumexp-partial epilogue (LM head + loss fusion)
// =====================================================================
#define TILE_B  16384u
#define STAGE_B 32768u
#define GT_SMEM_BYTES (3*STAGE_B) // 98304

__global__ __launch_bounds__(256, 2)
void gemm_tc(const bf16* __restrict__ A, const bf16* __restrict__ W,
             void* __restrict__ Cv, int M, int N, int K, float alpha, int mode,
             const float* __restrict__ bias, const int* __restrict__ tgt) {
    extern __shared__ char smraw[];
    const uint32_t sb = smem_u32(smraw);
    const int tid  = threadIdx.x;
    const int lane = tid & 31;
    const int wid  = tid >> 5;
    const int wm   = wid & 3;
    const int wn   = wid >> 2;
    const int bm   = blockIdx.y * 128, bn = blockIdx.x * 128;
    const int gid  = lane >> 2;
    const int tig  = lane & 3;

    float acc[2][8][4];
#pragma unroll
    for (int mt = 0; mt < 2; mt++)
#pragma unroll
        for (int nt = 0; nt < 8; nt++)
#pragma unroll
            for (int j = 0; j < 4; j++) acc[mt][nt][j] = 0.f;

    const int nIter = K >> 6;
    const int lrow  = tid >> 3;
    const int lc    = tid & 7;

#define LOAD_STAGE(it, s) do {                                               \
        int k0 = (it) * 64;                                                   \
        uint32_t base = sb + (uint32_t)(s) * STAGE_B;                         \
        _Pragma("unroll")                                                     \
        for (int i = 0; i < 4; i++) {                                         \
            int r = lrow + i * 32;                                            \
            uint32_t sw = (uint32_t)((lc ^ (r & 7)) << 4);                    \
            cp16(base + (uint32_t)r * 128u + sw,                              \
                 A + (size_t)(bm + r) * K + k0 + lc * 8);                     \
            cp16(base + TILE_B + (uint32_t)r * 128u + sw,                     \
                 W + (size_t)(bn + r) * K + k0 + lc * 8);                     \
        }                                                                     \
    } while (0)

    LOAD_STAGE(0, 0); CP_COMMIT();
    LOAD_STAGE(1, 1); CP_COMMIT();

    const int lg  = lane >> 3;
    const int lgi = lane & 7;

    for (int it = 0; it < nIter; it++) {
        CP_WAIT1();
        __syncthreads();
        if (it + 2 < nIter) LOAD_STAGE(it + 2, (it + 2) % 3);
        CP_COMMIT();

        const uint32_t sA = sb + (uint32_t)(it % 3) * STAGE_B;
        const uint32_t sW = sA + TILE_B;

#pragma unroll
        for (int kk = 0; kk < 4; kk++) {
            uint32_t afr[2][4], bfr[8][2];
#pragma unroll
            for (int mt = 0; mt < 2; mt++) {
                int row = wm * 32 + mt * 16 + lgi + (lg & 1) * 8;
                int chunk = kk * 2 + (lg >> 1);
                ldsm4(afr[mt], sA + (uint32_t)row * 128u +
                               (uint32_t)((chunk ^ (row & 7)) << 4));
            }
#pragma unroll
            for (int ntp = 0; ntp < 4; ntp++) {
                int row = wn * 64 + ntp * 16 + lgi + (lg >> 1) * 8;
                int chunk = kk * 2 + (lg & 1);
                uint32_t t4[4];
                ldsm4(t4, sW + (uint32_t)row * 128u +
                          (uint32_t)((chunk ^ (row & 7)) << 4));
                bfr[2 * ntp][0] = t4[0]; bfr[2 * ntp][1] = t4[1];
                bfr[2 * ntp + 1][0] = t4[2]; bfr[2 * ntp + 1][1] = t4[3];
            }
#pragma unroll
            for (int mt = 0; mt < 2; mt++)
#pragma unroll
                for (int nt = 0; nt < 8; nt++)
                    mma_bf16(acc[mt][nt], afr[mt], bfr[nt]);
        }
    }

    if (mode == 4) {
        // ---- fused logsumexp-partial epilogue (LM head) ----
        __syncthreads();
        float2* sm_ls = reinterpret_cast<float2*>(smraw);
#pragma unroll
        for (int mt = 0; mt < 2; mt++) {
            int rA = bm + wm * 32 + mt * 16 + gid;
            int rB = rA + 8;
            float vA[16], vB[16];
            float mA = -1e30f, mB = -1e30f;
#pragma unroll
            for (int nt = 0; nt < 8; nt++) {
                int col = bn + wn * 64 + nt * 8 + tig * 2;
                float2 bv = *reinterpret_cast<const float2*>(bias + col);
                vA[2 * nt]     = acc[mt][nt][0] + bv.x;
                vA[2 * nt + 1] = acc[mt][nt][1] + bv.y;
                vB[2 * nt]     = acc[mt][nt][2] + bv.x;
                vB[2 * nt + 1] = acc[mt][nt][3] + bv.y;
                mA = fmaxf(mA, fmaxf(vA[2 * nt], vA[2 * nt + 1]));
                mB = fmaxf(mB, fmaxf(vB[2 * nt], vB[2 * nt + 1]));
            }
#pragma unroll
            for (int o = 1; o <= 2; o <<= 1) {
                mA = fmaxf(mA, __shfl_xor_sync(0xffffffffu, mA, o));
                mB = fmaxf(mB, __shfl_xor_sync(0xffffffffu, mB, o));
            }
            float sA = 0.f, sB = 0.f;
#pragma unroll
            for (int i = 0; i < 16; i++) {
                sA += __expf(vA[i] - mA);
                sB += __expf(vB[i] - mB);
            }
#pragma unroll
            for (int o = 1; o <= 2; o <<= 1) {
                sA += __shfl_xor_sync(0xffffffffu, sA, o);
                sB += __shfl_xor_sync(0xffffffffu, sB, o);
            }
            if (tig == 0) {
                sm_ls[(((wm * 2 + mt) * 2 + 0) * 8 + gid) * 2 + wn] =
                    make_float2(mA, sA);
                sm_ls[(((wm * 2 + mt) * 2 + 1) * 8 + gid) * 2 + wn] =
                    make_float2(mB, sB);
            }
            {
                int t = tgt[rA];
                int local = t - bn - wn * 64;
                if (local >= 0 && local < 64 && ((local >> 1) & 3) == tig)
                    g_tgtlog[rA] = vA[(local >> 3) * 2 + (local & 1)];
                t = tgt[rB];
                local = t - bn - wn * 64;
                if (local >= 0 && local < 64 && ((local >> 1) & 3) == tig)
                    g_tgtlog[rB] = vB[(local >> 3) * 2 + (local & 1)];
            }
        }
        __syncthreads();
        if (tid < 128) {
            int wm2 = tid >> 5, rest = tid & 31;
            int mt = rest >> 4, ab = (rest >> 3) & 1, gd = rest & 7;
            int row = bm + wm2 * 32 + mt * 16 + ab * 8 + gd;
            float2 h0 = sm_ls[(((wm2 * 2 + mt) * 2 + ab) * 8 + gd) * 2 + 0];
            float2 h1 = sm_ls[(((wm2 * 2 + mt) * 2 + ab) * 8 + gd) * 2 + 1];
            float mm = fmaxf(h0.x, h1.x);
            float ss = h0.y * __expf(h0.x - mm) + h1.y * __expf(h1.x - mm);
            g_ls[(size_t)row * (N >> 7) + blockIdx.x] = make_float2(mm, ss);
        }
        return;
    }

    // ---- standard epilogues ----
#pragma unroll
    for (int mt = 0; mt < 2; mt++) {
        int r0 = bm + wm * 32 + mt * 16 + gid;
#pragma unroll
        for (int nt = 0; nt < 8; nt++) {
            int col = bn + wn * 64 + nt * 8 + tig * 2;
            float v0 = acc[mt][nt][0], v1 = acc[mt][nt][1];
            float v2 = acc[mt][nt][2], v3 = acc[mt][nt][3];
            if (mode == 2) {
                bf16* hp0 = (bf16*)Cv + (size_t)r0 * N + col;
                bf16* hp1 = (bf16*)Cv + (size_t)(r0 + 8) * N + col;
                *reinterpret_cast<uint32_t*>(hp0) =
                    pack_bf16(v0 / (1.f + __expf(-v0)), v1 / (1.f + __expf(-v1)));
                *reinterpret_cast<uint32_t*>(hp1) =
                    pack_bf16(v2 / (1.f + __expf(-v2)), v3 / (1.f + __expf(-v3)));
            } else if (mode == 3) {
                bf16* hp0 = (bf16*)Cv + (size_t)r0 * N + col;
                bf16* hp1 = (bf16*)Cv + (size_t)(r0 + 8) * N + col;
                *reinterpret_cast<uint32_t*>(hp0) = pack_bf16(v0, v1);
                *reinterpret_cast<uint32_t*>(hp1) = pack_bf16(v2, v3);
            } else {
                float* p0 = (float*)Cv + (size_t)r0 * N + col;
                float* p1 = (float*)Cv + (size_t)(r0 + 8) * N + col;
                if (mode == 1) {
                    float2 o0 = *reinterpret_cast<float2*>(p0);
                    float2 o1 = *reinterpret_cast<float2*>(p1);
                    o0.x += alpha * v0; o0.y += alpha * v1;
                    o1.x += alpha * v2; o1.y += alpha * v3;
                    *reinterpret_cast<float2*>(p0) = o0;
                    *reinterpret_cast<float2*>(p1) = o1;
                } else {
                    *reinterpret_cast<float2*>(p0) = make_float2(alpha * v0, alpha * v1);
                    *reinterpret_cast<float2*>(p1) = make_float2(alpha * v2, alpha * v3);
                }
            }
        }
    }
}

// =====================================================================
// tensor-core flash attention (reverse-qt scheduling for load balance)
// =====================================================================
#define FA_QTILE  128
#define FA_KTILE  64
#define FA_QBYTES 16384u
#define FA_STAGE  16384u
#define FA_SMEM_BYTES (FA_QBYTES + 3*FA_STAGE)

__global__ __launch_bounds__(256, 1)
void flash_attn_tc() {
    extern __shared__ char smraw[];
    const uint32_t sQ = smem_u32(smraw);
    const int tid  = threadIdx.x;
    const int lane = tid & 31;
    const int wq   = tid >> 5;
    const int gid  = lane >> 2;
    const int tig  = lane & 3;
    const int lg   = lane >> 3;
    const int lgi  = lane & 7;
    const int qt = (gridDim.x - 1) - blockIdx.x;   // big tiles first
    const int h = blockIdx.y, b = blockIdx.z;

    const bf16* qkv = g_qkv;
    const size_t rowstride = 3 * D_;
    const size_t qbase = (size_t)(b * S_ + qt * FA_QTILE) * rowstride + h * HD_;

    {
#pragma unroll
        for (int i = 0; i < 4; i++) {
            int idx = tid + i * 256;
            int r = idx >> 3, ch = idx & 7;
            cp16(sQ + (uint32_t)r * 128u + (uint32_t)((ch ^ (r & 7)) << 4),
                 qkv + qbase + (size_t)r * rowstride + ch * 8);
        }
    }
    const int nK = 2 * (qt + 1);

#define FA_LOAD(kt, s) do {                                                  \
        size_t kbase = (size_t)(b * S_ + (kt) * FA_KTILE) * rowstride         \
                       + h * HD_ + D_;                                         \
        uint32_t base = sQ + FA_QBYTES + (uint32_t)(s) * FA_STAGE;            \
        _Pragma("unroll")                                                     \
        for (int i = 0; i < 2; i++) {                                         \
            int idx = tid + i * 256;                                          \
            int r = idx >> 3, ch = idx & 7;                                   \
            uint32_t sw = (uint32_t)((ch ^ (r & 7)) << 4);                    \
            cp16(base + (uint32_t)r * 128u + sw,                              \
                 qkv + kbase + (size_t)r * rowstride + ch * 8);               \
            cp16(base + 8192u + (uint32_t)r * 128u + sw,                      \
                 qkv + kbase + D_ + (size_t)r * rowstride + ch * 8);          \
        }                                                                     \
    } while (0)

    FA_LOAD(0, 0); CP_COMMIT();
    FA_LOAD(1, 1); CP_COMMIT();

    uint32_t aQ[4][4];
    float O[8][4];
#pragma unroll
    for (int dt = 0; dt < 8; dt++)
#pragma unroll
        for (int j = 0; j < 4; j++) O[dt][j] = 0.f;
    float m0 = -1e30f, m1 = -1e30f, l0 = 0.f, l1 = 0.f;
    const int qr0 = qt * FA_QTILE + wq * 16 + gid;
    bool qload = false;

    for (int kt = 0; kt < nK; kt++) {
        CP_WAIT1();
        __syncthreads();
        if (!qload) {
#pragma unroll
            for (int c = 0; c < 4; c++) {
                int row = wq * 16 + (lg & 1) * 8 + lgi;
                int chunk = c * 2 + (lg >> 1);
                ldsm4(aQ[c], sQ + (uint32_t)row * 128u +
                             (uint32_t)((chunk ^ (row & 7)) << 4));
            }
            qload = true;
        }
        if (kt + 2 < nK) FA_LOAD(kt + 2, (kt + 2) % 3);
        CP_COMMIT();

        const uint32_t sK = sQ + FA_QBYTES + (uint32_t)(kt % 3) * FA_STAGE;
        const uint32_t sV = sK + 8192u;

        float sc[8][4];
#pragma unroll
        for (int nt = 0; nt < 8; nt++)
#pragma unroll
            for (int j = 0; j < 4; j++) sc[nt][j] = 0.f;
#pragma unroll
        for (int c = 0; c < 4; c++) {
            uint32_t bK[8][2];
#pragma unroll
            for (int ntp = 0; ntp < 4; ntp++) {
                int row = ntp * 16 + lgi + (lg >> 1) * 8;
                int chunk = c * 2 + (lg & 1);
                uint32_t t4[4];
                ldsm4(t4, sK + (uint32_t)row * 128u +
                          (uint32_t)((chunk ^ (row & 7)) << 4));
                bK[2 * ntp][0] = t4[0]; bK[2 * ntp][1] = t4[1];
                bK[2 * ntp + 1][0] = t4[2]; bK[2 * ntp + 1][1] = t4[3];
            }
#pragma unroll
            for (int nt = 0; nt < 8; nt++)
                mma_bf16(sc[nt], aQ[c], bK[nt]);
        }

        const bool boundary = (kt >= 2 * qt);
#pragma unroll
        for (int nt = 0; nt < 8; nt++) {
            int key = kt * FA_KTILE + nt * 8 + tig * 2;
#pragma unroll
            for (int j = 0; j < 4; j++) {
                sc[nt][j] *= 0.125f;
                if (boundary) {
                    int kj = key + (j & 1);
                    int rq = qr0 + (j >> 1) * 8;
                    if (kj > rq) sc[nt][j] = -1e30f;
                }
            }
        }

        float rmax0 = -1e30f, rmax1 = -1e30f;
#pragma unroll
        for (int nt = 0; nt < 8; nt++) {
            rmax0 = fmaxf(rmax0, fmaxf(sc[nt][0], sc[nt][1]));
            rmax1 = fmaxf(rmax1, fmaxf(sc[nt][2], sc[nt][3]));
        }
#pragma unroll
        for (int o = 1; o <= 2; o <<= 1) {
            rmax0 = fmaxf(rmax0, __shfl_xor_sync(0xffffffffu, rmax0, o));
            rmax1 = fmaxf(rmax1, __shfl_xor_sync(0xffffffffu, rmax1, o));
        }
        float mn0 = fmaxf(m0, rmax0), mn1 = fmaxf(m1, rmax1);
        float c0 = __expf(m0 - mn0), c1 = __expf(m1 - mn1);
        float s0 = 0.f, s1 = 0.f;
        uint32_t pfr[8][2];
#pragma unroll
        for (int nt = 0; nt < 8; nt++) {
            float p0 = __expf(sc[nt][0] - mn0);
            float p1 = __expf(sc[nt][1] - mn0);
            float p2 = __expf(sc[nt][2] - mn1);
            float p3 = __expf(sc[nt][3] - mn1);
            s0 += p0 + p1; s1 += p2 + p3;
            pfr[nt][0] = pack_bf16(p0, p1);
            pfr[nt][1] = pack_bf16(p2, p3);
        }
#pragma unroll
        for (int o = 1; o <= 2; o <<= 1) {
            s0 += __shfl_xor_sync(0xffffffffu, s0, o);
            s1 += __shfl_xor_sync(0xffffffffu, s1, o);
        }
        l0 = l0 * c0 + s0;  l1 = l1 * c1 + s1;
        m0 = mn0; m1 = mn1;
#pragma unroll
        for (int dt = 0; dt < 8; dt++) {
            O[dt][0] *= c0; O[dt][1] *= c0;
            O[dt][2] *= c1; O[dt][3] *= c1;
        }

#pragma unroll
        for (int c = 0; c < 4; c++) {
            uint32_t aP[4] = { pfr[2 * c][0], pfr[2 * c][1],
                               pfr[2 * c + 1][0], pfr[2 * c + 1][1] };
            uint32_t bV[8][2];
#pragma unroll
            for (int dtp = 0; dtp < 4; dtp++) {
                int row = c * 16 + (lg & 1) * 8 + lgi;
                int chunk = dtp * 2 + (lg >> 1);
                uint32_t t4[4];
                ldsm4t(t4, sV + (uint32_t)row * 128u +
                           (uint32_t)((chunk ^ (row & 7)) << 4));
                bV[2 * dtp][0] = t4[0]; bV[2 * dtp][1] = t4[1];
                bV[2 * dtp + 1][0] = t4[2]; bV[2 * dtp + 1][1] = t4[3];
            }
#pragma unroll
            for (int dt = 0; dt < 8; dt++)
                mma_bf16(O[dt], aP, bV[dt]);
        }
    }

    float inv0 = 1.f / l0, inv1 = 1.f / l1;
    bf16* y0 = g_y + (size_t)(b * S_ + qr0) * D_ + h * HD_;
    bf16* y1 = y0 + (size_t)8 * D_;
#pragma unroll
    for (int dt = 0; dt < 8; dt++) {
        int col = dt * 8 + tig * 2;
        *reinterpret_cast<uint32_t*>(y0 + col) =
            pack_bf16(O[dt][0] * inv0, O[dt][1] * inv0);
        *reinterpret_cast<uint32_t*>(y1 + col) =
            pack_bf16(O[dt][2] * inv1, O[dt][3] * inv1);
    }
}

// =====================================================================
// conversion + non-GEMM kernels
// =====================================================================
__global__ void f2bf_kernel(const float* __restrict__ src,
                            bf16* __restrict__ dst, int n4) {
    int i = blockIdx.x * blockDim.x + threadIdx.x;
    if (i < n4) {
        float4 v = reinterpret_cast<const float4*>(src)[i];
        uint2 o = make_uint2(pack_bf16(v.x, v.y), pack_bf16(v.z, v.w));
        reinterpret_cast<uint2*>(dst)[i] = o;
    }
}

__global__ void embed_kernel(const int* __restrict__ ids,
                             const float* __restrict__ emb,
                             float* __restrict__ x) {
    int row = blockIdx.x;
    int id = ids[row];
    const float* src = emb + (size_t)id * D_;
    float* dst = x + (size_t)row * D_;
    for (int d = threadIdx.x; d < D_; d += blockDim.x) dst[d] = src[d];
}

__global__ void rmsnorm_kernel(const float* __restrict__ x,
                               const float* __restrict__ w,
                               bf16* __restrict__ y, float eps) {
    __shared__ float red[256];
    int row = blockIdx.x;
    const float* xr = x + (size_t)row * D_;
    float s = 0.f;
    for (int d = threadIdx.x; d < D_; d += 256) { float v = xr[d]; s += v * v; }
    red[threadIdx.x] = s; __syncthreads();
    for (int o = 128; o > 0; o >>= 1) {
        if (threadIdx.x < o) red[threadIdx.x] += red[threadIdx.x + o];
        __syncthreads();
    }
    float r = rsqrtf(red[0] / D_ + eps);
    bf16* yr = y + (size_t)row * D_;
    for (int d = threadIdx.x; d < D_; d += 256)
        yr[d] = __float2bfloat16(w[d] * xr[d] * r);
}

// q-RMS scalar: one warp per (row, head) -> g_rq[row*H + h]
__global__ void gdn_pre_q() {
    int gw = blockIdx.x * 8 + (threadIdx.x >> 5);
    int lid = threadIdx.x & 31;
    int row = gw >> 4;
    int h = gw & 15;
    size_t base = (size_t)row * (5 * D_) + h * 64;
    float q0 = g_proj[base + lid];
    float q1 = g_proj[base + 32 + lid];
    float s = q0 * q0 + q1 * q1;
#pragma unroll
    for (int o = 16; o > 0; o >>= 1) s += __shfl_xor_sync(0xffffffffu, s, o);
    if (lid == 0)
        g_rq[row * H_ + h] = rsqrtf(s / 64.f + QEPS_);
}

// ---- chunked gated scan (u,a recomputed from proj) ----
__device__ __forceinline__ void gdn_ua(size_t b5, int col, float& a, float& u) {
    float kv = tanhf(g_proj[b5 + D_ + col]);
    float vv = g_proj[b5 + 2 * D_ + col];
    float av = 1.f / (1.f + expf(-(g_proj[b5 + 3 * D_ + col] + 2.f)));
    a = fminf(fmaxf(av, 0.6f), 0.9995f);
    u = kv * vv;
}

__global__ void scan_phase1() {
    int g = blockIdx.x * blockDim.x + threadIdx.x;
    int lane = g & 2047;
    int c = g >> 11;
    int b = lane >> 10, col = lane & 1023;
    float p = 1.f, acc = 0.f;
    int row0 = b * S_ + c * CHUNK_;
    for (int t = 0; t < CHUNK_; t++) {
        size_t b5 = (size_t)(row0 + t) * (5 * D_);
        float a, u;
        gdn_ua(b5, col, a, u);
        p *= a;
        acc += u / fmaxf(p, 1e-6f);
    }
    g_scanP[g] = p; g_scanA[g] = acc;
}
__global__ void scan_phase2() {
    int lane = blockIdx.x * blockDim.x + threadIdx.x;
    float carry = 0.f;
    for (int c = 0; c < NCHUNK_; c++) {
        int i = c * 2048 + lane;
        g_scanC[i] = carry;
        carry = g_scanP[i] * (carry + g_scanA[i]);
    }
}
__global__ void scan_phase3_post() {
    int g = blockIdx.x * blockDim.x + threadIdx.x;
    int lane = g & 2047;
    int c = g >> 11;
    int b = lane >> 10, col = lane & 1023;
    float carry = g_scanC[g];
    float p = 1.f, acc = 0.f;
    int row0 = b * S_ + c * CHUNK_;
    const int hh = col >> 6;
    for (int t = 0; t < CHUNK_; t++) {
        int row = row0 + t;
        size_t b5 = (size_t)row * (5 * D_);
        float a, u;
        gdn_ua(b5, col, a, u);
        p *= a;
        acc += u / fmaxf(p, 1e-6f);
        float mem = p * (carry + acc);
        float qh = g_proj[b5 + col] * g_rq[row * H_ + hh];
        float gate = 1.f / (1.f + expf(-g_proj[b5 + 4 * D_ + col]));
        float vv = g_proj[b5 + 2 * D_ + col];
        g_y[(size_t)row * D_ + col] =
            __float2bfloat16(gate * (qh * mem) + (1.f - gate) * vv);
    }
}

// ---- loss finalization ----
__global__ void loss_final() {
    __shared__ float mred[256], sred[256];
    int row = blockIdx.x;
    float2 v = g_ls[(size_t)row * 256 + threadIdx.x];
    mred[threadIdx.x] = v.x; sred[threadIdx.x] = v.y;
    __syncthreads();
    for (int o = 128; o > 0; o >>= 1) {
        if (threadIdx.x < o) {
            float m2 = mred[threadIdx.x + o], s2 = sred[threadIdx.x + o];
            float m1 = mred[threadIdx.x],     s1 = sred[threadIdx.x];
            float nm = fmaxf(m1, m2);
            mred[threadIdx.x] = nm;
            sred[threadIdx.x] = s1 * __expf(m1 - nm) + s2 * __expf(m2 - nm);
        }
        __syncthreads();
    }
    if (threadIdx.x == 0)
        g_rowloss[row] = -(g_tgtlog[row] - mred[0] - logf(sred[0]));
}

__global__ void loss_reduce_kernel(float* __restrict__ out) {
    __shared__ float red[256];
    float s = 0.f;
    for (int i = threadIdx.x; i < BS_; i += 256) s += g_rowloss[i];
    red[threadIdx.x] = s; __syncthreads();
    for (int o = 128; o > 0; o >>= 1) {
        if (threadIdx.x < o) red[threadIdx.x] += red[threadIdx.x + o];
        __syncthreads();
    }
    if (threadIdx.x == 0) out[0] = red[0] / (float)BS_;
}

// =====================================================================
// host orchestration
// =====================================================================
static void launch_gemm(const bf16* A, const bf16* W, void* C,
                        int M, int N, int K, float alpha, int mode,
                        const float* bias = nullptr, const int* tgt = nullptr) {
    dim3 grid(N / 128, M / 128);
    gemm_tc<<<grid, 256, GT_SMEM_BYTES>>>(A, W, C, M, N, K, alpha, mode, bias, tgt);
}
static void convert(const float* src, bf16* dst, size_t n) {
    int n4 = (int)(n / 4);
    f2bf_kernel<<<(n4 + 255) / 256, 256>>>(src, dst, n4);
}

extern "C" void kernel_launch(void* const* d_in, const int* in_sizes, int n_in,
                              void* d_out, int out_size) {
    const int*   input_ids   = (const int*)  d_in[0];
    const int*   target_ids  = (const int*)  d_in[1];
    const float* tok_emb     = (const float*)d_in[2];
    const float* lm_bias     = (const float*)d_in[3];
    const float* gdn_in_w    = (const float*)d_in[4];
    const float* gdn_out_w   = (const float*)d_in[5];
    const float* gdn_norm1   = (const float*)d_in[6];
    const float* gdn_norm2   = (const float*)d_in[7];
    const float* gdn_fc_w    = (const float*)d_in[8];
    const float* gdn_proj_w  = (const float*)d_in[9];
    const float* attn_qkv_w  = (const float*)d_in[10];
    const float* attn_proj_w = (const float*)d_in[11];
    const float* attn_norm1  = (const float*)d_in[12];
    const float* attn_norm2  = (const float*)d_in[13];
    const float* attn_fc_w   = (const float*)d_in[14];
    const float* attn_mlp_w  = (const float*)d_in[15];
    const float* final_norm  = (const float*)d_in[16];
    float* out = (float*)d_out;

    cudaFuncSetAttribute(gemm_tc, cudaFuncAttributeMaxDynamicSharedMemorySize,
                         GT_SMEM_BYTES);
    cudaFuncSetAttribute(flash_attn_tc, cudaFuncAttributeMaxDynamicSharedMemorySize,
                         FA_SMEM_BYTES);

    float *x, *proj;
    bf16 *xn, *y, *hid, *qkvb;
    bf16 *bw_in, *bw_out, *bw_fc, *bw_pj, *bw_qkv, *bw_apj, *bw_afc, *bw_ampj, *bw_emb;
    cudaGetSymbolAddress((void**)&x,      g_x);
    cudaGetSymbolAddress((void**)&xn,     g_xn);
    cudaGetSymbolAddress((void**)&proj,   g_proj);
    cudaGetSymbolAddress((void**)&y,      g_y);
    cudaGetSymbolAddress((void**)&hid,    g_hid);
    cudaGetSymbolAddress((void**)&qkvb,   g_qkv);
    cudaGetSymbolAddress((void**)&bw_in,   w_gdn_in);
    cudaGetSymbolAddress((void**)&bw_out,  w_gdn_out);
    cudaGetSymbolAddress((void**)&bw_fc,   w_gdn_fc);
    cudaGetSymbolAddress((void**)&bw_pj,   w_gdn_pj);
    cudaGetSymbolAddress((void**)&bw_qkv,  w_qkv);
    cudaGetSymbolAddress((void**)&bw_apj,  w_apj);
    cudaGetSymbolAddress((void**)&bw_afc,  w_afc);
    cudaGetSymbolAddress((void**)&bw_ampj, w_ampj);
    cudaGetSymbolAddress((void**)&bw_emb,  w_emb);

    // launch order chosen so launch index 5 (ncu -s 5 -c 1) is gemm_tc
    embed_kernel<<<BS_, 256>>>(input_ids, tok_emb, x);                     // 0
    rmsnorm_kernel<<<BS_, 256>>>(x, gdn_norm1, xn, 1e-6f);                 // 1
    convert(gdn_in_w,   bw_in,   (size_t)LG_ * 5 * D_ * D_);               // 2
    convert(gdn_out_w,  bw_out,  (size_t)LG_ * D_ * D_);                   // 3
    convert(gdn_fc_w,   bw_fc,   (size_t)LG_ * HM_ * D_);                  // 4
    launch_gemm(xn, bw_in, proj, BS_, 5 * D_, D_, 1.f, 0);                 // 5 <- profiled
    convert(gdn_proj_w, bw_pj,   (size_t)LG_ * D_ * HM_);                  // 6

    for (int i = 0; i < LG_; i++) {
        float rsc = rsqrtf(2.0f * (i + 1));
        if (i > 0) {
            rmsnorm_kernel<<<BS_, 256>>>(x, gdn_norm1 + (size_t)i * D_, xn, 1e-6f);
            launch_gemm(xn, bw_in + (size_t)i * 5 * D_ * D_, proj, BS_, 5 * D_, D_, 1.f, 0);
        }
        gdn_pre_q<<<BS_ * H_ / 8, 256>>>();
        scan_phase1<<<B_ * D_ * NCHUNK_ / 256, 256>>>();
        scan_phase2<<<B_ * D_ / 256, 256>>>();
        scan_phase3_post<<<B_ * D_ * NCHUNK_ / 256, 256>>>();
        launch_gemm(y, bw_out + (size_t)i * D_ * D_, x, BS_, D_, D_, rsc, 1);
        rmsnorm_kernel<<<BS_, 256>>>(x, gdn_norm2 + (size_t)i * D_, xn, 1e-6f);
        launch_gemm(xn, bw_fc + (size_t)i * HM_ * D_, hid, BS_, HM_, D_, 1.f, 2);
        launch_gemm(hid, bw_pj + (size_t)i * D_ * HM_, x, BS_, D_, HM_, rsc, 1);
    }

    convert(attn_qkv_w, bw_qkv,  (size_t)3 * D_ * D_);
    convert(attn_proj_w, bw_apj, (size_t)D_ * D_);
    convert(attn_fc_w,  bw_afc,  (size_t)HM_ * D_);
    convert(attn_mlp_w, bw_ampj, (size_t)D_ * HM_);
    convert(tok_emb,    bw_emb,  (size_t)V_ * D_);

    float rsc = rsqrtf(2.0f * (LG_ + 1));
    rmsnorm_kernel<<<BS_, 256>>>(x, attn_norm1, xn, 1e-6f);
    launch_gemm(xn, bw_qkv, qkvb, BS_, 3 * D_, D_, 1.f, 3);
    {
        dim3 fgrid(S_ / FA_QTILE, H_, B_);
        flash_attn_tc<<<fgrid, 256, FA_SMEM_BYTES>>>();
    }
    launch_gemm(y, bw_apj, x, BS_, D_, D_, rsc, 1);
    rmsnorm_kernel<<<BS_, 256>>>(x, attn_norm2, xn, 1e-6f);
    launch_gemm(xn, bw_afc, hid, BS_, HM_, D_, 1.f, 2);
    launch_gemm(hid, bw_ampj, x, BS_, D_, HM_, rsc, 1);

    rmsnorm_kernel<<<BS_, 256>>>(x, final_norm, xn, 1e-6f);
    launch_gemm(xn, bw_emb, nullptr, BS_, V_, D_, 1.f, 4, lm_bias, target_ids);
    loss_final<<<BS_, 256>>>();
    loss_reduce_kernel<<<1, 256>>>(out);
}